// round 4
// baseline (speedup 1.0000x reference)
#include <cuda_runtime.h>

// LogicMachine: B=8, n=32, C=64, O=64
// Output layout (floats): o0[8,64] | o1[8,32,64] | o2[8,32,32,64] | o3[8,32,32,32,64]
#define OUT0 0
#define OUT1 512
#define OUT2 16896
#define OUT3 541184

// Transposed-weight pool offsets (layout [in][64] each)
#define W_OP0_T   0
#define W_RED0_T  4096
#define W_EXP1_T  12288
#define W_OP1_T   16384
#define W_RED1_T  20480
#define W_EXP2_T  28672
#define W_OP2_T   36864
#define W_RED2_T  45056
#define W_EXP3_T  61440
#define W_OP3_T   86016
#define W_TOTAL   110592

__device__ __align__(16) float d_wt[W_TOTAL];
__device__ __align__(16) float d_r0[8 * 128];
__device__ __align__(16) float d_r1[8 * 32 * 128];
__device__ __align__(16) float d_r2[8 * 32 * 32 * 128];
__device__ __align__(16) float d_y2e[8 * 32 * 32 * 384];

// ---------------- helpers ----------------
__device__ __forceinline__ float sigf(float s) { return 1.0f / (1.0f + __expf(-s)); }

__device__ __forceinline__ unsigned long long pack2f(float x) {
    unsigned int u = __float_as_uint(x);
    unsigned long long r;
    asm("mov.b64 %0, {%1, %1};" : "=l"(r) : "r"(u));
    return r;
}
__device__ __forceinline__ void fma2(unsigned long long& d, unsigned long long a, unsigned long long b) {
    asm("fma.rn.f32x2 %0, %1, %2, %0;" : "+l"(d) : "l"(a), "l"(b));
}
__device__ __forceinline__ void unpack2f(unsigned long long v, float& lo, float& hi) {
    unsigned int a, b;
    asm("mov.b64 {%0, %1}, %2;" : "=r"(a), "=r"(b) : "l"(v));
    lo = __uint_as_float(a);
    hi = __uint_as_float(b);
}
__device__ __forceinline__ int any_bits(const int* act, int lo, int hi) {
    int g = 0;
    for (int b = 0; b < 8; ++b)
        for (int t = lo; t < hi; ++t) g |= act[b * 10 + t];
    return g;
}

// ---------------- weight transpose ----------------
__global__ void k_prep(const float* __restrict__ w_op0, const float* __restrict__ w_red0,
                       const float* __restrict__ w_exp1, const float* __restrict__ w_op1,
                       const float* __restrict__ w_red1, const float* __restrict__ w_exp2,
                       const float* __restrict__ w_op2, const float* __restrict__ w_red2,
                       const float* __restrict__ w_exp3, const float* __restrict__ w_op3) {
    int tid = blockIdx.x * 256 + threadIdx.x;
    if (tid >= W_TOTAL) return;
    const float* src;
    int off, IN;
    if (tid < 4096)        { src = w_op0;  off = tid;          IN = 64;  }
    else if (tid < 12288)  { src = w_red0; off = tid - 4096;   IN = 128; }
    else if (tid < 16384)  { src = w_exp1; off = tid - 12288;  IN = 64;  }
    else if (tid < 20480)  { src = w_op1;  off = tid - 16384;  IN = 64;  }
    else if (tid < 28672)  { src = w_red1; off = tid - 20480;  IN = 128; }
    else if (tid < 36864)  { src = w_exp2; off = tid - 28672;  IN = 128; }
    else if (tid < 45056)  { src = w_op2;  off = tid - 36864;  IN = 128; }
    else if (tid < 61440)  { src = w_red2; off = tid - 45056;  IN = 256; }
    else if (tid < 86016)  { src = w_exp3; off = tid - 61440;  IN = 384; }
    else                   { src = w_op3;  off = tid - 86016;  IN = 384; }
    int in = off >> 6, o = off & 63;
    d_wt[tid] = src[o * IN + in];
}

// ---------------- reductions ----------------
__global__ void k_r0(const float* __restrict__ x1) {
    int b = blockIdx.x, c = threadIdx.x;
    float mx = -3.4e38f, mn = 3.4e38f;
    for (int i = 0; i < 32; ++i) {
        float v = x1[(b * 32 + i) * 64 + c];
        mx = fmaxf(mx, v);
        mn = fminf(mn, v);
    }
    d_r0[b * 128 + 2 * c] = mx;
    d_r0[b * 128 + 2 * c + 1] = mn;
}

__global__ void k_r1(const float* __restrict__ x2) {
    int b = blockIdx.x >> 5, i = blockIdx.x & 31, c = threadIdx.x;
    float mx = -3.4e38f, mn = 3.4e38f;
    for (int j = 0; j < 32; ++j) {
        if (j == i) continue;
        float v = x2[((b * 32 + i) * 32 + j) * 64 + c];
        mx = fmaxf(mx, v);
        mn = fminf(mn, v);
    }
    d_r1[(b * 32 + i) * 128 + 2 * c] = mx;
    d_r1[(b * 32 + i) * 128 + 2 * c + 1] = mn;
}

__global__ void k_r2(const float* __restrict__ x3) {
    int x = blockIdx.x;
    int b = x >> 10, i = (x >> 5) & 31, j = x & 31, c = threadIdx.x;
    float mx, mn;
    if (i == j) {
        mx = 0.0f;  // max over masked-to-0 (empty valid set)
        mn = 1.0f;  // min over masked-to-1
    } else {
        mx = -3.4e38f; mn = 3.4e38f;
        const float* base = x3 + ((b * 32 + i) * 32 + j) * 2048 + c;
        for (int k = 0; k < 32; ++k) {
            if (k == i || k == j) continue;
            float v = base[k * 64];
            mx = fmaxf(mx, v);
            mn = fminf(mn, v);
        }
    }
    int row = ((b * 32 + i) * 32 + j) * 128;
    d_r2[row + 2 * c] = mx;
    d_r2[row + 2 * c + 1] = mn;
}

// ---------------- y2e precompute: y2e[b,i,j,q*64+o] = sum_c x2[b,i,j,c]*w_exp3[o,q*64+c]
__global__ void k_y2e(const float* __restrict__ x2) {
    __shared__ float xs[64];
    int x = blockIdx.x;
    int b = x >> 6, i = (x >> 1) & 31, h = x & 1;
    int tx = threadIdx.x;
    int q = tx >> 4, og = (tx & 15) * 4;
    const float* wbase = d_wt + W_EXP3_T + (q * 64) * 64 + og;
    for (int j = h * 16; j < h * 16 + 16; ++j) {
        __syncthreads();
        if (tx < 64) xs[tx] = x2[((b * 32 + i) * 32 + j) * 64 + tx];
        __syncthreads();
        float4 acc = make_float4(0.f, 0.f, 0.f, 0.f);
#pragma unroll 8
        for (int c = 0; c < 64; ++c) {
            float xv = xs[c];
            float4 w4 = *(const float4*)(wbase + c * 64);
            acc.x += xv * w4.x;
            acc.y += xv * w4.y;
            acc.z += xv * w4.z;
            acc.w += xv * w4.w;
        }
        *(float4*)(d_y2e + ((b * 32 + i) * 32 + j) * 384 + q * 64 + og) = acc;
    }
}

// ---------------- o0 + o1 ----------------
__global__ void k_o0o1(const float* __restrict__ x0, const float* __restrict__ x1,
                       const float* __restrict__ b_op0, const float* __restrict__ b_red0,
                       const float* __restrict__ b_exp1, const float* __restrict__ b_op1,
                       const float* __restrict__ b_red1,
                       const int* __restrict__ act, float* __restrict__ out) {
    int b = blockIdx.x, o = threadIdx.x;
    const int* ab = act + b * 10;
    int g0 = any_bits(act, 0, 2);
    int g1 = any_bits(act, 2, 5);

    float s0 = 0.f;
    if (ab[0]) {
        float d = 0.f;
        for (int c = 0; c < 64; ++c) d += x0[b * 64 + c] * d_wt[W_OP0_T + c * 64 + o];
        s0 += d + b_op0[o];
    }
    if (ab[1]) {
        float d = 0.f;
        for (int c = 0; c < 128; ++c) d += d_r0[b * 128 + c] * d_wt[W_RED0_T + c * 64 + o];
        s0 += d + b_red0[o];
    }
    out[OUT0 + b * 64 + o] = g0 ? sigf(s0) : 0.f;

    float sE = 0.f;
    if (ab[2]) {
        float d = 0.f;
        for (int c = 0; c < 64; ++c) d += x0[b * 64 + c] * d_wt[W_EXP1_T + c * 64 + o];
        sE = d + b_exp1[o];
    }
    for (int i = 0; i < 32; ++i) {
        float s1 = sE;
        if (ab[3]) {
            float d = 0.f;
            for (int c = 0; c < 64; ++c) d += x1[(b * 32 + i) * 64 + c] * d_wt[W_OP1_T + c * 64 + o];
            s1 += d + b_op1[o];
        }
        if (ab[4]) {
            float d = 0.f;
            for (int c = 0; c < 128; ++c) d += d_r1[(b * 32 + i) * 128 + c] * d_wt[W_RED1_T + c * 64 + o];
            s1 += d + b_red1[o];
        }
        out[OUT1 + (b * 32 + i) * 64 + o] = g1 ? sigf(s1) : 0.f;
    }
}

// ---------------- o2 ----------------
__global__ void k_o2(const float* __restrict__ x1, const float* __restrict__ x2,
                     const float* __restrict__ b_exp2, const float* __restrict__ b_op2,
                     const float* __restrict__ b_red2,
                     const int* __restrict__ act, float* __restrict__ out) {
    __shared__ float ein[512];
    __shared__ float psum[4][64];
    int x = blockIdx.x;
    int b = x >> 10, i = (x >> 5) & 31, j = x & 31;
    int tx = threadIdx.x;
    const int* ab = act + b * 10;
    int g2 = any_bits(act, 5, 8);

    for (int idx = tx; idx < 512; idx += 256) {
        float v;
        if (idx < 64)       v = x1[(b * 32 + i) * 64 + idx];
        else if (idx < 128) v = x1[(b * 32 + j) * 64 + idx - 64];
        else if (idx < 192) v = x2[((b * 32 + i) * 32 + j) * 64 + idx - 128];
        else if (idx < 256) v = x2[((b * 32 + j) * 32 + i) * 64 + idx - 192];
        else if (idx < 384) v = d_r2[((b * 32 + i) * 32 + j) * 128 + idx - 256];
        else                v = d_r2[((b * 32 + j) * 32 + i) * 128 + idx - 384];
        ein[idx] = v;
    }
    __syncthreads();

    int o = tx & 63, q4 = tx >> 6;
    int bit = (q4 == 0) ? ab[5] : (q4 == 1) ? ab[6] : ab[7];
    int wtoff = (q4 == 0) ? W_EXP2_T : (q4 == 1) ? W_OP2_T : (W_RED2_T + ((q4 == 3) ? 128 * 64 : 0));
    int eoff = q4 * 128;
    float d = 0.f;
    if (bit) {
#pragma unroll 8
        for (int c = 0; c < 128; ++c) d += ein[eoff + c] * d_wt[wtoff + c * 64 + o];
    }
    psum[q4][o] = d;
    __syncthreads();
    if (q4 == 0) {
        float s = psum[0][o] + psum[1][o] + psum[2][o] + psum[3][o]
                + (float)ab[5] * b_exp2[o] + (float)ab[6] * b_op2[o] + (float)ab[7] * b_red2[o];
        out[OUT2 + ((b * 32 + i) * 32 + j) * 64 + o] = g2 ? sigf(s) : 0.f;
    }
}

// ---------------- o3: the heavy kernel ----------------
// Segment mapping (inverse-permutation semantics of jnp.transpose!):
//   q=0: x[b,i,j,k]  q=1: x[b,i,k,j]  q=2: x[b,j,i,k]
//   q=3: x[b,k,i,j]  q=4: x[b,j,k,i]  q=5: x[b,k,j,i]
// grid 2048: (b, i, j-quad). 128 threads: warp = o-tile of 16, lane = k.
// dynamic smem: ws[384*64] (wt_op3) + xs[192*65] (gathered x3 rows, pitch 65).
__global__ void __launch_bounds__(128, 1)
k_o3(const float* __restrict__ x3, const float* __restrict__ b_exp3,
     const float* __restrict__ b_op3, const int* __restrict__ act,
     float* __restrict__ out) {
    extern __shared__ float sm[];
    float* ws = sm;           // 24576 floats
    float* xs = sm + 24576;   // 192*65 = 12480 floats

    int bid = blockIdx.x;
    int b = bid >> 8, i = (bid >> 3) & 31, jbase = (bid & 7) * 4;
    int tx = threadIdx.x, warp = tx >> 5, lane = tx & 31;
    int o0 = warp * 16;

    int g3 = any_bits(act, 8, 10);
    int a8 = act[b * 10 + 8], a9 = act[b * 10 + 9];

    if (!g3 || (!a8 && !a9)) {
        float fill = g3 ? 0.5f : 0.0f;  // sigmoid(0)=0.5 when globally gated on
        float4 f4 = make_float4(fill, fill, fill, fill);
        for (int jj = jbase; jj < jbase + 4; ++jj) {
            float4* op = (float4*)(out + OUT3 + ((b * 32 + i) * 32 + jj) * 2048) + tx * 4;
            op[0] = f4; op[1] = f4; op[2] = f4; op[3] = f4;
        }
        return;
    }

    // per-thread bias (j-invariant)
    float bb[16];
#pragma unroll
    for (int t = 0; t < 16; ++t)
        bb[t] = (a9 ? b_op3[o0 + t] : 0.f) + (a8 ? b_exp3[o0 + t] : 0.f);

    if (a9) {
        // stage wt_op3 into smem (once per block)
        const float4* src = (const float4*)(d_wt + W_OP3_T);
        float4* dst = (float4*)ws;
        for (int t = tx; t < 6144; t += 128) dst[t] = src[t];
    }

    for (int j = jbase; j < jbase + 4; ++j) {
        __syncthreads();
        if (a9) {
            // gather 6 segments x 32 rows of x3 into xs (k-major rows, pitch 65)
            for (int r = warp; r < 192; r += 4) {
                int q = r >> 5, k = r & 31;
                int a1, a2, a3;
                switch (q) {
                    case 0: a1 = i; a2 = j; a3 = k; break;
                    case 1: a1 = i; a2 = k; a3 = j; break;
                    case 2: a1 = j; a2 = i; a3 = k; break;
                    case 3: a1 = k; a2 = i; a3 = j; break;   // p=(2,3,1) inverse
                    case 4: a1 = j; a2 = k; a3 = i; break;   // p=(3,1,2) inverse
                    default: a1 = k; a2 = j; a3 = i; break;
                }
                const float* src = x3 + (((b * 32 + a1) * 32 + a2) * 32 + a3) * 64;
                xs[r * 65 + lane] = src[lane];
                xs[r * 65 + lane + 32] = src[lane + 32];
            }
        }
        __syncthreads();

        unsigned long long acc[8];
#pragma unroll
        for (int p = 0; p < 8; ++p) acc[p] = 0ull;

        if (a9) {
#pragma unroll
            for (int q = 0; q < 6; ++q) {
                const float* xr = xs + q * 2080 + lane * 65;
                const float* wr = ws + q * 4096 + o0;
#pragma unroll 4
                for (int cc = 0; cc < 64; ++cc) {
                    unsigned long long xp = pack2f(xr[cc]);
                    const ulonglong2* wp = (const ulonglong2*)(wr + cc * 64);
                    ulonglong2 w01 = wp[0];
                    ulonglong2 w23 = wp[1];
                    ulonglong2 w45 = wp[2];
                    ulonglong2 w67 = wp[3];
                    fma2(acc[0], xp, w01.x); fma2(acc[1], xp, w01.y);
                    fma2(acc[2], xp, w23.x); fma2(acc[3], xp, w23.y);
                    fma2(acc[4], xp, w45.x); fma2(acc[5], xp, w45.y);
                    fma2(acc[6], xp, w67.x); fma2(acc[7], xp, w67.y);
                }
            }
        }

        float res[16];
#pragma unroll
        for (int p = 0; p < 8; ++p) unpack2f(acc[p], res[2 * p], res[2 * p + 1]);

        if (a8) {
            int k = lane;
            // expand-branch (x2) index pairs per segment, matching q-map above
            int a1s[6] = { i, i, j, k, j, k };
            int a2s[6] = { j, k, i, i, k, j };
#pragma unroll
            for (int q = 0; q < 6; ++q) {
                const float4* yp = (const float4*)(d_y2e + ((b * 32 + a1s[q]) * 32 + a2s[q]) * 384 + q * 64 + o0);
                float4 y0 = yp[0], y1 = yp[1], y2v = yp[2], y3 = yp[3];
                res[0] += y0.x;  res[1] += y0.y;  res[2] += y0.z;  res[3] += y0.w;
                res[4] += y1.x;  res[5] += y1.y;  res[6] += y1.z;  res[7] += y1.w;
                res[8] += y2v.x; res[9] += y2v.y; res[10] += y2v.z; res[11] += y2v.w;
                res[12] += y3.x; res[13] += y3.y; res[14] += y3.z; res[15] += y3.w;
            }
        }

#pragma unroll
        for (int t = 0; t < 16; ++t) res[t] = sigf(res[t] + bb[t]);

        float* op = out + OUT3 + (((b * 32 + i) * 32 + j) * 32 + lane) * 64 + o0;
        ((float4*)op)[0] = make_float4(res[0], res[1], res[2], res[3]);
        ((float4*)op)[1] = make_float4(res[4], res[5], res[6], res[7]);
        ((float4*)op)[2] = make_float4(res[8], res[9], res[10], res[11]);
        ((float4*)op)[3] = make_float4(res[12], res[13], res[14], res[15]);
    }
}

// ---------------- launch ----------------
extern "C" void kernel_launch(void* const* d_in, const int* in_sizes, int n_in,
                              void* d_out, int out_size) {
    const float* x0 = (const float*)d_in[0];
    const float* x1 = (const float*)d_in[1];
    const float* x2 = (const float*)d_in[2];
    const float* x3 = (const float*)d_in[3];
    const float* w_op0 = (const float*)d_in[4];
    const float* b_op0 = (const float*)d_in[5];
    const float* w_red0 = (const float*)d_in[6];
    const float* b_red0 = (const float*)d_in[7];
    const float* w_exp1 = (const float*)d_in[8];
    const float* b_exp1 = (const float*)d_in[9];
    const float* w_op1 = (const float*)d_in[10];
    const float* b_op1 = (const float*)d_in[11];
    const float* w_red1 = (const float*)d_in[12];
    const float* b_red1 = (const float*)d_in[13];
    const float* w_exp2 = (const float*)d_in[14];
    const float* b_exp2 = (const float*)d_in[15];
    const float* w_op2 = (const float*)d_in[16];
    const float* b_op2 = (const float*)d_in[17];
    const float* w_red2 = (const float*)d_in[18];
    const float* b_red2 = (const float*)d_in[19];
    const float* w_exp3 = (const float*)d_in[20];
    const float* b_exp3 = (const float*)d_in[21];
    const float* w_op3 = (const float*)d_in[22];
    const float* b_op3 = (const float*)d_in[23];
    const int* act = (const int*)d_in[24];
    float* out = (float*)d_out;

    static int attr_set = 0;
    if (!attr_set) {
        cudaFuncSetAttribute(k_o3, cudaFuncAttributeMaxDynamicSharedMemorySize, 148224);
        attr_set = 1;
    }

    k_prep<<<(W_TOTAL + 255) / 256, 256>>>(w_op0, w_red0, w_exp1, w_op1, w_red1,
                                           w_exp2, w_op2, w_red2, w_exp3, w_op3);
    k_r0<<<8, 64>>>(x1);
    k_r1<<<256, 64>>>(x2);
    k_r2<<<8192, 64>>>(x3);
    k_y2e<<<512, 96>>>(x2);
    k_o0o1<<<8, 64>>>(x0, x1, b_op0, b_red0, b_exp1, b_op1, b_red1, act, out);
    k_o2<<<8192, 256>>>(x1, x2, b_exp2, b_op2, b_red2, act, out);
    k_o3<<<2048, 128, 148224>>>(x3, b_exp3, b_op3, act, out);
}

// round 5
// speedup vs baseline: 2.0119x; 2.0119x over previous
#include <cuda_runtime.h>

// LogicMachine: B=8, n=32, C=64, O=64
// Output layout (floats): o0[8,64] | o1[8,32,64] | o2[8,32,32,64] | o3[8,32,32,32,64]
#define OUT0 0
#define OUT1 512
#define OUT2 16896
#define OUT3 541184

// Transposed-weight pool offsets (layout [in][64] each)
#define W_OP0_T   0
#define W_RED0_T  4096
#define W_EXP1_T  12288
#define W_OP1_T   16384
#define W_RED1_T  20480
#define W_EXP2_T  28672
#define W_OP2_T   36864
#define W_RED2_T  45056
#define W_EXP3_T  61440
#define W_OP3_T   86016
#define W_TOTAL   110592

__device__ __align__(16) float d_wt[W_TOTAL];
__device__ __align__(16) float d_r0[8 * 128];
__device__ __align__(16) float d_r1[8 * 32 * 128];
__device__ __align__(16) float d_r2[8 * 32 * 32 * 128];
__device__ __align__(16) float d_y2e[8 * 32 * 32 * 384];
// Paired wt_op3: d_w2p[(q*64+c)*32 + p] = f32x2 pair (W[q*64+c][2p], W[q*64+c][2p+1])
__device__ __align__(16) unsigned long long d_w2p[6 * 64 * 32];

// ---------------- helpers ----------------
__device__ __forceinline__ float sigf(float s) { return 1.0f / (1.0f + __expf(-s)); }

__device__ __forceinline__ unsigned long long pack2f(float x) {
    unsigned int u = __float_as_uint(x);
    unsigned long long r;
    asm("mov.b64 %0, {%1, %1};" : "=l"(r) : "r"(u));
    return r;
}
__device__ __forceinline__ void fma2(unsigned long long& d, unsigned long long a, unsigned long long b) {
    asm("fma.rn.f32x2 %0, %1, %2, %0;" : "+l"(d) : "l"(a), "l"(b));
}
__device__ __forceinline__ void unpack2f(unsigned long long v, float& lo, float& hi) {
    unsigned int a, b;
    asm("mov.b64 {%0, %1}, %2;" : "=r"(a), "=r"(b) : "l"(v));
    lo = __uint_as_float(a);
    hi = __uint_as_float(b);
}
__device__ __forceinline__ int any_bits(const int* act, int lo, int hi) {
    int g = 0;
    for (int b = 0; b < 8; ++b)
        for (int t = lo; t < hi; ++t) g |= act[b * 10 + t];
    return g;
}
__device__ __forceinline__ void cp16(void* dst_smem, const void* src) {
    unsigned sdst = (unsigned)__cvta_generic_to_shared(dst_smem);
    asm volatile("cp.async.ca.shared.global [%0], [%1], 16;" :: "r"(sdst), "l"(src));
}
__device__ __forceinline__ void cp_commit() { asm volatile("cp.async.commit_group;"); }
__device__ __forceinline__ void cp_wait0() { asm volatile("cp.async.wait_group 0;"); }
__device__ __forceinline__ void cp_wait1() { asm volatile("cp.async.wait_group 1;"); }

// ---------------- weight transpose ----------------
__global__ void k_prep(const float* __restrict__ w_op0, const float* __restrict__ w_red0,
                       const float* __restrict__ w_exp1, const float* __restrict__ w_op1,
                       const float* __restrict__ w_red1, const float* __restrict__ w_exp2,
                       const float* __restrict__ w_op2, const float* __restrict__ w_red2,
                       const float* __restrict__ w_exp3, const float* __restrict__ w_op3) {
    int tid = blockIdx.x * 256 + threadIdx.x;
    if (tid >= W_TOTAL) return;
    const float* src;
    int off, IN;
    if (tid < 4096)        { src = w_op0;  off = tid;          IN = 64;  }
    else if (tid < 12288)  { src = w_red0; off = tid - 4096;   IN = 128; }
    else if (tid < 16384)  { src = w_exp1; off = tid - 12288;  IN = 64;  }
    else if (tid < 20480)  { src = w_op1;  off = tid - 16384;  IN = 64;  }
    else if (tid < 28672)  { src = w_red1; off = tid - 20480;  IN = 128; }
    else if (tid < 36864)  { src = w_exp2; off = tid - 28672;  IN = 128; }
    else if (tid < 45056)  { src = w_op2;  off = tid - 36864;  IN = 128; }
    else if (tid < 61440)  { src = w_red2; off = tid - 45056;  IN = 256; }
    else if (tid < 86016)  { src = w_exp3; off = tid - 61440;  IN = 384; }
    else                   { src = w_op3;  off = tid - 86016;  IN = 384; }
    int in = off >> 6, o = off & 63;
    d_wt[tid] = src[o * IN + in];
}

// paired wt_op3 for k_o3
__global__ void k_prep2(const float* __restrict__ w_op3) {
    int t = blockIdx.x * 256 + threadIdx.x;
    if (t >= 6 * 64 * 32) return;
    int C = t >> 5, p = t & 31;
    unsigned long long lo = __float_as_uint(w_op3[(2 * p) * 384 + C]);
    unsigned long long hi = __float_as_uint(w_op3[(2 * p + 1) * 384 + C]);
    d_w2p[t] = lo | (hi << 32);
}

// ---------------- reductions ----------------
__global__ void k_r0(const float* __restrict__ x1) {
    int b = blockIdx.x, c = threadIdx.x;
    float mx = -3.4e38f, mn = 3.4e38f;
    for (int i = 0; i < 32; ++i) {
        float v = x1[(b * 32 + i) * 64 + c];
        mx = fmaxf(mx, v);
        mn = fminf(mn, v);
    }
    d_r0[b * 128 + 2 * c] = mx;
    d_r0[b * 128 + 2 * c + 1] = mn;
}

__global__ void k_r1(const float* __restrict__ x2) {
    int b = blockIdx.x >> 5, i = blockIdx.x & 31, c = threadIdx.x;
    float mx = -3.4e38f, mn = 3.4e38f;
    for (int j = 0; j < 32; ++j) {
        if (j == i) continue;
        float v = x2[((b * 32 + i) * 32 + j) * 64 + c];
        mx = fmaxf(mx, v);
        mn = fminf(mn, v);
    }
    d_r1[(b * 32 + i) * 128 + 2 * c] = mx;
    d_r1[(b * 32 + i) * 128 + 2 * c + 1] = mn;
}

__global__ void k_r2(const float* __restrict__ x3) {
    int x = blockIdx.x;
    int b = x >> 10, i = (x >> 5) & 31, j = x & 31, c = threadIdx.x;
    float mx, mn;
    if (i == j) {
        mx = 0.0f;  // max over masked-to-0
        mn = 1.0f;  // min over masked-to-1
    } else {
        mx = -3.4e38f; mn = 3.4e38f;
        const float* base = x3 + ((b * 32 + i) * 32 + j) * 2048 + c;
        for (int k = 0; k < 32; ++k) {
            if (k == i || k == j) continue;
            float v = base[k * 64];
            mx = fmaxf(mx, v);
            mn = fminf(mn, v);
        }
    }
    int row = ((b * 32 + i) * 32 + j) * 128;
    d_r2[row + 2 * c] = mx;
    d_r2[row + 2 * c + 1] = mn;
}

// ---------------- y2e precompute ----------------
__global__ void k_y2e(const float* __restrict__ x2) {
    __shared__ float xs[64];
    int x = blockIdx.x;
    int b = x >> 6, i = (x >> 1) & 31, h = x & 1;
    int tx = threadIdx.x;
    int q = tx >> 4, og = (tx & 15) * 4;
    const float* wbase = d_wt + W_EXP3_T + (q * 64) * 64 + og;
    for (int j = h * 16; j < h * 16 + 16; ++j) {
        __syncthreads();
        if (tx < 64) xs[tx] = x2[((b * 32 + i) * 32 + j) * 64 + tx];
        __syncthreads();
        float4 acc = make_float4(0.f, 0.f, 0.f, 0.f);
#pragma unroll 8
        for (int c = 0; c < 64; ++c) {
            float xv = xs[c];
            float4 w4 = *(const float4*)(wbase + c * 64);
            acc.x += xv * w4.x;
            acc.y += xv * w4.y;
            acc.z += xv * w4.z;
            acc.w += xv * w4.w;
        }
        *(float4*)(d_y2e + ((b * 32 + i) * 32 + j) * 384 + q * 64 + og) = acc;
    }
}

// ---------------- o0 + o1 ----------------
__global__ void k_o0o1(const float* __restrict__ x0, const float* __restrict__ x1,
                       const float* __restrict__ b_op0, const float* __restrict__ b_red0,
                       const float* __restrict__ b_exp1, const float* __restrict__ b_op1,
                       const float* __restrict__ b_red1,
                       const int* __restrict__ act, float* __restrict__ out) {
    int b = blockIdx.x, o = threadIdx.x;
    const int* ab = act + b * 10;
    int g0 = any_bits(act, 0, 2);
    int g1 = any_bits(act, 2, 5);

    float s0 = 0.f;
    if (ab[0]) {
        float d = 0.f;
        for (int c = 0; c < 64; ++c) d += x0[b * 64 + c] * d_wt[W_OP0_T + c * 64 + o];
        s0 += d + b_op0[o];
    }
    if (ab[1]) {
        float d = 0.f;
        for (int c = 0; c < 128; ++c) d += d_r0[b * 128 + c] * d_wt[W_RED0_T + c * 64 + o];
        s0 += d + b_red0[o];
    }
    out[OUT0 + b * 64 + o] = g0 ? sigf(s0) : 0.f;

    float sE = 0.f;
    if (ab[2]) {
        float d = 0.f;
        for (int c = 0; c < 64; ++c) d += x0[b * 64 + c] * d_wt[W_EXP1_T + c * 64 + o];
        sE = d + b_exp1[o];
    }
    for (int i = 0; i < 32; ++i) {
        float s1 = sE;
        if (ab[3]) {
            float d = 0.f;
            for (int c = 0; c < 64; ++c) d += x1[(b * 32 + i) * 64 + c] * d_wt[W_OP1_T + c * 64 + o];
            s1 += d + b_op1[o];
        }
        if (ab[4]) {
            float d = 0.f;
            for (int c = 0; c < 128; ++c) d += d_r1[(b * 32 + i) * 128 + c] * d_wt[W_RED1_T + c * 64 + o];
            s1 += d + b_red1[o];
        }
        out[OUT1 + (b * 32 + i) * 64 + o] = g1 ? sigf(s1) : 0.f;
    }
}

// ---------------- o2 ----------------
__global__ void k_o2(const float* __restrict__ x1, const float* __restrict__ x2,
                     const float* __restrict__ b_exp2, const float* __restrict__ b_op2,
                     const float* __restrict__ b_red2,
                     const int* __restrict__ act, float* __restrict__ out) {
    __shared__ float ein[512];
    __shared__ float psum[4][64];
    int x = blockIdx.x;
    int b = x >> 10, i = (x >> 5) & 31, j = x & 31;
    int tx = threadIdx.x;
    const int* ab = act + b * 10;
    int g2 = any_bits(act, 5, 8);

    for (int idx = tx; idx < 512; idx += 256) {
        float v;
        if (idx < 64)       v = x1[(b * 32 + i) * 64 + idx];
        else if (idx < 128) v = x1[(b * 32 + j) * 64 + idx - 64];
        else if (idx < 192) v = x2[((b * 32 + i) * 32 + j) * 64 + idx - 128];
        else if (idx < 256) v = x2[((b * 32 + j) * 32 + i) * 64 + idx - 192];
        else if (idx < 384) v = d_r2[((b * 32 + i) * 32 + j) * 128 + idx - 256];
        else                v = d_r2[((b * 32 + j) * 32 + i) * 128 + idx - 384];
        ein[idx] = v;
    }
    __syncthreads();

    int o = tx & 63, q4 = tx >> 6;
    int bit = (q4 == 0) ? ab[5] : (q4 == 1) ? ab[6] : ab[7];
    int wtoff = (q4 == 0) ? W_EXP2_T : (q4 == 1) ? W_OP2_T : (W_RED2_T + ((q4 == 3) ? 128 * 64 : 0));
    int eoff = q4 * 128;
    float d = 0.f;
    if (bit) {
#pragma unroll 8
        for (int c = 0; c < 128; ++c) d += ein[eoff + c] * d_wt[wtoff + c * 64 + o];
    }
    psum[q4][o] = d;
    __syncthreads();
    if (q4 == 0) {
        float s = psum[0][o] + psum[1][o] + psum[2][o] + psum[3][o]
                + (float)ab[5] * b_exp2[o] + (float)ab[6] * b_op2[o] + (float)ab[7] * b_red2[o];
        out[OUT2 + ((b * 32 + i) * 32 + j) * 64 + o] = g2 ? sigf(s) : 0.f;
    }
}

// ---------------- o3: streaming heavy kernel ----------------
// Segment map (inverse-perm semantics of jnp.transpose):
//   q=0: x[b,i,j,k]  q=1: x[b,i,k,j]  q=2: x[b,j,i,k]
//   q=3: x[b,k,i,j]  q=4: x[b,j,k,i]  q=5: x[b,k,j,i]
// grid 4096 = (b:8, i:32, jgroup:8, oh:2). block 256 = 8 warps (jj 0..3 x o-tile 0/1).
// smem: 2 buffers x (x: 4j*32k*64c floats [XOR-swizzled 16B groups] + w: 1024 ull pairs).
#define BUF_FLOATS 10240
#define SMEM_O3    (2 * BUF_FLOATS * 4)

__device__ __forceinline__ void stage_q(float* sm, int bufbase, int q,
                                        int b, int i, int jbase, int oh, int tx,
                                        const float* __restrict__ x3) {
    int bb32 = b * 32;
#pragma unroll
    for (int it = 0; it < 8; ++it) {
        int m = tx + (it << 8);
        int jj = m >> 9, k = (m >> 4) & 31, g = m & 15;
        int j = jbase + jj;
        int base, strd;
        switch (q) {
            case 0:  base = (((bb32 + i) * 32 + j) * 32) * 64; strd = 64;    break;
            case 1:  base = ((bb32 + i) * 1024 + j) * 64;      strd = 2048;  break;
            case 2:  base = (((bb32 + j) * 32 + i) * 32) * 64; strd = 64;    break;
            case 3:  base = (b * 32768 + i * 32 + j) * 64;     strd = 65536; break;
            case 4:  base = ((bb32 + j) * 1024 + i) * 64;      strd = 2048;  break;
            default: base = (b * 32768 + j * 32 + i) * 64;     strd = 65536; break;
        }
        const float* src = x3 + base + k * strd + g * 4;
        float* dst = sm + bufbase + ((jj * 32 + k) << 6) + (((g ^ (k & 15)) << 2));
        cp16(dst, src);
    }
#pragma unroll
    for (int it = 0; it < 2; ++it) {
        int m = tx + (it << 8);
        int c = m >> 3, pp = m & 7;
        const unsigned long long* srcw = d_w2p + (q * 64 + c) * 32 + oh * 16 + pp * 2;
        unsigned long long* dstw = (unsigned long long*)(sm + bufbase + 8192) + (c * 16 + pp * 2);
        cp16(dstw, srcw);
    }
}

__device__ __forceinline__ void compute_q(const float* sm, int bufbase,
                                          int jj, int wsel, int lane,
                                          unsigned long long* acc) {
    const float* xrow = sm + bufbase + ((jj * 32 + lane) << 6);
    const ulonglong2* wb = (const ulonglong2*)((const unsigned long long*)(sm + bufbase + 8192)) + wsel * 4;
    int swl = (lane & 15) << 2;
#pragma unroll
    for (int g = 0; g < 16; ++g) {
        float4 x4 = *(const float4*)(xrow + (((g << 2)) ^ swl));
        const ulonglong2* wp = wb + (g << 5);
        unsigned long long xp;
        xp = pack2f(x4.x);
        { ulonglong2 w0 = wp[0], w1 = wp[1], w2 = wp[2], w3 = wp[3];
          fma2(acc[0], xp, w0.x); fma2(acc[1], xp, w0.y);
          fma2(acc[2], xp, w1.x); fma2(acc[3], xp, w1.y);
          fma2(acc[4], xp, w2.x); fma2(acc[5], xp, w2.y);
          fma2(acc[6], xp, w3.x); fma2(acc[7], xp, w3.y); }
        xp = pack2f(x4.y);
        { ulonglong2 w0 = wp[8], w1 = wp[9], w2 = wp[10], w3 = wp[11];
          fma2(acc[0], xp, w0.x); fma2(acc[1], xp, w0.y);
          fma2(acc[2], xp, w1.x); fma2(acc[3], xp, w1.y);
          fma2(acc[4], xp, w2.x); fma2(acc[5], xp, w2.y);
          fma2(acc[6], xp, w3.x); fma2(acc[7], xp, w3.y); }
        xp = pack2f(x4.z);
        { ulonglong2 w0 = wp[16], w1 = wp[17], w2 = wp[18], w3 = wp[19];
          fma2(acc[0], xp, w0.x); fma2(acc[1], xp, w0.y);
          fma2(acc[2], xp, w1.x); fma2(acc[3], xp, w1.y);
          fma2(acc[4], xp, w2.x); fma2(acc[5], xp, w2.y);
          fma2(acc[6], xp, w3.x); fma2(acc[7], xp, w3.y); }
        xp = pack2f(x4.w);
        { ulonglong2 w0 = wp[24], w1 = wp[25], w2 = wp[26], w3 = wp[27];
          fma2(acc[0], xp, w0.x); fma2(acc[1], xp, w0.y);
          fma2(acc[2], xp, w1.x); fma2(acc[3], xp, w1.y);
          fma2(acc[4], xp, w2.x); fma2(acc[5], xp, w2.y);
          fma2(acc[6], xp, w3.x); fma2(acc[7], xp, w3.y); }
    }
}

__global__ void __launch_bounds__(256, 2)
k_o3(const float* __restrict__ x3, const float* __restrict__ b_exp3,
     const float* __restrict__ b_op3, const int* __restrict__ act,
     float* __restrict__ out) {
    extern __shared__ float sm[];
    int bid = blockIdx.x;
    int b = bid >> 9, i = (bid >> 4) & 31, jbase = ((bid >> 1) & 7) * 4, oh = bid & 1;
    int tx = threadIdx.x, w = tx >> 5, lane = tx & 31;
    int jj = w >> 1, wsel = w & 1;
    int o0 = oh * 32 + wsel * 16;
    int j = jbase + jj;

    int g3 = any_bits(act, 8, 10);
    int a8 = act[b * 10 + 8], a9 = act[b * 10 + 9];

    if (!g3 || (!a8 && !a9)) {
        float fill = g3 ? 0.5f : 0.0f;  // sigmoid(0)=0.5 when globally gated on
        float4 f4 = make_float4(fill, fill, fill, fill);
        for (int f = tx; f < 1024; f += 256) {
            int fj = f >> 8, fk = (f >> 3) & 31, c4 = f & 7;
            *((float4*)(out + OUT3 + (((b * 32 + i) * 32 + jbase + fj) * 32 + fk) * 64 + oh * 32) + c4) = f4;
        }
        return;
    }

    unsigned long long acc[8];
#pragma unroll
    for (int p = 0; p < 8; ++p) acc[p] = 0ull;

    if (a9) {
        stage_q(sm, 0, 0, b, i, jbase, oh, tx, x3);
        cp_commit();
#pragma unroll 1
        for (int q = 0; q < 6; ++q) {
            int cur = (q & 1) * BUF_FLOATS;
            if (q < 5) {
                stage_q(sm, ((q + 1) & 1) * BUF_FLOATS, q + 1, b, i, jbase, oh, tx, x3);
                cp_commit();
                cp_wait1();
            } else {
                cp_wait0();
            }
            __syncthreads();
            compute_q(sm, cur, jj, wsel, lane, acc);
            __syncthreads();
        }
    }

    float res[16];
#pragma unroll
    for (int p = 0; p < 8; ++p) unpack2f(acc[p], res[2 * p], res[2 * p + 1]);

    if (a8) {
        int k = lane;
        int a1s[6] = { i, i, j, k, j, k };
        int a2s[6] = { j, k, i, i, k, j };
#pragma unroll
        for (int q = 0; q < 6; ++q) {
            const float4* yp = (const float4*)(d_y2e + ((b * 32 + a1s[q]) * 32 + a2s[q]) * 384 + q * 64 + o0);
            float4 y0 = yp[0], y1 = yp[1], y2v = yp[2], y3 = yp[3];
            res[0] += y0.x;  res[1] += y0.y;  res[2] += y0.z;  res[3] += y0.w;
            res[4] += y1.x;  res[5] += y1.y;  res[6] += y1.z;  res[7] += y1.w;
            res[8] += y2v.x; res[9] += y2v.y; res[10] += y2v.z; res[11] += y2v.w;
            res[12] += y3.x; res[13] += y3.y; res[14] += y3.z; res[15] += y3.w;
        }
    }

#pragma unroll
    for (int t = 0; t < 16; ++t) {
        float bb = (a9 ? b_op3[o0 + t] : 0.f) + (a8 ? b_exp3[o0 + t] : 0.f);
        res[t] = sigf(res[t] + bb);
    }

    float* op = out + OUT3 + (((b * 32 + i) * 32 + j) * 32 + lane) * 64 + o0;
    ((float4*)op)[0] = make_float4(res[0], res[1], res[2], res[3]);
    ((float4*)op)[1] = make_float4(res[4], res[5], res[6], res[7]);
    ((float4*)op)[2] = make_float4(res[8], res[9], res[10], res[11]);
    ((float4*)op)[3] = make_float4(res[12], res[13], res[14], res[15]);
}

// ---------------- launch ----------------
extern "C" void kernel_launch(void* const* d_in, const int* in_sizes, int n_in,
                              void* d_out, int out_size) {
    const float* x0 = (const float*)d_in[0];
    const float* x1 = (const float*)d_in[1];
    const float* x2 = (const float*)d_in[2];
    const float* x3 = (const float*)d_in[3];
    const float* w_op0 = (const float*)d_in[4];
    const float* b_op0 = (const float*)d_in[5];
    const float* w_red0 = (const float*)d_in[6];
    const float* b_red0 = (const float*)d_in[7];
    const float* w_exp1 = (const float*)d_in[8];
    const float* b_exp1 = (const float*)d_in[9];
    const float* w_op1 = (const float*)d_in[10];
    const float* b_op1 = (const float*)d_in[11];
    const float* w_red1 = (const float*)d_in[12];
    const float* b_red1 = (const float*)d_in[13];
    const float* w_exp2 = (const float*)d_in[14];
    const float* b_exp2 = (const float*)d_in[15];
    const float* w_op2 = (const float*)d_in[16];
    const float* b_op2 = (const float*)d_in[17];
    const float* w_red2 = (const float*)d_in[18];
    const float* b_red2 = (const float*)d_in[19];
    const float* w_exp3 = (const float*)d_in[20];
    const float* b_exp3 = (const float*)d_in[21];
    const float* w_op3 = (const float*)d_in[22];
    const float* b_op3 = (const float*)d_in[23];
    const int* act = (const int*)d_in[24];
    float* out = (float*)d_out;

    static int attr_set = 0;
    if (!attr_set) {
        cudaFuncSetAttribute(k_o3, cudaFuncAttributeMaxDynamicSharedMemorySize, SMEM_O3);
        attr_set = 1;
    }

    k_prep<<<(W_TOTAL + 255) / 256, 256>>>(w_op0, w_red0, w_exp1, w_op1, w_red1,
                                           w_exp2, w_op2, w_red2, w_exp3, w_op3);
    k_prep2<<<48, 256>>>(w_op3);
    k_r0<<<8, 64>>>(x1);
    k_r1<<<256, 64>>>(x2);
    k_r2<<<8192, 64>>>(x3);
    k_y2e<<<512, 96>>>(x2);
    k_o0o1<<<8, 64>>>(x0, x1, b_op0, b_red0, b_exp1, b_op1, b_red1, act, out);
    k_o2<<<8192, 256>>>(x1, x2, b_exp2, b_op2, b_red2, act, out);
    k_o3<<<4096, 256, SMEM_O3>>>(x3, b_exp3, b_op3, act, out);
}

// round 7
// speedup vs baseline: 2.5940x; 1.2893x over previous
#include <cuda_runtime.h>
#include <cuda_bf16.h>

// LogicMachine: B=8, n=32, C=64, O=64
// Output layout (floats): o0[8,64] | o1[8,32,64] | o2[8,32,32,64] | o3[8,32,32,32,64]
#define OUT0 0
#define OUT1 512
#define OUT2 16896
#define OUT3 541184

// Transposed-weight pool offsets (layout [in][64] each) — used by o0/o1/o2 kernels
#define W_OP0_T   0
#define W_RED0_T  4096
#define W_EXP1_T  12288
#define W_OP1_T   16384
#define W_RED1_T  20480
#define W_EXP2_T  28672
#define W_OP2_T   36864
#define W_RED2_T  45056
#define W_TOTAL   61440

__device__ __align__(16) float d_wt[W_TOTAL];
__device__ __align__(16) float d_r0[8 * 128];
__device__ __align__(16) float d_r1[8 * 32 * 128];
__device__ __align__(16) float d_r2[8 * 32 * 32 * 128];
// bf16 hi/lo B-operand images for o3 MMA: 12 chunks x [64 o][64 c], plain layout
// chunk q<6: w_op3[:, q*64:...], q>=6: w_exp3[:, (q-6)*64:...]
__device__ __align__(16) __nv_bfloat16 d_wBhi[12 * 4096];
__device__ __align__(16) __nv_bfloat16 d_wBlo[12 * 4096];

// ---------------- helpers ----------------
__device__ __forceinline__ float sigf(float s) { return 1.0f / (1.0f + __expf(-s)); }

__device__ __forceinline__ int any_bits(const int* act, int lo, int hi) {
    int g = 0;
    for (int b = 0; b < 8; ++b)
        for (int t = lo; t < hi; ++t) g |= act[b * 10 + t];
    return g;
}
__device__ __forceinline__ unsigned smem_u32(const void* p) {
    return (unsigned)__cvta_generic_to_shared(p);
}
__device__ __forceinline__ void cp16(void* dst_smem, const void* src) {
    unsigned sdst = smem_u32(dst_smem);
    asm volatile("cp.async.ca.shared.global [%0], [%1], 16;" :: "r"(sdst), "l"(src));
}
__device__ __forceinline__ void cp_commit() { asm volatile("cp.async.commit_group;"); }
__device__ __forceinline__ void cp_wait0() { asm volatile("cp.async.wait_group 0;"); }

__device__ __forceinline__ void ldm4(unsigned* r, unsigned addr) {
    asm volatile("ldmatrix.sync.aligned.m8n8.x4.shared.b16 {%0,%1,%2,%3}, [%4];"
                 : "=r"(r[0]), "=r"(r[1]), "=r"(r[2]), "=r"(r[3]) : "r"(addr));
}
__device__ __forceinline__ void mma_bf16(float* c, const unsigned* a, unsigned b0, unsigned b1) {
    asm volatile(
        "mma.sync.aligned.m16n8k16.row.col.f32.bf16.bf16.f32 "
        "{%0,%1,%2,%3}, {%4,%5,%6,%7}, {%8,%9}, {%0,%1,%2,%3};"
        : "+f"(c[0]), "+f"(c[1]), "+f"(c[2]), "+f"(c[3])
        : "r"(a[0]), "r"(a[1]), "r"(a[2]), "r"(a[3]), "r"(b0), "r"(b1));
}

// ---------------- weight transpose (o0/o1/o2 weights) ----------------
__global__ void k_prep(const float* __restrict__ w_op0, const float* __restrict__ w_red0,
                       const float* __restrict__ w_exp1, const float* __restrict__ w_op1,
                       const float* __restrict__ w_red1, const float* __restrict__ w_exp2,
                       const float* __restrict__ w_op2, const float* __restrict__ w_red2) {
    int tid = blockIdx.x * 256 + threadIdx.x;
    if (tid >= W_TOTAL) return;
    const float* src;
    int off, IN;
    if (tid < 4096)        { src = w_op0;  off = tid;          IN = 64;  }
    else if (tid < 12288)  { src = w_red0; off = tid - 4096;   IN = 128; }
    else if (tid < 16384)  { src = w_exp1; off = tid - 12288;  IN = 64;  }
    else if (tid < 20480)  { src = w_op1;  off = tid - 16384;  IN = 64;  }
    else if (tid < 28672)  { src = w_red1; off = tid - 20480;  IN = 128; }
    else if (tid < 36864)  { src = w_exp2; off = tid - 28672;  IN = 128; }
    else if (tid < 45056)  { src = w_op2;  off = tid - 36864;  IN = 128; }
    else                   { src = w_red2; off = tid - 45056;  IN = 256; }
    int in = off >> 6, o = off & 63;
    d_wt[tid] = src[o * IN + in];
}

// ---------------- o3 weight images: bf16 hi/lo, plain [q][o][c] ----------------
__global__ void k_prep3(const float* __restrict__ w_exp3, const float* __restrict__ w_op3) {
    int tid = blockIdx.x * 256 + threadIdx.x;
    if (tid >= 12 * 4096) return;
    int q = tid >> 12, idx = tid & 4095;
    int o = idx >> 6, c = idx & 63;
    const float* w = (q < 6) ? w_op3 : w_exp3;
    float v = w[o * 384 + (q % 6) * 64 + c];
    __nv_bfloat16 h = __float2bfloat16(v);
    __nv_bfloat16 l = __float2bfloat16(v - __bfloat162float(h));
    d_wBhi[tid] = h;
    d_wBlo[tid] = l;
}

// ---------------- reductions ----------------
__global__ void k_r0(const float* __restrict__ x1) {
    int b = blockIdx.x, c = threadIdx.x;
    float mx = -3.4e38f, mn = 3.4e38f;
    for (int i = 0; i < 32; ++i) {
        float v = x1[(b * 32 + i) * 64 + c];
        mx = fmaxf(mx, v);
        mn = fminf(mn, v);
    }
    d_r0[b * 128 + 2 * c] = mx;
    d_r0[b * 128 + 2 * c + 1] = mn;
}

__global__ void k_r1(const float* __restrict__ x2) {
    int b = blockIdx.x >> 5, i = blockIdx.x & 31, c = threadIdx.x;
    float mx = -3.4e38f, mn = 3.4e38f;
    for (int j = 0; j < 32; ++j) {
        if (j == i) continue;
        float v = x2[((b * 32 + i) * 32 + j) * 64 + c];
        mx = fmaxf(mx, v);
        mn = fminf(mn, v);
    }
    d_r1[(b * 32 + i) * 128 + 2 * c] = mx;
    d_r1[(b * 32 + i) * 128 + 2 * c + 1] = mn;
}

__global__ void k_r2(const float* __restrict__ x3) {
    int x = blockIdx.x;
    int b = x >> 10, i = (x >> 5) & 31, j = x & 31, c = threadIdx.x;
    float mx, mn;
    if (i == j) {
        mx = 0.0f;
        mn = 1.0f;
    } else {
        mx = -3.4e38f; mn = 3.4e38f;
        const float* base = x3 + ((b * 32 + i) * 32 + j) * 2048 + c;
        for (int k = 0; k < 32; ++k) {
            if (k == i || k == j) continue;
            float v = base[k * 64];
            mx = fmaxf(mx, v);
            mn = fminf(mn, v);
        }
    }
    int row = ((b * 32 + i) * 32 + j) * 128;
    d_r2[row + 2 * c] = mx;
    d_r2[row + 2 * c + 1] = mn;
}

// ---------------- o0 + o1 ----------------
__global__ void k_o0o1(const float* __restrict__ x0, const float* __restrict__ x1,
                       const float* __restrict__ b_op0, const float* __restrict__ b_red0,
                       const float* __restrict__ b_exp1, const float* __restrict__ b_op1,
                       const float* __restrict__ b_red1,
                       const int* __restrict__ act, float* __restrict__ out) {
    int b = blockIdx.x, o = threadIdx.x;
    const int* ab = act + b * 10;
    int g0 = any_bits(act, 0, 2);
    int g1 = any_bits(act, 2, 5);

    float s0 = 0.f;
    if (ab[0]) {
        float d = 0.f;
        for (int c = 0; c < 64; ++c) d += x0[b * 64 + c] * d_wt[W_OP0_T + c * 64 + o];
        s0 += d + b_op0[o];
    }
    if (ab[1]) {
        float d = 0.f;
        for (int c = 0; c < 128; ++c) d += d_r0[b * 128 + c] * d_wt[W_RED0_T + c * 64 + o];
        s0 += d + b_red0[o];
    }
    out[OUT0 + b * 64 + o] = g0 ? sigf(s0) : 0.f;

    float sE = 0.f;
    if (ab[2]) {
        float d = 0.f;
        for (int c = 0; c < 64; ++c) d += x0[b * 64 + c] * d_wt[W_EXP1_T + c * 64 + o];
        sE = d + b_exp1[o];
    }
    for (int i = 0; i < 32; ++i) {
        float s1 = sE;
        if (ab[3]) {
            float d = 0.f;
            for (int c = 0; c < 64; ++c) d += x1[(b * 32 + i) * 64 + c] * d_wt[W_OP1_T + c * 64 + o];
            s1 += d + b_op1[o];
        }
        if (ab[4]) {
            float d = 0.f;
            for (int c = 0; c < 128; ++c) d += d_r1[(b * 32 + i) * 128 + c] * d_wt[W_RED1_T + c * 64 + o];
            s1 += d + b_red1[o];
        }
        out[OUT1 + (b * 32 + i) * 64 + o] = g1 ? sigf(s1) : 0.f;
    }
}

// ---------------- o2 ----------------
__global__ void k_o2(const float* __restrict__ x1, const float* __restrict__ x2,
                     const float* __restrict__ b_exp2, const float* __restrict__ b_op2,
                     const float* __restrict__ b_red2,
                     const int* __restrict__ act, float* __restrict__ out) {
    __shared__ float ein[512];
    __shared__ float psum[4][64];
    int x = blockIdx.x;
    int b = x >> 10, i = (x >> 5) & 31, j = x & 31;
    int tx = threadIdx.x;
    const int* ab = act + b * 10;
    int g2 = any_bits(act, 5, 8);

    for (int idx = tx; idx < 512; idx += 256) {
        float v;
        if (idx < 64)       v = x1[(b * 32 + i) * 64 + idx];
        else if (idx < 128) v = x1[(b * 32 + j) * 64 + idx - 64];
        else if (idx < 192) v = x2[((b * 32 + i) * 32 + j) * 64 + idx - 128];
        else if (idx < 256) v = x2[((b * 32 + j) * 32 + i) * 64 + idx - 192];
        else if (idx < 384) v = d_r2[((b * 32 + i) * 32 + j) * 128 + idx - 256];
        else                v = d_r2[((b * 32 + j) * 32 + i) * 128 + idx - 384];
        ein[idx] = v;
    }
    __syncthreads();

    int o = tx & 63, q4 = tx >> 6;
    int bit = (q4 == 0) ? ab[5] : (q4 == 1) ? ab[6] : ab[7];
    int wtoff = (q4 == 0) ? W_EXP2_T : (q4 == 1) ? W_OP2_T : (W_RED2_T + ((q4 == 3) ? 128 * 64 : 0));
    int eoff = q4 * 128;
    float d = 0.f;
    if (bit) {
#pragma unroll 8
        for (int c = 0; c < 128; ++c) d += ein[eoff + c] * d_wt[wtoff + c * 64 + o];
    }
    psum[q4][o] = d;
    __syncthreads();
    if (q4 == 0) {
        float s = psum[0][o] + psum[1][o] + psum[2][o] + psum[3][o]
                + (float)ab[5] * b_exp2[o] + (float)ab[6] * b_op2[o] + (float)ab[7] * b_red2[o];
        out[OUT2 + ((b * 32 + i) * 32 + j) * 64 + o] = g2 ? sigf(s) : 0.f;
    }
}

// ---------------- o3: mma.sync bf16-split GEMM ----------------
// Per CTA (b,i,jgroup4): D[128 pos, 64 out] = sum over K-chunks of A_q[128,64]·B_q[64,64]^T
// chunks 0-5 (gated a9): A rows = permuted x3 rows, B = w_op3 slices
// chunks 6-11 (gated a8): A rows = x2 rows (expand branch), B = w_exp3 slices
// fp32 emulated as bf16 hi/lo: passes AhBh + AhBl + AlBh per k-step.
// smem: A_hi[128x72 bf16 pitch] A_lo | B_hi[64x72] B_lo   (pitch 144B, ldmatrix-conflict-free)
#define A_HI 0
#define A_LO 18432
#define B_HI 36864
#define B_LO 46080
#define O3_SMEM 55296

__device__ __forceinline__ int elem_off(int q, int b, int i, int j, int k) {
    switch (q) {
        case 0:  return (((b * 32 + i) * 1024) + j * 32 + k) * 64;
        case 1:  return (((b * 32 + i) * 1024) + k * 32 + j) * 64;
        case 2:  return (((b * 32 + j) * 1024) + i * 32 + k) * 64;
        case 3:  return (((b * 32 + k) * 1024) + i * 32 + j) * 64;
        case 4:  return (((b * 32 + j) * 1024) + k * 32 + i) * 64;
        case 5:  return (((b * 32 + k) * 1024) + j * 32 + i) * 64;
        case 6:  return ((b * 32 + i) * 32 + j) * 64;
        case 7:  return ((b * 32 + i) * 32 + k) * 64;
        case 8:  return ((b * 32 + j) * 32 + i) * 64;
        case 9:  return ((b * 32 + k) * 32 + i) * 64;
        case 10: return ((b * 32 + j) * 32 + k) * 64;
        default: return ((b * 32 + k) * 32 + j) * 64;
    }
}

__device__ __forceinline__ void cvt4(float4 v, unsigned long long& hi, unsigned long long& lo) {
    __nv_bfloat16 h0 = __float2bfloat16(v.x), h1 = __float2bfloat16(v.y);
    __nv_bfloat16 h2 = __float2bfloat16(v.z), h3 = __float2bfloat16(v.w);
    __nv_bfloat16 l0 = __float2bfloat16(v.x - __bfloat162float(h0));
    __nv_bfloat16 l1 = __float2bfloat16(v.y - __bfloat162float(h1));
    __nv_bfloat16 l2 = __float2bfloat16(v.z - __bfloat162float(h2));
    __nv_bfloat16 l3 = __float2bfloat16(v.w - __bfloat162float(h3));
    hi = (unsigned long long)__bfloat16_as_ushort(h0)
       | ((unsigned long long)__bfloat16_as_ushort(h1) << 16)
       | ((unsigned long long)__bfloat16_as_ushort(h2) << 32)
       | ((unsigned long long)__bfloat16_as_ushort(h3) << 48);
    lo = (unsigned long long)__bfloat16_as_ushort(l0)
       | ((unsigned long long)__bfloat16_as_ushort(l1) << 16)
       | ((unsigned long long)__bfloat16_as_ushort(l2) << 32)
       | ((unsigned long long)__bfloat16_as_ushort(l3) << 48);
}

__global__ void __launch_bounds__(256, 2)
k_o3(const float* __restrict__ x3, const float* __restrict__ x2,
     const float* __restrict__ b_exp3, const float* __restrict__ b_op3,
     const int* __restrict__ act, float* __restrict__ out) {
    extern __shared__ char sm[];
    int bid = blockIdx.x;
    int b = bid >> 8, i = (bid >> 3) & 31, jbase = (bid & 7) * 4;
    int tx = threadIdx.x, warp = tx >> 5, lane = tx & 31;

    int g3 = any_bits(act, 8, 10);
    int a8 = act[b * 10 + 8], a9 = act[b * 10 + 9];

    if (!g3 || (!a8 && !a9)) {
        float fill = g3 ? 0.5f : 0.0f;
        float4 f4 = make_float4(fill, fill, fill, fill);
        float4* ob = (float4*)(out + OUT3 + ((b * 32 + i) * 32 + jbase) * 2048);
        for (int f = tx; f < 2048; f += 256) ob[f] = f4;
        return;
    }

    // chunk schedule
    int qs[12], nq = 0;
    if (a9) { for (int q = 0; q < 6; ++q) qs[nq++] = q; }
    if (a8) { for (int q = 6; q < 12; ++q) qs[nq++] = q; }

    unsigned smb = smem_u32(sm);
    // per-lane ldmatrix addresses (byte offsets within planes)
    int rbase = warp * 16;
    unsigned aoff = (unsigned)((rbase + ((lane >> 3) & 1) * 8 + (lane & 7)) * 144
                               + ((lane >> 4) & 1) * 16);
    unsigned boff = (unsigned)((((lane >> 4) & 1) * 8 + (lane & 7)) * 144
                               + ((lane >> 3) & 1) * 16);

    float acc[8][4];
#pragma unroll
    for (int nt = 0; nt < 8; ++nt)
#pragma unroll
        for (int r = 0; r < 4; ++r) acc[nt][r] = 0.f;

    for (int s = 0; s < nq; ++s) {
        int q = qs[s];
        __syncthreads();  // previous chunk's compute done before overwrite
        // stage A: 128 rows x 64 floats -> hi/lo bf16, pitch 144B
        {
            const float* src = (q < 6) ? x3 : x2;
#pragma unroll
            for (int it = 0; it < 8; ++it) {
                int u = tx + (it << 8);
                int m = u >> 4, g = u & 15;
                float4 v = __ldg((const float4*)(src + elem_off(q, b, i, jbase + (m >> 5), m & 31)) + g);
                unsigned long long hp, lp;
                cvt4(v, hp, lp);
                int off = m * 144 + g * 8;
                *(unsigned long long*)(sm + A_HI + off) = hp;
                *(unsigned long long*)(sm + A_LO + off) = lp;
            }
        }
        // stage B: 64 rows x 64 bf16 (128B) -> pitch 144B, hi+lo
        {
            const char* wh = (const char*)(d_wBhi + q * 4096);
            const char* wl = (const char*)(d_wBlo + q * 4096);
#pragma unroll
            for (int it = 0; it < 2; ++it) {
                int u = tx + (it << 8);  // 0..511: row o = u>>3, seg = u&7
                int o = u >> 3, seg = u & 7;
                cp16(sm + B_HI + o * 144 + seg * 16, wh + o * 128 + seg * 16);
                cp16(sm + B_LO + o * 144 + seg * 16, wl + o * 128 + seg * 16);
            }
            cp_commit();
            cp_wait0();
        }
        __syncthreads();

        // compute: 4 k-steps of k16
#pragma unroll
        for (int ks = 0; ks < 4; ++ks) {
            unsigned Ah[4], Al[4];
            ldm4(Ah, smb + A_HI + aoff + ks * 32);
            ldm4(Al, smb + A_LO + aoff + ks * 32);
#pragma unroll
            for (int p = 0; p < 4; ++p) {
                unsigned Bh[4], Bl[4];
                ldm4(Bh, smb + B_HI + boff + p * (16 * 144) + ks * 32);
                ldm4(Bl, smb + B_LO + boff + p * (16 * 144) + ks * 32);
                mma_bf16(acc[2 * p],     Ah, Bh[0], Bh[1]);
                mma_bf16(acc[2 * p + 1], Ah, Bh[2], Bh[3]);
                mma_bf16(acc[2 * p],     Ah, Bl[0], Bl[1]);
                mma_bf16(acc[2 * p + 1], Ah, Bl[2], Bl[3]);
                mma_bf16(acc[2 * p],     Al, Bh[0], Bh[1]);
                mma_bf16(acc[2 * p + 1], Al, Bh[2], Bh[3]);
            }
        }
    }

    // epilogue: warp w owns D rows w*16..+15 (jj = w>>1, k = (w&1)*16 + r)
    int jj = warp >> 1;
    int kbase = (warp & 1) * 16;
    int r0 = lane >> 2;
    int ocol = 2 * (lane & 3);
    float* orow0 = out + OUT3 + (((b * 32 + i) * 32 + (jbase + jj)) * 32 + kbase + r0) * 64;
    float* orow1 = orow0 + 8 * 64;
#pragma unroll
    for (int nt = 0; nt < 8; ++nt) {
        int o = nt * 8 + ocol;
        float bb0 = (a9 ? b_op3[o] : 0.f) + (a8 ? b_exp3[o] : 0.f);
        float bb1 = (a9 ? b_op3[o + 1] : 0.f) + (a8 ? b_exp3[o + 1] : 0.f);
        float2 v0 = make_float2(sigf(acc[nt][0] + bb0), sigf(acc[nt][1] + bb1));
        float2 v1 = make_float2(sigf(acc[nt][2] + bb0), sigf(acc[nt][3] + bb1));
        *(float2*)(orow0 + o) = v0;
        *(float2*)(orow1 + o) = v1;
    }
}

// ---------------- launch ----------------
extern "C" void kernel_launch(void* const* d_in, const int* in_sizes, int n_in,
                              void* d_out, int out_size) {
    const float* x0 = (const float*)d_in[0];
    const float* x1 = (const float*)d_in[1];
    const float* x2 = (const float*)d_in[2];
    const float* x3 = (const float*)d_in[3];
    const float* w_op0 = (const float*)d_in[4];
    const float* b_op0 = (const float*)d_in[5];
    const float* w_red0 = (const float*)d_in[6];
    const float* b_red0 = (const float*)d_in[7];
    const float* w_exp1 = (const float*)d_in[8];
    const float* b_exp1 = (const float*)d_in[9];
    const float* w_op1 = (const float*)d_in[10];
    const float* b_op1 = (const float*)d_in[11];
    const float* w_red1 = (const float*)d_in[12];
    const float* b_red1 = (const float*)d_in[13];
    const float* w_exp2 = (const float*)d_in[14];
    const float* b_exp2 = (const float*)d_in[15];
    const float* w_op2 = (const float*)d_in[16];
    const float* b_op2 = (const float*)d_in[17];
    const float* w_red2 = (const float*)d_in[18];
    const float* b_red2 = (const float*)d_in[19];
    const float* w_exp3 = (const float*)d_in[20];
    const float* b_exp3 = (const float*)d_in[21];
    const float* w_op3 = (const float*)d_in[22];
    const float* b_op3 = (const float*)d_in[23];
    const int* act = (const int*)d_in[24];
    float* out = (float*)d_out;

    static int attr_set = 0;
    if (!attr_set) {
        cudaFuncSetAttribute(k_o3, cudaFuncAttributeMaxDynamicSharedMemorySize, O3_SMEM);
        attr_set = 1;
    }

    k_prep<<<(W_TOTAL + 255) / 256, 256>>>(w_op0, w_red0, w_exp1, w_op1, w_red1,
                                           w_exp2, w_op2, w_red2);
    k_prep3<<<192, 256>>>(w_exp3, w_op3);
    k_r0<<<8, 64>>>(x1);
    k_r1<<<256, 64>>>(x2);
    k_r2<<<8192, 64>>>(x3);
    k_o0o1<<<8, 64>>>(x0, x1, b_op0, b_red0, b_exp1, b_op1, b_red1, act, out);
    k_o2<<<8192, 256>>>(x1, x2, b_exp2, b_op2, b_red2, act, out);
    k_o3<<<2048, 256, O3_SMEM>>>(x3, x2, b_exp3, b_op3, act, out);
}

// round 8
// speedup vs baseline: 2.7905x; 1.0757x over previous
#include <cuda_runtime.h>
#include <cuda_bf16.h>

// LogicMachine: B=8, n=32, C=64, O=64
// Output layout (floats): o0[8,64] | o1[8,32,64] | o2[8,32,32,64] | o3[8,32,32,32,64]
#define OUT0 0
#define OUT1 512
#define OUT2 16896
#define OUT3 541184

// Transposed-weight pool offsets (layout [in][64] each) — used by o0/o1/o2 kernels
#define W_OP0_T   0
#define W_RED0_T  4096
#define W_EXP1_T  12288
#define W_OP1_T   16384
#define W_RED1_T  20480
#define W_EXP2_T  28672
#define W_OP2_T   36864
#define W_RED2_T  45056
#define W_TOTAL   61440

__device__ __align__(16) float d_wt[W_TOTAL];
__device__ __align__(16) float d_r0[8 * 128];
__device__ __align__(16) float d_r1[8 * 32 * 128];
__device__ __align__(16) float d_r2[8 * 32 * 32 * 128];
// bf16 hi/lo B-operand images for o3 MMA: 12 chunks x [64 o][64 c], plain layout
__device__ __align__(16) __nv_bfloat16 d_wBhi[12 * 4096];
__device__ __align__(16) __nv_bfloat16 d_wBlo[12 * 4096];
// Pre-split bf16 hi/lo images of x3 and x2 (same index layout as the fp32 originals)
__device__ __align__(16) __nv_bfloat16 d_x3hi[8 * 32 * 32 * 32 * 64];
__device__ __align__(16) __nv_bfloat16 d_x3lo[8 * 32 * 32 * 32 * 64];
__device__ __align__(16) __nv_bfloat16 d_x2hi[8 * 32 * 32 * 64];
__device__ __align__(16) __nv_bfloat16 d_x2lo[8 * 32 * 32 * 64];

// ---------------- helpers ----------------
__device__ __forceinline__ float sigf(float s) { return 1.0f / (1.0f + __expf(-s)); }

__device__ __forceinline__ int any_bits(const int* act, int lo, int hi) {
    int g = 0;
    for (int b = 0; b < 8; ++b)
        for (int t = lo; t < hi; ++t) g |= act[b * 10 + t];
    return g;
}
__device__ __forceinline__ unsigned smem_u32(const void* p) {
    return (unsigned)__cvta_generic_to_shared(p);
}
__device__ __forceinline__ void cp16(void* dst_smem, const void* src) {
    unsigned sdst = smem_u32(dst_smem);
    asm volatile("cp.async.ca.shared.global [%0], [%1], 16;" :: "r"(sdst), "l"(src));
}
__device__ __forceinline__ void cp_commit() { asm volatile("cp.async.commit_group;"); }
__device__ __forceinline__ void cp_wait0() { asm volatile("cp.async.wait_group 0;"); }

__device__ __forceinline__ void ldm4(unsigned* r, unsigned addr) {
    asm volatile("ldmatrix.sync.aligned.m8n8.x4.shared.b16 {%0,%1,%2,%3}, [%4];"
                 : "=r"(r[0]), "=r"(r[1]), "=r"(r[2]), "=r"(r[3]) : "r"(addr));
}
__device__ __forceinline__ void mma_bf16(float* c, const unsigned* a, unsigned b0, unsigned b1) {
    asm volatile(
        "mma.sync.aligned.m16n8k16.row.col.f32.bf16.bf16.f32 "
        "{%0,%1,%2,%3}, {%4,%5,%6,%7}, {%8,%9}, {%0,%1,%2,%3};"
        : "+f"(c[0]), "+f"(c[1]), "+f"(c[2]), "+f"(c[3])
        : "r"(a[0]), "r"(a[1]), "r"(a[2]), "r"(a[3]), "r"(b0), "r"(b1));
}

__device__ __forceinline__ void cvt4(float4 v, unsigned long long& hi, unsigned long long& lo) {
    __nv_bfloat16 h0 = __float2bfloat16(v.x), h1 = __float2bfloat16(v.y);
    __nv_bfloat16 h2 = __float2bfloat16(v.z), h3 = __float2bfloat16(v.w);
    __nv_bfloat16 l0 = __float2bfloat16(v.x - __bfloat162float(h0));
    __nv_bfloat16 l1 = __float2bfloat16(v.y - __bfloat162float(h1));
    __nv_bfloat16 l2 = __float2bfloat16(v.z - __bfloat162float(h2));
    __nv_bfloat16 l3 = __float2bfloat16(v.w - __bfloat162float(h3));
    hi = (unsigned long long)__bfloat16_as_ushort(h0)
       | ((unsigned long long)__bfloat16_as_ushort(h1) << 16)
       | ((unsigned long long)__bfloat16_as_ushort(h2) << 32)
       | ((unsigned long long)__bfloat16_as_ushort(h3) << 48);
    lo = (unsigned long long)__bfloat16_as_ushort(l0)
       | ((unsigned long long)__bfloat16_as_ushort(l1) << 16)
       | ((unsigned long long)__bfloat16_as_ushort(l2) << 32)
       | ((unsigned long long)__bfloat16_as_ushort(l3) << 48);
}

// ---------------- fp32 -> bf16 hi/lo split (x3, x2) ----------------
__global__ void k_split(const float4* __restrict__ src,
                        unsigned long long* __restrict__ hi,
                        unsigned long long* __restrict__ lo, int n4) {
    int t = blockIdx.x * 256 + threadIdx.x;
    if (t >= n4) return;
    float4 v = __ldg(src + t);
    unsigned long long hp, lp;
    cvt4(v, hp, lp);
    hi[t] = hp;
    lo[t] = lp;
}

// ---------------- weight transpose (o0/o1/o2 weights) ----------------
__global__ void k_prep(const float* __restrict__ w_op0, const float* __restrict__ w_red0,
                       const float* __restrict__ w_exp1, const float* __restrict__ w_op1,
                       const float* __restrict__ w_red1, const float* __restrict__ w_exp2,
                       const float* __restrict__ w_op2, const float* __restrict__ w_red2) {
    int tid = blockIdx.x * 256 + threadIdx.x;
    if (tid >= W_TOTAL) return;
    const float* src;
    int off, IN;
    if (tid < 4096)        { src = w_op0;  off = tid;          IN = 64;  }
    else if (tid < 12288)  { src = w_red0; off = tid - 4096;   IN = 128; }
    else if (tid < 16384)  { src = w_exp1; off = tid - 12288;  IN = 64;  }
    else if (tid < 20480)  { src = w_op1;  off = tid - 16384;  IN = 64;  }
    else if (tid < 28672)  { src = w_red1; off = tid - 20480;  IN = 128; }
    else if (tid < 36864)  { src = w_exp2; off = tid - 28672;  IN = 128; }
    else if (tid < 45056)  { src = w_op2;  off = tid - 36864;  IN = 128; }
    else                   { src = w_red2; off = tid - 45056;  IN = 256; }
    int in = off >> 6, o = off & 63;
    d_wt[tid] = src[o * IN + in];
}

// ---------------- o3 weight images: bf16 hi/lo, plain [q][o][c] ----------------
__global__ void k_prep3(const float* __restrict__ w_exp3, const float* __restrict__ w_op3) {
    int tid = blockIdx.x * 256 + threadIdx.x;
    if (tid >= 12 * 4096) return;
    int q = tid >> 12, idx = tid & 4095;
    int o = idx >> 6, c = idx & 63;
    const float* w = (q < 6) ? w_op3 : w_exp3;
    float v = w[o * 384 + (q % 6) * 64 + c];
    __nv_bfloat16 h = __float2bfloat16(v);
    __nv_bfloat16 l = __float2bfloat16(v - __bfloat162float(h));
    d_wBhi[tid] = h;
    d_wBlo[tid] = l;
}

// ---------------- reductions ----------------
__global__ void k_r0(const float* __restrict__ x1) {
    int b = blockIdx.x, c = threadIdx.x;
    float mx = -3.4e38f, mn = 3.4e38f;
    for (int i = 0; i < 32; ++i) {
        float v = x1[(b * 32 + i) * 64 + c];
        mx = fmaxf(mx, v);
        mn = fminf(mn, v);
    }
    d_r0[b * 128 + 2 * c] = mx;
    d_r0[b * 128 + 2 * c + 1] = mn;
}

__global__ void k_r1(const float* __restrict__ x2) {
    int b = blockIdx.x >> 5, i = blockIdx.x & 31, c = threadIdx.x;
    float mx = -3.4e38f, mn = 3.4e38f;
    for (int j = 0; j < 32; ++j) {
        if (j == i) continue;
        float v = x2[((b * 32 + i) * 32 + j) * 64 + c];
        mx = fmaxf(mx, v);
        mn = fminf(mn, v);
    }
    d_r1[(b * 32 + i) * 128 + 2 * c] = mx;
    d_r1[(b * 32 + i) * 128 + 2 * c + 1] = mn;
}

__global__ void k_r2(const float* __restrict__ x3) {
    int x = blockIdx.x;
    int b = x >> 10, i = (x >> 5) & 31, j = x & 31, c = threadIdx.x;
    float mx, mn;
    if (i == j) {
        mx = 0.0f;
        mn = 1.0f;
    } else {
        mx = -3.4e38f; mn = 3.4e38f;
        const float* base = x3 + ((b * 32 + i) * 32 + j) * 2048 + c;
        for (int k = 0; k < 32; ++k) {
            if (k == i || k == j) continue;
            float v = base[k * 64];
            mx = fmaxf(mx, v);
            mn = fminf(mn, v);
        }
    }
    int row = ((b * 32 + i) * 32 + j) * 128;
    d_r2[row + 2 * c] = mx;
    d_r2[row + 2 * c + 1] = mn;
}

// ---------------- o0 + o1 ----------------
__global__ void k_o0o1(const float* __restrict__ x0, const float* __restrict__ x1,
                       const float* __restrict__ b_op0, const float* __restrict__ b_red0,
                       const float* __restrict__ b_exp1, const float* __restrict__ b_op1,
                       const float* __restrict__ b_red1,
                       const int* __restrict__ act, float* __restrict__ out) {
    int b = blockIdx.x, o = threadIdx.x;
    const int* ab = act + b * 10;
    int g0 = any_bits(act, 0, 2);
    int g1 = any_bits(act, 2, 5);

    float s0 = 0.f;
    if (ab[0]) {
        float d = 0.f;
        for (int c = 0; c < 64; ++c) d += x0[b * 64 + c] * d_wt[W_OP0_T + c * 64 + o];
        s0 += d + b_op0[o];
    }
    if (ab[1]) {
        float d = 0.f;
        for (int c = 0; c < 128; ++c) d += d_r0[b * 128 + c] * d_wt[W_RED0_T + c * 64 + o];
        s0 += d + b_red0[o];
    }
    out[OUT0 + b * 64 + o] = g0 ? sigf(s0) : 0.f;

    float sE = 0.f;
    if (ab[2]) {
        float d = 0.f;
        for (int c = 0; c < 64; ++c) d += x0[b * 64 + c] * d_wt[W_EXP1_T + c * 64 + o];
        sE = d + b_exp1[o];
    }
    for (int i = 0; i < 32; ++i) {
        float s1 = sE;
        if (ab[3]) {
            float d = 0.f;
            for (int c = 0; c < 64; ++c) d += x1[(b * 32 + i) * 64 + c] * d_wt[W_OP1_T + c * 64 + o];
            s1 += d + b_op1[o];
        }
        if (ab[4]) {
            float d = 0.f;
            for (int c = 0; c < 128; ++c) d += d_r1[(b * 32 + i) * 128 + c] * d_wt[W_RED1_T + c * 64 + o];
            s1 += d + b_red1[o];
        }
        out[OUT1 + (b * 32 + i) * 64 + o] = g1 ? sigf(s1) : 0.f;
    }
}

// ---------------- o2: one block per (b,i), weights staged in smem once ----------------
// smem: ws[512*64] floats (128KB) + ein[512] + psum[16*64]
#define O2_SMEM ((32768 + 512 + 1024) * 4)
__global__ void __launch_bounds__(256, 1)
k_o2(const float* __restrict__ x1, const float* __restrict__ x2,
     const float* __restrict__ b_exp2, const float* __restrict__ b_op2,
     const float* __restrict__ b_red2,
     const int* __restrict__ act, float* __restrict__ out) {
    extern __shared__ float s2[];
    float* ws = s2;
    float* ein = s2 + 32768;
    float* psum = s2 + 33280;
    int b = blockIdx.x >> 5, i = blockIdx.x & 31;
    int tx = threadIdx.x;
    const int* ab = act + b * 10;
    int g2 = any_bits(act, 5, 8);

    // stage weights: rows 0-127 exp2, 128-255 op2, 256-511 red2 (each row = 64 floats)
    for (int u = tx; u < 8192; u += 256) {
        int row = u >> 4, sg = u & 15;
        const float* src;
        if (row < 128)      src = d_wt + W_EXP2_T + row * 64;
        else if (row < 256) src = d_wt + W_OP2_T + (row - 128) * 64;
        else                src = d_wt + W_RED2_T + (row - 256) * 64;
        cp16(ws + row * 64 + sg * 4, src + sg * 4);
    }
    cp_commit();

    int og = (tx & 15) * 4, sl = tx >> 4;
    int bit = ab[5 + (sl >= 4) + (sl >= 8)];
    cp_wait0();
    __syncthreads();

    for (int j = 0; j < 32; ++j) {
        __syncthreads();  // previous j's psum consumed
        for (int idx = tx; idx < 512; idx += 256) {
            float v;
            if (idx < 64)       v = x1[(b * 32 + i) * 64 + idx];
            else if (idx < 128) v = x1[(b * 32 + j) * 64 + idx - 64];
            else if (idx < 192) v = x2[((b * 32 + i) * 32 + j) * 64 + idx - 128];
            else if (idx < 256) v = x2[((b * 32 + j) * 32 + i) * 64 + idx - 192];
            else if (idx < 384) v = d_r2[((b * 32 + i) * 32 + j) * 128 + idx - 256];
            else                v = d_r2[((b * 32 + j) * 32 + i) * 128 + idx - 384];
            ein[idx] = v;
        }
        __syncthreads();

        float4 a = make_float4(0.f, 0.f, 0.f, 0.f);
        if (bit) {
            int cb = sl * 32;
#pragma unroll 8
            for (int c = 0; c < 32; ++c) {
                float xv = ein[cb + c];
                float4 w4 = *(const float4*)(ws + (cb + c) * 64 + og);
                a.x += xv * w4.x; a.y += xv * w4.y;
                a.z += xv * w4.z; a.w += xv * w4.w;
            }
        }
        *(float4*)(psum + sl * 64 + og) = a;
        __syncthreads();
        if (tx < 64) {
            int o = tx;
            float s = 0.f;
#pragma unroll
            for (int t = 0; t < 16; ++t) s += psum[t * 64 + o];
            s += (float)ab[5] * b_exp2[o] + (float)ab[6] * b_op2[o] + (float)ab[7] * b_red2[o];
            out[OUT2 + ((b * 32 + i) * 32 + j) * 64 + o] = g2 ? sigf(s) : 0.f;
        }
    }
}

// ---------------- o3: mma.sync bf16-split GEMM, cp.async staging from pre-split images ----------------
#define A_HI 0
#define A_LO 18432
#define B_HI 36864
#define B_LO 46080
#define O3_SMEM 55296

__device__ __forceinline__ int elem_off(int q, int b, int i, int j, int k) {
    switch (q) {
        case 0:  return (((b * 32 + i) * 1024) + j * 32 + k) * 64;
        case 1:  return (((b * 32 + i) * 1024) + k * 32 + j) * 64;
        case 2:  return (((b * 32 + j) * 1024) + i * 32 + k) * 64;
        case 3:  return (((b * 32 + k) * 1024) + i * 32 + j) * 64;
        case 4:  return (((b * 32 + j) * 1024) + k * 32 + i) * 64;
        case 5:  return (((b * 32 + k) * 1024) + j * 32 + i) * 64;
        case 6:  return ((b * 32 + i) * 32 + j) * 64;
        case 7:  return ((b * 32 + i) * 32 + k) * 64;
        case 8:  return ((b * 32 + j) * 32 + i) * 64;
        case 9:  return ((b * 32 + k) * 32 + i) * 64;
        case 10: return ((b * 32 + j) * 32 + k) * 64;
        default: return ((b * 32 + k) * 32 + j) * 64;
    }
}

__global__ void __launch_bounds__(256, 2)
k_o3(const float* __restrict__ b_exp3, const float* __restrict__ b_op3,
     const int* __restrict__ act, float* __restrict__ out) {
    extern __shared__ char sm[];
    int bid = blockIdx.x;
    int b = bid >> 8, i = (bid >> 3) & 31, jbase = (bid & 7) * 4;
    int tx = threadIdx.x, warp = tx >> 5, lane = tx & 31;

    int g3 = any_bits(act, 8, 10);
    int a8 = act[b * 10 + 8], a9 = act[b * 10 + 9];

    if (!g3 || (!a8 && !a9)) {
        float fill = g3 ? 0.5f : 0.0f;
        float4 f4 = make_float4(fill, fill, fill, fill);
        float4* ob = (float4*)(out + OUT3 + ((b * 32 + i) * 32 + jbase) * 2048);
        for (int f = tx; f < 2048; f += 256) ob[f] = f4;
        return;
    }

    int qs[12], nq = 0;
    if (a9) { for (int q = 0; q < 6; ++q) qs[nq++] = q; }
    if (a8) { for (int q = 6; q < 12; ++q) qs[nq++] = q; }

    unsigned smb = smem_u32(sm);
    int rbase = warp * 16;
    unsigned aoff = (unsigned)((rbase + ((lane >> 3) & 1) * 8 + (lane & 7)) * 144
                               + ((lane >> 4) & 1) * 16);
    unsigned boff = (unsigned)((((lane >> 4) & 1) * 8 + (lane & 7)) * 144
                               + ((lane >> 3) & 1) * 16);

    float acc[8][4];
#pragma unroll
    for (int nt = 0; nt < 8; ++nt)
#pragma unroll
        for (int r = 0; r < 4; ++r) acc[nt][r] = 0.f;

    for (int s = 0; s < nq; ++s) {
        int q = qs[s];
        __syncthreads();
        // stage A from pre-split bf16 images: 128 rows x 128B per half
        {
            const __nv_bfloat16* sh = (q < 6) ? d_x3hi : d_x2hi;
            const __nv_bfloat16* sl = (q < 6) ? d_x3lo : d_x2lo;
#pragma unroll
            for (int it = 0; it < 4; ++it) {
                int u = tx + (it << 8);
                int m = u >> 3, seg = u & 7;
                int off = elem_off(q, b, i, jbase + (m >> 5), m & 31);
                int so = m * 144 + seg * 16;
                cp16(sm + A_HI + so, (const char*)(sh + off) + seg * 16);
                cp16(sm + A_LO + so, (const char*)(sl + off) + seg * 16);
            }
        }
        // stage B: 64 rows x 128B per half
        {
            const char* wh = (const char*)(d_wBhi + q * 4096);
            const char* wl = (const char*)(d_wBlo + q * 4096);
#pragma unroll
            for (int it = 0; it < 2; ++it) {
                int u = tx + (it << 8);
                int o = u >> 3, seg = u & 7;
                cp16(sm + B_HI + o * 144 + seg * 16, wh + o * 128 + seg * 16);
                cp16(sm + B_LO + o * 144 + seg * 16, wl + o * 128 + seg * 16);
            }
        }
        cp_commit();
        cp_wait0();
        __syncthreads();

#pragma unroll
        for (int ks = 0; ks < 4; ++ks) {
            unsigned Ah[4], Al[4];
            ldm4(Ah, smb + A_HI + aoff + ks * 32);
            ldm4(Al, smb + A_LO + aoff + ks * 32);
#pragma unroll
            for (int p = 0; p < 4; ++p) {
                unsigned Bh[4], Bl[4];
                ldm4(Bh, smb + B_HI + boff + p * (16 * 144) + ks * 32);
                ldm4(Bl, smb + B_LO + boff + p * (16 * 144) + ks * 32);
                mma_bf16(acc[2 * p],     Ah, Bh[0], Bh[1]);
                mma_bf16(acc[2 * p + 1], Ah, Bh[2], Bh[3]);
                mma_bf16(acc[2 * p],     Ah, Bl[0], Bl[1]);
                mma_bf16(acc[2 * p + 1], Ah, Bl[2], Bl[3]);
                mma_bf16(acc[2 * p],     Al, Bh[0], Bh[1]);
                mma_bf16(acc[2 * p + 1], Al, Bh[2], Bh[3]);
            }
        }
    }

    // epilogue
    int jj = warp >> 1;
    int kbase = (warp & 1) * 16;
    int r0 = lane >> 2;
    int ocol = 2 * (lane & 3);
    float* orow0 = out + OUT3 + (((b * 32 + i) * 32 + (jbase + jj)) * 32 + kbase + r0) * 64;
    float* orow1 = orow0 + 8 * 64;
#pragma unroll
    for (int nt = 0; nt < 8; ++nt) {
        int o = nt * 8 + ocol;
        float bb0 = (a9 ? b_op3[o] : 0.f) + (a8 ? b_exp3[o] : 0.f);
        float bb1 = (a9 ? b_op3[o + 1] : 0.f) + (a8 ? b_exp3[o + 1] : 0.f);
        float2 v0 = make_float2(sigf(acc[nt][0] + bb0), sigf(acc[nt][1] + bb1));
        float2 v1 = make_float2(sigf(acc[nt][2] + bb0), sigf(acc[nt][3] + bb1));
        *(float2*)(orow0 + o) = v0;
        *(float2*)(orow1 + o) = v1;
    }
}

// ---------------- launch ----------------
extern "C" void kernel_launch(void* const* d_in, const int* in_sizes, int n_in,
                              void* d_out, int out_size) {
    const float* x0 = (const float*)d_in[0];
    const float* x1 = (const float*)d_in[1];
    const float* x2 = (const float*)d_in[2];
    const float* x3 = (const float*)d_in[3];
    const float* w_op0 = (const float*)d_in[4];
    const float* b_op0 = (const float*)d_in[5];
    const float* w_red0 = (const float*)d_in[6];
    const float* b_red0 = (const float*)d_in[7];
    const float* w_exp1 = (const float*)d_in[8];
    const float* b_exp1 = (const float*)d_in[9];
    const float* w_op1 = (const float*)d_in[10];
    const float* b_op1 = (const float*)d_in[11];
    const float* w_red1 = (const float*)d_in[12];
    const float* b_red1 = (const float*)d_in[13];
    const float* w_exp2 = (const float*)d_in[14];
    const float* b_exp2 = (const float*)d_in[15];
    const float* w_op2 = (const float*)d_in[16];
    const float* b_op2 = (const float*)d_in[17];
    const float* w_red2 = (const float*)d_in[18];
    const float* b_red2 = (const float*)d_in[19];
    const float* w_exp3 = (const float*)d_in[20];
    const float* b_exp3 = (const float*)d_in[21];
    const float* w_op3 = (const float*)d_in[22];
    const float* b_op3 = (const float*)d_in[23];
    const int* act = (const int*)d_in[24];
    float* out = (float*)d_out;

    static int attr_set = 0;
    if (!attr_set) {
        cudaFuncSetAttribute(k_o3, cudaFuncAttributeMaxDynamicSharedMemorySize, O3_SMEM);
        cudaFuncSetAttribute(k_o2, cudaFuncAttributeMaxDynamicSharedMemorySize, O2_SMEM);
        attr_set = 1;
    }

    // resolve device-global pointers for k_split targets
    unsigned long long* x3hi;
    unsigned long long* x3lo;
    unsigned long long* x2hi;
    unsigned long long* x2lo;
    cudaGetSymbolAddress((void**)&x3hi, d_x3hi);
    cudaGetSymbolAddress((void**)&x3lo, d_x3lo);
    cudaGetSymbolAddress((void**)&x2hi, d_x2hi);
    cudaGetSymbolAddress((void**)&x2lo, d_x2lo);

    k_prep<<<(W_TOTAL + 255) / 256, 256>>>(w_op0, w_red0, w_exp1, w_op1, w_red1,
                                           w_exp2, w_op2, w_red2);
    k_prep3<<<192, 256>>>(w_exp3, w_op3);
    k_split<<<16384, 256>>>((const float4*)x3, x3hi, x3lo, 4194304);
    k_split<<<512, 256>>>((const float4*)x2, x2hi, x2lo, 131072);
    k_r0<<<8, 64>>>(x1);
    k_r1<<<256, 64>>>(x2);
    k_r2<<<8192, 64>>>(x3);
    k_o0o1<<<8, 64>>>(x0, x1, b_op0, b_red0, b_exp1, b_op1, b_red1, act, out);
    k_o2<<<256, 256, O2_SMEM>>>(x1, x2, b_exp2, b_op2, b_red2, act, out);
    k_o3<<<2048, 256, O3_SMEM>>>(b_exp3, b_op3, act, out);
}

// round 9
// speedup vs baseline: 4.2655x; 1.5286x over previous
#include <cuda_runtime.h>
#include <cuda_bf16.h>

// LogicMachine: B=8, n=32, C=64, O=64
// Output layout (floats): o0[8,64] | o1[8,32,64] | o2[8,32,32,64] | o3[8,32,32,32,64]
#define OUT0 0
#define OUT1 512
#define OUT2 16896
#define OUT3 541184

#define W_OP0_T   0
#define W_RED0_T  4096
#define W_EXP1_T  12288
#define W_OP1_T   16384
#define W_RED1_T  20480
#define W_EXP2_T  28672
#define W_OP2_T   36864
#define W_RED2_T  45056
#define W_TOTAL   61440

__device__ __align__(16) float d_wt[W_TOTAL];
__device__ __align__(16) float d_r0[8 * 128];
__device__ __align__(16) float d_r1[8 * 32 * 128];
__device__ __align__(16) float d_r2[8 * 32 * 32 * 128];
__device__ __align__(16) __nv_bfloat16 d_wBhi[12 * 4096];
__device__ __align__(16) __nv_bfloat16 d_wBlo[12 * 4096];
__device__ __align__(16) __nv_bfloat16 d_x3hi[8 * 32 * 32 * 32 * 64];
__device__ __align__(16) __nv_bfloat16 d_x3lo[8 * 32 * 32 * 32 * 64];
__device__ __align__(16) __nv_bfloat16 d_x2hi[8 * 32 * 32 * 64];
__device__ __align__(16) __nv_bfloat16 d_x2lo[8 * 32 * 32 * 64];

// ---------------- helpers ----------------
__device__ __forceinline__ float sigf(float s) { return 1.0f / (1.0f + __expf(-s)); }

__device__ __forceinline__ int any_bits(const int* act, int lo, int hi) {
    int g = 0;
    for (int b = 0; b < 8; ++b)
        for (int t = lo; t < hi; ++t) g |= act[b * 10 + t];
    return g;
}
__device__ __forceinline__ unsigned smem_u32(const void* p) {
    return (unsigned)__cvta_generic_to_shared(p);
}
__device__ __forceinline__ void cp16(void* dst_smem, const void* src) {
    unsigned sdst = smem_u32(dst_smem);
    asm volatile("cp.async.ca.shared.global [%0], [%1], 16;" :: "r"(sdst), "l"(src));
}
__device__ __forceinline__ void cp_commit() { asm volatile("cp.async.commit_group;"); }
__device__ __forceinline__ void cp_wait0() { asm volatile("cp.async.wait_group 0;"); }
__device__ __forceinline__ void cp_wait1() { asm volatile("cp.async.wait_group 1;"); }

__device__ __forceinline__ void ldm4(unsigned* r, unsigned addr) {
    asm volatile("ldmatrix.sync.aligned.m8n8.x4.shared.b16 {%0,%1,%2,%3}, [%4];"
                 : "=r"(r[0]), "=r"(r[1]), "=r"(r[2]), "=r"(r[3]) : "r"(addr));
}
__device__ __forceinline__ void mma_bf16(float* c, const unsigned* a, unsigned b0, unsigned b1) {
    asm volatile(
        "mma.sync.aligned.m16n8k16.row.col.f32.bf16.bf16.f32 "
        "{%0,%1,%2,%3}, {%4,%5,%6,%7}, {%8,%9}, {%0,%1,%2,%3};"
        : "+f"(c[0]), "+f"(c[1]), "+f"(c[2]), "+f"(c[3])
        : "r"(a[0]), "r"(a[1]), "r"(a[2]), "r"(a[3]), "r"(b0), "r"(b1));
}

__device__ __forceinline__ void cvt4(float4 v, unsigned long long& hi, unsigned long long& lo) {
    __nv_bfloat16 h0 = __float2bfloat16(v.x), h1 = __float2bfloat16(v.y);
    __nv_bfloat16 h2 = __float2bfloat16(v.z), h3 = __float2bfloat16(v.w);
    __nv_bfloat16 l0 = __float2bfloat16(v.x - __bfloat162float(h0));
    __nv_bfloat16 l1 = __float2bfloat16(v.y - __bfloat162float(h1));
    __nv_bfloat16 l2 = __float2bfloat16(v.z - __bfloat162float(h2));
    __nv_bfloat16 l3 = __float2bfloat16(v.w - __bfloat162float(h3));
    hi = (unsigned long long)__bfloat16_as_ushort(h0)
       | ((unsigned long long)__bfloat16_as_ushort(h1) << 16)
       | ((unsigned long long)__bfloat16_as_ushort(h2) << 32)
       | ((unsigned long long)__bfloat16_as_ushort(h3) << 48);
    lo = (unsigned long long)__bfloat16_as_ushort(l0)
       | ((unsigned long long)__bfloat16_as_ushort(l1) << 16)
       | ((unsigned long long)__bfloat16_as_ushort(l2) << 32)
       | ((unsigned long long)__bfloat16_as_ushort(l3) << 48);
}

// ---------------- fp32 -> bf16 hi/lo split (x2) ----------------
__global__ void k_split(const float4* __restrict__ src,
                        unsigned long long* __restrict__ hi,
                        unsigned long long* __restrict__ lo, int n4) {
    int t = blockIdx.x * 256 + threadIdx.x;
    if (t >= n4) return;
    float4 v = __ldg(src + t);
    unsigned long long hp, lp;
    cvt4(v, hp, lp);
    hi[t] = hp;
    lo[t] = lp;
}

// ---------------- fused x3 split + r2 reduction: one block per (b,i,j) ----------------
__global__ void k_sr(const float4* __restrict__ x3) {
    __shared__ float xs[2048];
    __shared__ float red[2][4][64];
    int bid = blockIdx.x;
    int b = bid >> 10, i = (bid >> 5) & 31, j = bid & 31;
    int tx = threadIdx.x;
    unsigned long long* hi = reinterpret_cast<unsigned long long*>(d_x3hi);
    unsigned long long* lo = reinterpret_cast<unsigned long long*>(d_x3lo);
#pragma unroll
    for (int it = 0; it < 2; ++it) {
        int f4 = tx + it * 256;
        float4 v = __ldg(x3 + bid * 512 + f4);
        unsigned long long hp, lp;
        cvt4(v, hp, lp);
        hi[bid * 512 + f4] = hp;
        lo[bid * 512 + f4] = lp;
        *(float4*)(xs + f4 * 4) = v;
    }
    __syncthreads();
    int c = tx & 63, kg = tx >> 6;
    float mx = -3.4e38f, mn = 3.4e38f;
#pragma unroll
    for (int kk = 0; kk < 8; ++kk) {
        int k = kg * 8 + kk;
        if (k == i || k == j) continue;
        float v = xs[k * 64 + c];
        mx = fmaxf(mx, v);
        mn = fminf(mn, v);
    }
    red[0][kg][c] = mx;
    red[1][kg][c] = mn;
    __syncthreads();
    if (tx < 64) {
        float MX, MN;
        if (i == j) { MX = 0.f; MN = 1.f; }
        else {
            MX = fmaxf(fmaxf(red[0][0][tx], red[0][1][tx]), fmaxf(red[0][2][tx], red[0][3][tx]));
            MN = fminf(fminf(red[1][0][tx], red[1][1][tx]), fminf(red[1][2][tx], red[1][3][tx]));
        }
        d_r2[bid * 128 + 2 * tx] = MX;
        d_r2[bid * 128 + 2 * tx + 1] = MN;
    }
}

// ---------------- weight transpose (o0/o1/o2 weights) ----------------
__global__ void k_prep(const float* __restrict__ w_op0, const float* __restrict__ w_red0,
                       const float* __restrict__ w_exp1, const float* __restrict__ w_op1,
                       const float* __restrict__ w_red1, const float* __restrict__ w_exp2,
                       const float* __restrict__ w_op2, const float* __restrict__ w_red2) {
    int tid = blockIdx.x * 256 + threadIdx.x;
    if (tid >= W_TOTAL) return;
    const float* src;
    int off, IN;
    if (tid < 4096)        { src = w_op0;  off = tid;          IN = 64;  }
    else if (tid < 12288)  { src = w_red0; off = tid - 4096;   IN = 128; }
    else if (tid < 16384)  { src = w_exp1; off = tid - 12288;  IN = 64;  }
    else if (tid < 20480)  { src = w_op1;  off = tid - 16384;  IN = 64;  }
    else if (tid < 28672)  { src = w_red1; off = tid - 20480;  IN = 128; }
    else if (tid < 36864)  { src = w_exp2; off = tid - 28672;  IN = 128; }
    else if (tid < 45056)  { src = w_op2;  off = tid - 36864;  IN = 128; }
    else                   { src = w_red2; off = tid - 45056;  IN = 256; }
    int in = off >> 6, o = off & 63;
    d_wt[tid] = src[o * IN + in];
}

// ---------------- o3 weight images: bf16 hi/lo, plain [q][o][c] ----------------
__global__ void k_prep3(const float* __restrict__ w_exp3, const float* __restrict__ w_op3) {
    int tid = blockIdx.x * 256 + threadIdx.x;
    if (tid >= 12 * 4096) return;
    int q = tid >> 12, idx = tid & 4095;
    int o = idx >> 6, c = idx & 63;
    const float* w = (q < 6) ? w_op3 : w_exp3;
    float v = w[o * 384 + (q % 6) * 64 + c];
    __nv_bfloat16 h = __float2bfloat16(v);
    __nv_bfloat16 l = __float2bfloat16(v - __bfloat162float(h));
    d_wBhi[tid] = h;
    d_wBlo[tid] = l;
}

// ---------------- small reductions ----------------
__global__ void k_r0(const float* __restrict__ x1) {
    int b = blockIdx.x, c = threadIdx.x;
    float mx = -3.4e38f, mn = 3.4e38f;
    for (int i = 0; i < 32; ++i) {
        float v = x1[(b * 32 + i) * 64 + c];
        mx = fmaxf(mx, v);
        mn = fminf(mn, v);
    }
    d_r0[b * 128 + 2 * c] = mx;
    d_r0[b * 128 + 2 * c + 1] = mn;
}

__global__ void k_r1(const float* __restrict__ x2) {
    int b = blockIdx.x >> 5, i = blockIdx.x & 31, c = threadIdx.x;
    float mx = -3.4e38f, mn = 3.4e38f;
    for (int j = 0; j < 32; ++j) {
        if (j == i) continue;
        float v = x2[((b * 32 + i) * 32 + j) * 64 + c];
        mx = fmaxf(mx, v);
        mn = fminf(mn, v);
    }
    d_r1[(b * 32 + i) * 128 + 2 * c] = mx;
    d_r1[(b * 32 + i) * 128 + 2 * c + 1] = mn;
}

// ---------------- o0 + o1 (parallel: blocks 0-7 = o0, 8-263 = (b,i) of o1) ----------------
__global__ void k_o0o1(const float* __restrict__ x0, const float* __restrict__ x1,
                       const float* __restrict__ b_op0, const float* __restrict__ b_red0,
                       const float* __restrict__ b_exp1, const float* __restrict__ b_op1,
                       const float* __restrict__ b_red1,
                       const int* __restrict__ act, float* __restrict__ out) {
    int bid = blockIdx.x, o = threadIdx.x;
    if (bid < 8) {
        int b = bid;
        const int* ab = act + b * 10;
        int g0 = any_bits(act, 0, 2);
        float s0 = 0.f;
        if (ab[0]) {
            float d = 0.f;
            for (int c = 0; c < 64; ++c) d += x0[b * 64 + c] * d_wt[W_OP0_T + c * 64 + o];
            s0 += d + b_op0[o];
        }
        if (ab[1]) {
            float d = 0.f;
            for (int c = 0; c < 128; ++c) d += d_r0[b * 128 + c] * d_wt[W_RED0_T + c * 64 + o];
            s0 += d + b_red0[o];
        }
        out[OUT0 + b * 64 + o] = g0 ? sigf(s0) : 0.f;
    } else {
        int u = bid - 8, b = u >> 5, i = u & 31;
        const int* ab = act + b * 10;
        int g1 = any_bits(act, 2, 5);
        float s1 = 0.f;
        if (ab[2]) {
            float d = 0.f;
            for (int c = 0; c < 64; ++c) d += x0[b * 64 + c] * d_wt[W_EXP1_T + c * 64 + o];
            s1 += d + b_exp1[o];
        }
        if (ab[3]) {
            float d = 0.f;
            for (int c = 0; c < 64; ++c) d += x1[(b * 32 + i) * 64 + c] * d_wt[W_OP1_T + c * 64 + o];
            s1 += d + b_op1[o];
        }
        if (ab[4]) {
            float d = 0.f;
            for (int c = 0; c < 128; ++c) d += d_r1[(b * 32 + i) * 128 + c] * d_wt[W_RED1_T + c * 64 + o];
            s1 += d + b_red1[o];
        }
        out[OUT1 + (b * 32 + i) * 64 + o] = g1 ? sigf(s1) : 0.f;
    }
}

// ---------------- o2: one block per (b,i), weights staged in smem once ----------------
#define O2_SMEM ((32768 + 512 + 1024) * 4)
__global__ void __launch_bounds__(256, 1)
k_o2(const float* __restrict__ x1, const float* __restrict__ x2,
     const float* __restrict__ b_exp2, const float* __restrict__ b_op2,
     const float* __restrict__ b_red2,
     const int* __restrict__ act, float* __restrict__ out) {
    extern __shared__ float s2[];
    float* ws = s2;
    float* ein = s2 + 32768;
    float* psum = s2 + 33280;
    int b = blockIdx.x >> 5, i = blockIdx.x & 31;
    int tx = threadIdx.x;
    const int* ab = act + b * 10;
    int g2 = any_bits(act, 5, 8);

    for (int u = tx; u < 8192; u += 256) {
        int row = u >> 4, sg = u & 15;
        const float* src;
        if (row < 128)      src = d_wt + W_EXP2_T + row * 64;
        else if (row < 256) src = d_wt + W_OP2_T + (row - 128) * 64;
        else                src = d_wt + W_RED2_T + (row - 256) * 64;
        cp16(ws + row * 64 + sg * 4, src + sg * 4);
    }
    cp_commit();

    int og = (tx & 15) * 4, sl = tx >> 4;
    int bit = ab[5 + (sl >= 4) + (sl >= 8)];
    cp_wait0();
    __syncthreads();

    for (int j = 0; j < 32; ++j) {
        __syncthreads();
        for (int idx = tx; idx < 512; idx += 256) {
            float v;
            if (idx < 64)       v = x1[(b * 32 + i) * 64 + idx];
            else if (idx < 128) v = x1[(b * 32 + j) * 64 + idx - 64];
            else if (idx < 192) v = x2[((b * 32 + i) * 32 + j) * 64 + idx - 128];
            else if (idx < 256) v = x2[((b * 32 + j) * 32 + i) * 64 + idx - 192];
            else if (idx < 384) v = d_r2[((b * 32 + i) * 32 + j) * 128 + idx - 256];
            else                v = d_r2[((b * 32 + j) * 32 + i) * 128 + idx - 384];
            ein[idx] = v;
        }
        __syncthreads();

        float4 a = make_float4(0.f, 0.f, 0.f, 0.f);
        if (bit) {
            int cb = sl * 32;
#pragma unroll 8
            for (int c = 0; c < 32; ++c) {
                float xv = ein[cb + c];
                float4 w4 = *(const float4*)(ws + (cb + c) * 64 + og);
                a.x += xv * w4.x; a.y += xv * w4.y;
                a.z += xv * w4.z; a.w += xv * w4.w;
            }
        }
        *(float4*)(psum + sl * 64 + og) = a;
        __syncthreads();
        if (tx < 64) {
            int o = tx;
            float s = 0.f;
#pragma unroll
            for (int t = 0; t < 16; ++t) s += psum[t * 64 + o];
            s += (float)ab[5] * b_exp2[o] + (float)ab[6] * b_op2[o] + (float)ab[7] * b_red2[o];
            out[OUT2 + ((b * 32 + i) * 32 + j) * 64 + o] = g2 ? sigf(s) : 0.f;
        }
    }
}

// ---------------- o3: double-buffered mma.sync bf16-split GEMM ----------------
#define A_HI 0
#define A_LO 18432
#define B_HI 36864
#define B_LO 46080
#define BUF_STRIDE 55296
#define O3_SMEM (2 * BUF_STRIDE)

__device__ __forceinline__ int elem_off(int q, int b, int i, int j, int k) {
    switch (q) {
        case 0:  return (((b * 32 + i) * 1024) + j * 32 + k) * 64;
        case 1:  return (((b * 32 + i) * 1024) + k * 32 + j) * 64;
        case 2:  return (((b * 32 + j) * 1024) + i * 32 + k) * 64;
        case 3:  return (((b * 32 + k) * 1024) + i * 32 + j) * 64;
        case 4:  return (((b * 32 + j) * 1024) + k * 32 + i) * 64;
        case 5:  return (((b * 32 + k) * 1024) + j * 32 + i) * 64;
        case 6:  return ((b * 32 + i) * 32 + j) * 64;
        case 7:  return ((b * 32 + i) * 32 + k) * 64;
        case 8:  return ((b * 32 + j) * 32 + i) * 64;
        case 9:  return ((b * 32 + k) * 32 + i) * 64;
        case 10: return ((b * 32 + j) * 32 + k) * 64;
        default: return ((b * 32 + k) * 32 + j) * 64;
    }
}

__device__ __forceinline__ void o3_stage(char* smbuf, int q, int b, int i, int jbase, int tx) {
    const __nv_bfloat16* sh = (q < 6) ? d_x3hi : d_x2hi;
    const __nv_bfloat16* sl = (q < 6) ? d_x3lo : d_x2lo;
#pragma unroll
    for (int it = 0; it < 4; ++it) {
        int u = tx + (it << 8);
        int m = u >> 3, seg = u & 7;
        int off = elem_off(q, b, i, jbase + (m >> 5), m & 31);
        int so = m * 144 + seg * 16;
        cp16(smbuf + A_HI + so, (const char*)(sh + off) + seg * 16);
        cp16(smbuf + A_LO + so, (const char*)(sl + off) + seg * 16);
    }
    const char* wh = (const char*)(d_wBhi + q * 4096);
    const char* wl = (const char*)(d_wBlo + q * 4096);
#pragma unroll
    for (int it = 0; it < 2; ++it) {
        int u = tx + (it << 8);
        int o = u >> 3, seg = u & 7;
        cp16(smbuf + B_HI + o * 144 + seg * 16, wh + o * 128 + seg * 16);
        cp16(smbuf + B_LO + o * 144 + seg * 16, wl + o * 128 + seg * 16);
    }
}

__global__ void __launch_bounds__(256, 2)
k_o3(const float* __restrict__ b_exp3, const float* __restrict__ b_op3,
     const int* __restrict__ act, float* __restrict__ out) {
    extern __shared__ char sm[];
    int bid = blockIdx.x;
    int b = bid >> 8, i = (bid >> 3) & 31, jbase = (bid & 7) * 4;
    int tx = threadIdx.x, warp = tx >> 5, lane = tx & 31;

    int g3 = any_bits(act, 8, 10);
    int a8 = act[b * 10 + 8], a9 = act[b * 10 + 9];

    if (!g3 || (!a8 && !a9)) {
        float fill = g3 ? 0.5f : 0.0f;
        float4 f4 = make_float4(fill, fill, fill, fill);
        float4* ob = (float4*)(out + OUT3 + ((b * 32 + i) * 32 + jbase) * 2048);
        for (int f = tx; f < 2048; f += 256) ob[f] = f4;
        return;
    }

    int qs[12], nq = 0;
    if (a9) { for (int q = 0; q < 6; ++q) qs[nq++] = q; }
    if (a8) { for (int q = 6; q < 12; ++q) qs[nq++] = q; }

    unsigned smb = smem_u32(sm);
    int rbase = warp * 16;
    unsigned aoff = (unsigned)((rbase + ((lane >> 3) & 1) * 8 + (lane & 7)) * 144
                               + ((lane >> 4) & 1) * 16);
    unsigned boff = (unsigned)((((lane >> 4) & 1) * 8 + (lane & 7)) * 144
                               + ((lane >> 3) & 1) * 16);

    float acc[8][4];
#pragma unroll
    for (int nt = 0; nt < 8; ++nt)
#pragma unroll
        for (int r = 0; r < 4; ++r) acc[nt][r] = 0.f;

    o3_stage(sm, qs[0], b, i, jbase, tx);
    cp_commit();

    for (int s = 0; s < nq; ++s) {
        int cur = s & 1;
        if (s + 1 < nq) {
            o3_stage(sm + ((s + 1) & 1) * BUF_STRIDE, qs[s + 1], b, i, jbase, tx);
            cp_commit();
            cp_wait1();
        } else {
            cp_wait0();
        }
        __syncthreads();

        unsigned base = smb + cur * BUF_STRIDE;
#pragma unroll
        for (int ks = 0; ks < 4; ++ks) {
            unsigned Ah[4], Al[4];
            ldm4(Ah, base + A_HI + aoff + ks * 32);
            ldm4(Al, base + A_LO + aoff + ks * 32);
#pragma unroll
            for (int p = 0; p < 4; ++p) {
                unsigned Bh[4], Bl[4];
                ldm4(Bh, base + B_HI + boff + p * (16 * 144) + ks * 32);
                ldm4(Bl, base + B_LO + boff + p * (16 * 144) + ks * 32);
                mma_bf16(acc[2 * p],     Ah, Bh[0], Bh[1]);
                mma_bf16(acc[2 * p + 1], Ah, Bh[2], Bh[3]);
                mma_bf16(acc[2 * p],     Ah, Bl[0], Bl[1]);
                mma_bf16(acc[2 * p + 1], Ah, Bl[2], Bl[3]);
                mma_bf16(acc[2 * p],     Al, Bh[0], Bh[1]);
                mma_bf16(acc[2 * p + 1], Al, Bh[2], Bh[3]);
            }
        }
        __syncthreads();
    }

    int jj = warp >> 1;
    int kbase = (warp & 1) * 16;
    int r0 = lane >> 2;
    int ocol = 2 * (lane & 3);
    float* orow0 = out + OUT3 + (((b * 32 + i) * 32 + (jbase + jj)) * 32 + kbase + r0) * 64;
    float* orow1 = orow0 + 8 * 64;
#pragma unroll
    for (int nt = 0; nt < 8; ++nt) {
        int o = nt * 8 + ocol;
        float bb0 = (a9 ? b_op3[o] : 0.f) + (a8 ? b_exp3[o] : 0.f);
        float bb1 = (a9 ? b_op3[o + 1] : 0.f) + (a8 ? b_exp3[o + 1] : 0.f);
        float2 v0 = make_float2(sigf(acc[nt][0] + bb0), sigf(acc[nt][1] + bb1));
        float2 v1 = make_float2(sigf(acc[nt][2] + bb0), sigf(acc[nt][3] + bb1));
        *(float2*)(orow0 + o) = v0;
        *(float2*)(orow1 + o) = v1;
    }
}

// ---------------- launch ----------------
extern "C" void kernel_launch(void* const* d_in, const int* in_sizes, int n_in,
                              void* d_out, int out_size) {
    const float* x0 = (const float*)d_in[0];
    const float* x1 = (const float*)d_in[1];
    const float* x2 = (const float*)d_in[2];
    const float* x3 = (const float*)d_in[3];
    const float* w_op0 = (const float*)d_in[4];
    const float* b_op0 = (const float*)d_in[5];
    const float* w_red0 = (const float*)d_in[6];
    const float* b_red0 = (const float*)d_in[7];
    const float* w_exp1 = (const float*)d_in[8];
    const float* b_exp1 = (const float*)d_in[9];
    const float* w_op1 = (const float*)d_in[10];
    const float* b_op1 = (const float*)d_in[11];
    const float* w_red1 = (const float*)d_in[12];
    const float* b_red1 = (const float*)d_in[13];
    const float* w_exp2 = (const float*)d_in[14];
    const float* b_exp2 = (const float*)d_in[15];
    const float* w_op2 = (const float*)d_in[16];
    const float* b_op2 = (const float*)d_in[17];
    const float* w_red2 = (const float*)d_in[18];
    const float* b_red2 = (const float*)d_in[19];
    const float* w_exp3 = (const float*)d_in[20];
    const float* b_exp3 = (const float*)d_in[21];
    const float* w_op3 = (const float*)d_in[22];
    const float* b_op3 = (const float*)d_in[23];
    const int* act = (const int*)d_in[24];
    float* out = (float*)d_out;

    static cudaStream_t s1;
    static cudaEvent_t evA, evB, evC;
    static int init_done = 0;
    if (!init_done) {
        cudaFuncSetAttribute(k_o3, cudaFuncAttributeMaxDynamicSharedMemorySize, O3_SMEM);
        cudaFuncSetAttribute(k_o2, cudaFuncAttributeMaxDynamicSharedMemorySize, O2_SMEM);
        cudaStreamCreateWithFlags(&s1, cudaStreamNonBlocking);
        cudaEventCreateWithFlags(&evA, cudaEventDisableTiming);
        cudaEventCreateWithFlags(&evB, cudaEventDisableTiming);
        cudaEventCreateWithFlags(&evC, cudaEventDisableTiming);
        init_done = 1;
    }

    unsigned long long* x2hi;
    unsigned long long* x2lo;
    cudaGetSymbolAddress((void**)&x2hi, d_x2hi);
    cudaGetSymbolAddress((void**)&x2lo, d_x2lo);

    // fork side stream
    cudaEventRecord(evA, 0);
    cudaStreamWaitEvent(s1, evA, 0);

    // main chain: o3 dependencies
    k_prep3<<<192, 256>>>(w_exp3, w_op3);
    k_split<<<512, 256>>>((const float4*)x2, x2hi, x2lo, 131072);
    k_sr<<<8192, 256>>>((const float4*)x3);
    cudaEventRecord(evB, 0);  // r2 ready
    k_o3<<<2048, 256, O3_SMEM>>>(b_exp3, b_op3, act, out);

    // side chain: o0/o1/o2
    k_prep<<<(W_TOTAL + 255) / 256, 256, 0, s1>>>(w_op0, w_red0, w_exp1, w_op1, w_red1,
                                                  w_exp2, w_op2, w_red2);
    k_r0<<<8, 64, 0, s1>>>(x1);
    k_r1<<<256, 64, 0, s1>>>(x2);
    k_o0o1<<<264, 64, 0, s1>>>(x0, x1, b_op0, b_red0, b_exp1, b_op1, b_red1, act, out);
    cudaStreamWaitEvent(s1, evB, 0);
    k_o2<<<256, 256, O2_SMEM, s1>>>(x1, x2, b_exp2, b_op2, b_red2, act, out);
    cudaEventRecord(evC, s1);

    // join
    cudaStreamWaitEvent(0, evC, 0);
}

// round 11
// speedup vs baseline: 5.0592x; 1.1861x over previous
#include <cuda_runtime.h>
#include <cuda_fp16.h>

// LogicMachine: B=8, n=32, C=64, O=64
// Output layout (floats): o0[8,64] | o1[8,32,64] | o2[8,32,32,64] | o3[8,32,32,32,64]
#define OUT0 0
#define OUT1 512
#define OUT2 16896
#define OUT3 541184

#define W_OP0_T   0
#define W_RED0_T  4096
#define W_EXP1_T  12288
#define W_OP1_T   16384
#define W_RED1_T  20480
#define W_EXP2_T  28672
#define W_OP2_T   36864
#define W_RED2_T  45056
#define W_TOTAL   61440

__device__ __align__(16) float d_wt[W_TOTAL];
__device__ __align__(16) float d_r0[8 * 128];
__device__ __align__(16) float d_r1[8 * 32 * 128];
__device__ __align__(16) float d_r2[8 * 32 * 32 * 128];
// fp16 B images (scaled by 16): 12 chunks x [64 o][64 c]
__device__ __align__(16) __half d_wBh[12 * 4096];
__device__ __align__(16) __half d_wBl[12 * 4096];
// fp16 single images of x3 / x2
__device__ __align__(16) __half d_x3h[8 * 32 * 32 * 32 * 64];
__device__ __align__(16) __half d_x2h[8 * 32 * 32 * 64];

// ---------------- helpers ----------------
__device__ __forceinline__ float sigf(float s) { return 1.0f / (1.0f + __expf(-s)); }

__device__ __forceinline__ int any_bits(const int* act, int lo, int hi) {
    int g = 0;
    for (int b = 0; b < 8; ++b)
        for (int t = lo; t < hi; ++t) g |= act[b * 10 + t];
    return g;
}
__device__ __forceinline__ unsigned smem_u32(const void* p) {
    return (unsigned)__cvta_generic_to_shared(p);
}
__device__ __forceinline__ void cp16(void* dst_smem, const void* src) {
    unsigned sdst = smem_u32(dst_smem);
    asm volatile("cp.async.ca.shared.global [%0], [%1], 16;" :: "r"(sdst), "l"(src));
}
__device__ __forceinline__ void cp_commit() { asm volatile("cp.async.commit_group;"); }
__device__ __forceinline__ void cp_wait0() { asm volatile("cp.async.wait_group 0;"); }
__device__ __forceinline__ void cp_wait1() { asm volatile("cp.async.wait_group 1;"); }

__device__ __forceinline__ void ldm4(unsigned* r, unsigned addr) {
    asm volatile("ldmatrix.sync.aligned.m8n8.x4.shared.b16 {%0,%1,%2,%3}, [%4];"
                 : "=r"(r[0]), "=r"(r[1]), "=r"(r[2]), "=r"(r[3]) : "r"(addr));
}
__device__ __forceinline__ void mma_f16(float* c, const unsigned* a, unsigned b0, unsigned b1) {
    asm volatile(
        "mma.sync.aligned.m16n8k16.row.col.f32.f16.f16.f32 "
        "{%0,%1,%2,%3}, {%4,%5,%6,%7}, {%8,%9}, {%0,%1,%2,%3};"
        : "+f"(c[0]), "+f"(c[1]), "+f"(c[2]), "+f"(c[3])
        : "r"(a[0]), "r"(a[1]), "r"(a[2]), "r"(a[3]), "r"(b0), "r"(b1));
}

// pack float4 -> 4 fp16 in a u64
__device__ __forceinline__ unsigned long long h4(float4 v) {
    __half2 a = __floats2half2_rn(v.x, v.y);
    __half2 b = __floats2half2_rn(v.z, v.w);
    unsigned ua = *reinterpret_cast<unsigned*>(&a);
    unsigned ub = *reinterpret_cast<unsigned*>(&b);
    return (unsigned long long)ua | ((unsigned long long)ub << 32);
}

// ---------------- fp32 -> fp16 image (x2) ----------------
__global__ void k_split(const float4* __restrict__ src,
                        unsigned long long* __restrict__ dst, int n4) {
    int t = blockIdx.x * 256 + threadIdx.x;
    if (t >= n4) return;
    dst[t] = h4(__ldg(src + t));
}

// ---------------- fused x3->fp16 + r2 reduction: one block per (b,i,j) ----------------
__global__ void k_sr(const float4* __restrict__ x3) {
    __shared__ float xs[2048];
    __shared__ float red[2][4][64];
    int bid = blockIdx.x;
    int b = bid >> 10, i = (bid >> 5) & 31, j = bid & 31;
    int tx = threadIdx.x;
    unsigned long long* dst = reinterpret_cast<unsigned long long*>(d_x3h);
#pragma unroll
    for (int it = 0; it < 2; ++it) {
        int f4 = tx + it * 256;
        float4 v = __ldg(x3 + bid * 512 + f4);
        dst[bid * 512 + f4] = h4(v);
        *(float4*)(xs + f4 * 4) = v;
    }
    __syncthreads();
    int c = tx & 63, kg = tx >> 6;
    float mx = -3.4e38f, mn = 3.4e38f;
#pragma unroll
    for (int kk = 0; kk < 8; ++kk) {
        int k = kg * 8 + kk;
        if (k == i || k == j) continue;
        float v = xs[k * 64 + c];
        mx = fmaxf(mx, v);
        mn = fminf(mn, v);
    }
    red[0][kg][c] = mx;
    red[1][kg][c] = mn;
    __syncthreads();
    if (tx < 64) {
        float MX, MN;
        if (i == j) { MX = 0.f; MN = 1.f; }
        else {
            MX = fmaxf(fmaxf(red[0][0][tx], red[0][1][tx]), fmaxf(red[0][2][tx], red[0][3][tx]));
            MN = fminf(fminf(red[1][0][tx], red[1][1][tx]), fminf(red[1][2][tx], red[1][3][tx]));
        }
        d_r2[bid * 128 + 2 * tx] = MX;
        d_r2[bid * 128 + 2 * tx + 1] = MN;
    }
}

// ---------------- weight transpose (o0/o1/o2 weights) ----------------
__global__ void k_prep(const float* __restrict__ w_op0, const float* __restrict__ w_red0,
                       const float* __restrict__ w_exp1, const float* __restrict__ w_op1,
                       const float* __restrict__ w_red1, const float* __restrict__ w_exp2,
                       const float* __restrict__ w_op2, const float* __restrict__ w_red2) {
    int tid = blockIdx.x * 256 + threadIdx.x;
    if (tid >= W_TOTAL) return;
    const float* src;
    int off, IN;
    if (tid < 4096)        { src = w_op0;  off = tid;          IN = 64;  }
    else if (tid < 12288)  { src = w_red0; off = tid - 4096;   IN = 128; }
    else if (tid < 16384)  { src = w_exp1; off = tid - 12288;  IN = 64;  }
    else if (tid < 20480)  { src = w_op1;  off = tid - 16384;  IN = 64;  }
    else if (tid < 28672)  { src = w_red1; off = tid - 20480;  IN = 128; }
    else if (tid < 36864)  { src = w_exp2; off = tid - 28672;  IN = 128; }
    else if (tid < 45056)  { src = w_op2;  off = tid - 36864;  IN = 128; }
    else                   { src = w_red2; off = tid - 45056;  IN = 256; }
    int in = off >> 6, o = off & 63;
    d_wt[tid] = src[o * IN + in];
}

// ---------------- o3 weight images: fp16 hi/lo scaled by 16, plain [q][o][c] ----------------
__global__ void k_prep3(const float* __restrict__ w_exp3, const float* __restrict__ w_op3) {
    int tid = blockIdx.x * 256 + threadIdx.x;
    if (tid >= 12 * 4096) return;
    int q = tid >> 12, idx = tid & 4095;
    int o = idx >> 6, c = idx & 63;
    const float* w = (q < 6) ? w_op3 : w_exp3;
    float v = 16.0f * w[o * 384 + (q % 6) * 64 + c];
    __half h = __float2half_rn(v);
    __half l = __float2half_rn(v - __half2float(h));
    d_wBh[tid] = h;
    d_wBl[tid] = l;
}

// ---------------- small reductions ----------------
__global__ void k_r0(const float* __restrict__ x1) {
    int b = blockIdx.x, c = threadIdx.x;
    float mx = -3.4e38f, mn = 3.4e38f;
    for (int i = 0; i < 32; ++i) {
        float v = x1[(b * 32 + i) * 64 + c];
        mx = fmaxf(mx, v);
        mn = fminf(mn, v);
    }
    d_r0[b * 128 + 2 * c] = mx;
    d_r0[b * 128 + 2 * c + 1] = mn;
}

__global__ void k_r1(const float* __restrict__ x2) {
    int b = blockIdx.x >> 5, i = blockIdx.x & 31, c = threadIdx.x;
    float mx = -3.4e38f, mn = 3.4e38f;
    for (int j = 0; j < 32; ++j) {
        if (j == i) continue;
        float v = x2[((b * 32 + i) * 32 + j) * 64 + c];
        mx = fmaxf(mx, v);
        mn = fminf(mn, v);
    }
    d_r1[(b * 32 + i) * 128 + 2 * c] = mx;
    d_r1[(b * 32 + i) * 128 + 2 * c + 1] = mn;
}

// ---------------- o0 + o1 ----------------
__global__ void k_o0o1(const float* __restrict__ x0, const float* __restrict__ x1,
                       const float* __restrict__ b_op0, const float* __restrict__ b_red0,
                       const float* __restrict__ b_exp1, const float* __restrict__ b_op1,
                       const float* __restrict__ b_red1,
                       const int* __restrict__ act, float* __restrict__ out) {
    int bid = blockIdx.x, o = threadIdx.x;
    if (bid < 8) {
        int b = bid;
        const int* ab = act + b * 10;
        int g0 = any_bits(act, 0, 2);
        float s0 = 0.f;
        if (ab[0]) {
            float d = 0.f;
            for (int c = 0; c < 64; ++c) d += x0[b * 64 + c] * d_wt[W_OP0_T + c * 64 + o];
            s0 += d + b_op0[o];
        }
        if (ab[1]) {
            float d = 0.f;
            for (int c = 0; c < 128; ++c) d += d_r0[b * 128 + c] * d_wt[W_RED0_T + c * 64 + o];
            s0 += d + b_red0[o];
        }
        out[OUT0 + b * 64 + o] = g0 ? sigf(s0) : 0.f;
    } else {
        int u = bid - 8, b = u >> 5, i = u & 31;
        const int* ab = act + b * 10;
        int g1 = any_bits(act, 2, 5);
        float s1 = 0.f;
        if (ab[2]) {
            float d = 0.f;
            for (int c = 0; c < 64; ++c) d += x0[b * 64 + c] * d_wt[W_EXP1_T + c * 64 + o];
            s1 += d + b_exp1[o];
        }
        if (ab[3]) {
            float d = 0.f;
            for (int c = 0; c < 64; ++c) d += x1[(b * 32 + i) * 64 + c] * d_wt[W_OP1_T + c * 64 + o];
            s1 += d + b_op1[o];
        }
        if (ab[4]) {
            float d = 0.f;
            for (int c = 0; c < 128; ++c) d += d_r1[(b * 32 + i) * 128 + c] * d_wt[W_RED1_T + c * 64 + o];
            s1 += d + b_red1[o];
        }
        out[OUT1 + (b * 32 + i) * 64 + o] = g1 ? sigf(s1) : 0.f;
    }
}

// ---------------- o2: one block per (b,i), weights staged in smem once ----------------
#define O2_SMEM ((32768 + 512 + 1024) * 4)
__global__ void __launch_bounds__(256, 1)
k_o2(const float* __restrict__ x1, const float* __restrict__ x2,
     const float* __restrict__ b_exp2, const float* __restrict__ b_op2,
     const float* __restrict__ b_red2,
     const int* __restrict__ act, float* __restrict__ out) {
    extern __shared__ float s2[];
    float* ws = s2;
    float* ein = s2 + 32768;
    float* psum = s2 + 33280;
    int b = blockIdx.x >> 5, i = blockIdx.x & 31;
    int tx = threadIdx.x;
    const int* ab = act + b * 10;
    int g2 = any_bits(act, 5, 8);

    for (int u = tx; u < 8192; u += 256) {
        int row = u >> 4, sg = u & 15;
        const float* src;
        if (row < 128)      src = d_wt + W_EXP2_T + row * 64;
        else if (row < 256) src = d_wt + W_OP2_T + (row - 128) * 64;
        else                src = d_wt + W_RED2_T + (row - 256) * 64;
        cp16(ws + row * 64 + sg * 4, src + sg * 4);
    }
    cp_commit();

    int og = (tx & 15) * 4, sl = tx >> 4;
    int bit = ab[5 + (sl >= 4) + (sl >= 8)];
    cp_wait0();
    __syncthreads();

    for (int j = 0; j < 32; ++j) {
        __syncthreads();
        for (int idx = tx; idx < 512; idx += 256) {
            float v;
            if (idx < 64)       v = x1[(b * 32 + i) * 64 + idx];
            else if (idx < 128) v = x1[(b * 32 + j) * 64 + idx - 64];
            else if (idx < 192) v = x2[((b * 32 + i) * 32 + j) * 64 + idx - 128];
            else if (idx < 256) v = x2[((b * 32 + j) * 32 + i) * 64 + idx - 192];
            else if (idx < 384) v = d_r2[((b * 32 + i) * 32 + j) * 128 + idx - 256];
            else                v = d_r2[((b * 32 + j) * 32 + i) * 128 + idx - 384];
            ein[idx] = v;
        }
        __syncthreads();

        float4 a = make_float4(0.f, 0.f, 0.f, 0.f);
        if (bit) {
            int cb = sl * 32;
#pragma unroll 8
            for (int c = 0; c < 32; ++c) {
                float xv = ein[cb + c];
                float4 w4 = *(const float4*)(ws + (cb + c) * 64 + og);
                a.x += xv * w4.x; a.y += xv * w4.y;
                a.z += xv * w4.z; a.w += xv * w4.w;
            }
        }
        *(float4*)(psum + sl * 64 + og) = a;
        __syncthreads();
        if (tx < 64) {
            int o = tx;
            float s = 0.f;
#pragma unroll
            for (int t = 0; t < 16; ++t) s += psum[t * 64 + o];
            s += (float)ab[5] * b_exp2[o] + (float)ab[6] * b_op2[o] + (float)ab[7] * b_red2[o];
            out[OUT2 + ((b * 32 + i) * 32 + j) * 64 + o] = g2 ? sigf(s) : 0.f;
        }
    }
}

// ---------------- o3: fp16 2-pass mma.sync GEMM, 64x32 warp tiles ----------------
// A single fp16 image; B split hi/lo fp16 scaled by 16; D = (A*Bh + A*Bl)/16.
// CTA 128 threads = 4 warps, each owning 64 rows x 32 cols of D[128,64].
#define A_OFF  0
#define BH_OFF 18432
#define BL_OFF 27648
#define BUF_STRIDE 36864
#define O3_SMEM (2 * BUF_STRIDE)

__device__ __forceinline__ int elem_off(int q, int b, int i, int j, int k) {
    switch (q) {
        case 0:  return (((b * 32 + i) * 1024) + j * 32 + k) * 64;
        case 1:  return (((b * 32 + i) * 1024) + k * 32 + j) * 64;
        case 2:  return (((b * 32 + j) * 1024) + i * 32 + k) * 64;
        case 3:  return (((b * 32 + k) * 1024) + i * 32 + j) * 64;
        case 4:  return (((b * 32 + j) * 1024) + k * 32 + i) * 64;
        case 5:  return (((b * 32 + k) * 1024) + j * 32 + i) * 64;
        case 6:  return ((b * 32 + i) * 32 + j) * 64;
        case 7:  return ((b * 32 + i) * 32 + k) * 64;
        case 8:  return ((b * 32 + j) * 32 + i) * 64;
        case 9:  return ((b * 32 + k) * 32 + i) * 64;
        case 10: return ((b * 32 + j) * 32 + k) * 64;
        default: return ((b * 32 + k) * 32 + j) * 64;
    }
}

__device__ __forceinline__ void o3_stage(char* smbuf, int q, int b, int i, int jbase, int tx) {
    const __half* src = (q < 6) ? d_x3h : d_x2h;
    // A: 128 rows x 128B (64 fp16), pitch 144B
#pragma unroll
    for (int it = 0; it < 8; ++it) {
        int u = tx + (it << 7);
        int m = u >> 3, seg = u & 7;
        int off = elem_off(q, b, i, jbase + (m >> 5), m & 31);
        cp16(smbuf + A_OFF + m * 144 + seg * 16, (const char*)(src + off) + seg * 16);
    }
    // B: 64 rows x 128B per half, pitch 144B
    const char* wh = (const char*)(d_wBh + q * 4096);
    const char* wl = (const char*)(d_wBl + q * 4096);
#pragma unroll
    for (int it = 0; it < 4; ++it) {
        int u = tx + (it << 7);
        int o = u >> 3, seg = u & 7;
        cp16(smbuf + BH_OFF + o * 144 + seg * 16, wh + o * 128 + seg * 16);
        cp16(smbuf + BL_OFF + o * 144 + seg * 16, wl + o * 128 + seg * 16);
    }
}

__global__ void __launch_bounds__(128, 3)
k_o3(const float* __restrict__ b_exp3, const float* __restrict__ b_op3,
     const int* __restrict__ act, float* __restrict__ out) {
    extern __shared__ char sm[];
    int bid = blockIdx.x;
    int b = bid >> 8, i = (bid >> 3) & 31, jbase = (bid & 7) * 4;
    int tx = threadIdx.x, warp = tx >> 5, lane = tx & 31;
    int rowg = warp >> 1, colg = warp & 1;

    int g3 = any_bits(act, 8, 10);
    int a8 = act[b * 10 + 8], a9 = act[b * 10 + 9];

    if (!g3 || (!a8 && !a9)) {
        float fill = g3 ? 0.5f : 0.0f;
        float4 f4 = make_float4(fill, fill, fill, fill);
        float4* ob = (float4*)(out + OUT3 + ((b * 32 + i) * 32 + jbase) * 2048);
        for (int f = tx; f < 2048; f += 128) ob[f] = f4;
        return;
    }

    int qs[12], nq = 0;
    if (a9) { for (int q = 0; q < 6; ++q) qs[nq++] = q; }
    if (a8) { for (int q = 6; q < 12; ++q) qs[nq++] = q; }

    unsigned smb = smem_u32(sm);
    unsigned aoff = (unsigned)((rowg * 64 + ((lane >> 3) & 1) * 8 + (lane & 7)) * 144
                               + ((lane >> 4) & 1) * 16);
    unsigned bbase = (unsigned)((((lane >> 4) & 1) * 8 + (lane & 7)) * 144
                                + ((lane >> 3) & 1) * 16);
    unsigned boff0 = (unsigned)(colg * 2 * 2304) + bbase;
    unsigned boff1 = boff0 + 2304;

    float acc[16][4];
#pragma unroll
    for (int t = 0; t < 16; ++t)
#pragma unroll
        for (int r = 0; r < 4; ++r) acc[t][r] = 0.f;

    o3_stage(sm, qs[0], b, i, jbase, tx);
    cp_commit();

    for (int s = 0; s < nq; ++s) {
        int cur = s & 1;
        if (s + 1 < nq) {
            o3_stage(sm + ((s + 1) & 1) * BUF_STRIDE, qs[s + 1], b, i, jbase, tx);
            cp_commit();
            cp_wait1();
        } else {
            cp_wait0();
        }
        __syncthreads();

        unsigned base = smb + cur * BUF_STRIDE;
#pragma unroll
        for (int ks = 0; ks < 4; ++ks) {
            unsigned Bh0[4], Bh1[4], Bl0[4], Bl1[4];
            ldm4(Bh0, base + BH_OFF + boff0 + ks * 32);
            ldm4(Bh1, base + BH_OFF + boff1 + ks * 32);
            ldm4(Bl0, base + BL_OFF + boff0 + ks * 32);
            ldm4(Bl1, base + BL_OFF + boff1 + ks * 32);
#pragma unroll
            for (int rh = 0; rh < 4; ++rh) {
                unsigned A[4];
                ldm4(A, base + A_OFF + aoff + rh * 2304 + ks * 32);
                mma_f16(acc[rh * 4 + 0], A, Bh0[0], Bh0[1]);
                mma_f16(acc[rh * 4 + 1], A, Bh0[2], Bh0[3]);
                mma_f16(acc[rh * 4 + 2], A, Bh1[0], Bh1[1]);
                mma_f16(acc[rh * 4 + 3], A, Bh1[2], Bh1[3]);
                mma_f16(acc[rh * 4 + 0], A, Bl0[0], Bl0[1]);
                mma_f16(acc[rh * 4 + 1], A, Bl0[2], Bl0[3]);
                mma_f16(acc[rh * 4 + 2], A, Bl1[0], Bl1[1]);
                mma_f16(acc[rh * 4 + 3], A, Bl1[2], Bl1[3]);
            }
        }
        __syncthreads();
    }

    // epilogue: warp tile 64 rows x 32 cols; unscale by 1/16
#pragma unroll
    for (int rh = 0; rh < 4; ++rh) {
        int m0 = rowg * 64 + rh * 16 + (lane >> 2);
        int jj = m0 >> 5;
        int k0 = m0 & 31;
        float* prow0 = out + OUT3 + (((b * 32 + i) * 32 + (jbase + jj)) * 32 + k0) * 64;
        float* prow1 = prow0 + 8 * 64;
#pragma unroll
        for (int p = 0; p < 4; ++p) {
            int o = colg * 32 + p * 8 + 2 * (lane & 3);
            float bb0 = (a9 ? __ldg(b_op3 + o) : 0.f) + (a8 ? __ldg(b_exp3 + o) : 0.f);
            float bb1 = (a9 ? __ldg(b_op3 + o + 1) : 0.f) + (a8 ? __ldg(b_exp3 + o + 1) : 0.f);
            const float* a4 = acc[rh * 4 + p];
            float2 v0 = make_float2(sigf(a4[0] * 0.0625f + bb0), sigf(a4[1] * 0.0625f + bb1));
            float2 v1 = make_float2(sigf(a4[2] * 0.0625f + bb0), sigf(a4[3] * 0.0625f + bb1));
            *(float2*)(prow0 + o) = v0;
            *(float2*)(prow1 + o) = v1;
        }
    }
}

// ---------------- launch ----------------
extern "C" void kernel_launch(void* const* d_in, const int* in_sizes, int n_in,
                              void* d_out, int out_size) {
    const float* x0 = (const float*)d_in[0];
    const float* x1 = (const float*)d_in[1];
    const float* x2 = (const float*)d_in[2];
    const float* x3 = (const float*)d_in[3];
    const float* w_op0 = (const float*)d_in[4];
    const float* b_op0 = (const float*)d_in[5];
    const float* w_red0 = (const float*)d_in[6];
    const float* b_red0 = (const float*)d_in[7];
    const float* w_exp1 = (const float*)d_in[8];
    const float* b_exp1 = (const float*)d_in[9];
    const float* w_op1 = (const float*)d_in[10];
    const float* b_op1 = (const float*)d_in[11];
    const float* w_red1 = (const float*)d_in[12];
    const float* b_red1 = (const float*)d_in[13];
    const float* w_exp2 = (const float*)d_in[14];
    const float* b_exp2 = (const float*)d_in[15];
    const float* w_op2 = (const float*)d_in[16];
    const float* b_op2 = (const float*)d_in[17];
    const float* w_red2 = (const float*)d_in[18];
    const float* b_red2 = (const float*)d_in[19];
    const float* w_exp3 = (const float*)d_in[20];
    const float* b_exp3 = (const float*)d_in[21];
    const float* w_op3 = (const float*)d_in[22];
    const float* b_op3 = (const float*)d_in[23];
    const int* act = (const int*)d_in[24];
    float* out = (float*)d_out;

    static cudaStream_t s1;
    static cudaEvent_t evA, evB, evC;
    static int init_done = 0;
    if (!init_done) {
        cudaFuncSetAttribute(k_o3, cudaFuncAttributeMaxDynamicSharedMemorySize, O3_SMEM);
        cudaFuncSetAttribute(k_o2, cudaFuncAttributeMaxDynamicSharedMemorySize, O2_SMEM);
        cudaStreamCreateWithFlags(&s1, cudaStreamNonBlocking);
        cudaEventCreateWithFlags(&evA, cudaEventDisableTiming);
        cudaEventCreateWithFlags(&evB, cudaEventDisableTiming);
        cudaEventCreateWithFlags(&evC, cudaEventDisableTiming);
        init_done = 1;
    }

    unsigned long long* x2h;
    cudaGetSymbolAddress((void**)&x2h, d_x2h);

    // fork side stream
    cudaEventRecord(evA, 0);
    cudaStreamWaitEvent(s1, evA, 0);

    // main chain: o3 dependencies
    k_prep3<<<192, 256>>>(w_exp3, w_op3);
    k_split<<<512, 256>>>((const float4*)x2, x2h, 131072);   // FIX: full x2 (131072 float4)
    k_sr<<<8192, 256>>>((const float4*)x3);
    cudaEventRecord(evB, 0);  // r2 + x3h ready
    k_o3<<<2048, 128, O3_SMEM>>>(b_exp3, b_op3, act, out);

    // side chain: o0/o1/o2
    k_prep<<<(W_TOTAL + 255) / 256, 256, 0, s1>>>(w_op0, w_red0, w_exp1, w_op1, w_red1,
                                                  w_exp2, w_op2, w_red2);
    k_r0<<<8, 64, 0, s1>>>(x1);
    k_r1<<<256, 64, 0, s1>>>(x2);
    k_o0o1<<<264, 64, 0, s1>>>(x0, x1, b_op0, b_red0, b_exp1, b_op1, b_red1, act, out);
    cudaStreamWaitEvent(s1, evB, 0);
    k_o2<<<256, 256, O2_SMEM, s1>>>(x1, x2, b_exp2, b_op2, b_red2, act, out);
    cudaEventRecord(evC, s1);

    // join
    cudaStreamWaitEvent(0, evC, 0);
}

// round 12
// speedup vs baseline: 6.5557x; 1.2958x over previous
#include <cuda_runtime.h>
#include <cuda_fp16.h>

// LogicMachine: B=8, n=32, C=64, O=64
// Output layout (floats): o0[8,64] | o1[8,32,64] | o2[8,32,32,64] | o3[8,32,32,32,64]
#define OUT0 0
#define OUT1 512
#define OUT2 16896
#define OUT3 541184

#define W_OP0_T   0
#define W_RED0_T  4096
#define W_EXP1_T  12288
#define W_OP1_T   16384
#define W_RED1_T  20480
#define W_EXP2_T  28672
#define W_OP2_T   36864
#define W_RED2_T  45056
#define W_TOTAL   61440

__device__ __align__(16) float d_wt[W_TOTAL];
__device__ __align__(16) float d_r0[8 * 128];
__device__ __align__(16) float d_r1[8 * 32 * 128];
__device__ __align__(16) float d_r2[8 * 32 * 32 * 128];
// fp16 B image: 12 chunks x [64 o][64 c]
__device__ __align__(16) __half d_wB[12 * 4096];
// fp16 images of x3 / x2
__device__ __align__(16) __half d_x3h[8 * 32 * 32 * 32 * 64];
__device__ __align__(16) __half d_x2h[8 * 32 * 32 * 64];

// ---------------- helpers ----------------
__device__ __forceinline__ float sigf(float s) { return 1.0f / (1.0f + __expf(-s)); }

__device__ __forceinline__ int any_bits(const int* act, int lo, int hi) {
    int g = 0;
    for (int b = 0; b < 8; ++b)
        for (int t = lo; t < hi; ++t) g |= act[b * 10 + t];
    return g;
}
__device__ __forceinline__ unsigned smem_u32(const void* p) {
    return (unsigned)__cvta_generic_to_shared(p);
}
__device__ __forceinline__ void cp16(void* dst_smem, const void* src) {
    unsigned sdst = smem_u32(dst_smem);
    asm volatile("cp.async.ca.shared.global [%0], [%1], 16;" :: "r"(sdst), "l"(src));
}
__device__ __forceinline__ void cp_commit() { asm volatile("cp.async.commit_group;"); }
__device__ __forceinline__ void cp_wait0() { asm volatile("cp.async.wait_group 0;"); }
__device__ __forceinline__ void cp_wait1() { asm volatile("cp.async.wait_group 1;"); }

__device__ __forceinline__ void ldm4(unsigned* r, unsigned addr) {
    asm volatile("ldmatrix.sync.aligned.m8n8.x4.shared.b16 {%0,%1,%2,%3}, [%4];"
                 : "=r"(r[0]), "=r"(r[1]), "=r"(r[2]), "=r"(r[3]) : "r"(addr));
}
__device__ __forceinline__ void mma_f16(float* c, const unsigned* a, unsigned b0, unsigned b1) {
    asm volatile(
        "mma.sync.aligned.m16n8k16.row.col.f32.f16.f16.f32 "
        "{%0,%1,%2,%3}, {%4,%5,%6,%7}, {%8,%9}, {%0,%1,%2,%3};"
        : "+f"(c[0]), "+f"(c[1]), "+f"(c[2]), "+f"(c[3])
        : "r"(a[0]), "r"(a[1]), "r"(a[2]), "r"(a[3]), "r"(b0), "r"(b1));
}

// pack float4 -> 4 fp16 in a u64
__device__ __forceinline__ unsigned long long h4(float4 v) {
    __half2 a = __floats2half2_rn(v.x, v.y);
    __half2 b = __floats2half2_rn(v.z, v.w);
    unsigned ua = *reinterpret_cast<unsigned*>(&a);
    unsigned ub = *reinterpret_cast<unsigned*>(&b);
    return (unsigned long long)ua | ((unsigned long long)ub << 32);
}

// ---------------- fp32 -> fp16 image (x2) ----------------
__global__ void k_split(const float4* __restrict__ src,
                        unsigned long long* __restrict__ dst, int n4) {
    int t = blockIdx.x * 256 + threadIdx.x;
    if (t >= n4) return;
    dst[t] = h4(__ldg(src + t));
}

// ---------------- fused x3->fp16 + r2 reduction: one block per (b,i,j) ----------------
__global__ void k_sr(const float4* __restrict__ x3) {
    __shared__ float xs[2048];
    __shared__ float red[2][4][64];
    int bid = blockIdx.x;
    int b = bid >> 10, i = (bid >> 5) & 31, j = bid & 31;
    int tx = threadIdx.x;
    unsigned long long* dst = reinterpret_cast<unsigned long long*>(d_x3h);
#pragma unroll
    for (int it = 0; it < 2; ++it) {
        int f4 = tx + it * 256;
        float4 v = __ldg(x3 + bid * 512 + f4);
        dst[bid * 512 + f4] = h4(v);
        *(float4*)(xs + f4 * 4) = v;
    }
    __syncthreads();
    int c = tx & 63, kg = tx >> 6;
    float mx = -3.4e38f, mn = 3.4e38f;
#pragma unroll
    for (int kk = 0; kk < 8; ++kk) {
        int k = kg * 8 + kk;
        if (k == i || k == j) continue;
        float v = xs[k * 64 + c];
        mx = fmaxf(mx, v);
        mn = fminf(mn, v);
    }
    red[0][kg][c] = mx;
    red[1][kg][c] = mn;
    __syncthreads();
    if (tx < 64) {
        float MX, MN;
        if (i == j) { MX = 0.f; MN = 1.f; }
        else {
            MX = fmaxf(fmaxf(red[0][0][tx], red[0][1][tx]), fmaxf(red[0][2][tx], red[0][3][tx]));
            MN = fminf(fminf(red[1][0][tx], red[1][1][tx]), fminf(red[1][2][tx], red[1][3][tx]));
        }
        d_r2[bid * 128 + 2 * tx] = MX;
        d_r2[bid * 128 + 2 * tx + 1] = MN;
    }
}

// ---------------- weight transpose (o0/o1/o2 weights) ----------------
__global__ void k_prep(const float* __restrict__ w_op0, const float* __restrict__ w_red0,
                       const float* __restrict__ w_exp1, const float* __restrict__ w_op1,
                       const float* __restrict__ w_red1, const float* __restrict__ w_exp2,
                       const float* __restrict__ w_op2, const float* __restrict__ w_red2) {
    int tid = blockIdx.x * 256 + threadIdx.x;
    if (tid >= W_TOTAL) return;
    const float* src;
    int off, IN;
    if (tid < 4096)        { src = w_op0;  off = tid;          IN = 64;  }
    else if (tid < 12288)  { src = w_red0; off = tid - 4096;   IN = 128; }
    else if (tid < 16384)  { src = w_exp1; off = tid - 12288;  IN = 64;  }
    else if (tid < 20480)  { src = w_op1;  off = tid - 16384;  IN = 64;  }
    else if (tid < 28672)  { src = w_red1; off = tid - 20480;  IN = 128; }
    else if (tid < 36864)  { src = w_exp2; off = tid - 28672;  IN = 128; }
    else if (tid < 45056)  { src = w_op2;  off = tid - 36864;  IN = 128; }
    else                   { src = w_red2; off = tid - 45056;  IN = 256; }
    int in = off >> 6, o = off & 63;
    d_wt[tid] = src[o * IN + in];
}

// ---------------- o3 weight image: fp16, plain [q][o][c] ----------------
__global__ void k_prep3(const float* __restrict__ w_exp3, const float* __restrict__ w_op3) {
    int tid = blockIdx.x * 256 + threadIdx.x;
    if (tid >= 12 * 4096) return;
    int q = tid >> 12, idx = tid & 4095;
    int o = idx >> 6, c = idx & 63;
    const float* w = (q < 6) ? w_op3 : w_exp3;
    d_wB[tid] = __float2half_rn(w[o * 384 + (q % 6) * 64 + c]);
}

// ---------------- small reductions ----------------
__global__ void k_r0(const float* __restrict__ x1) {
    int b = blockIdx.x, c = threadIdx.x;
    float mx = -3.4e38f, mn = 3.4e38f;
    for (int i = 0; i < 32; ++i) {
        float v = x1[(b * 32 + i) * 64 + c];
        mx = fmaxf(mx, v);
        mn = fminf(mn, v);
    }
    d_r0[b * 128 + 2 * c] = mx;
    d_r0[b * 128 + 2 * c + 1] = mn;
}

__global__ void k_r1(const float* __restrict__ x2) {
    int b = blockIdx.x >> 5, i = blockIdx.x & 31, c = threadIdx.x;
    float mx = -3.4e38f, mn = 3.4e38f;
    for (int j = 0; j < 32; ++j) {
        if (j == i) continue;
        float v = x2[((b * 32 + i) * 32 + j) * 64 + c];
        mx = fmaxf(mx, v);
        mn = fminf(mn, v);
    }
    d_r1[(b * 32 + i) * 128 + 2 * c] = mx;
    d_r1[(b * 32 + i) * 128 + 2 * c + 1] = mn;
}

// ---------------- o0 + o1 ----------------
__global__ void k_o0o1(const float* __restrict__ x0, const float* __restrict__ x1,
                       const float* __restrict__ b_op0, const float* __restrict__ b_red0,
                       const float* __restrict__ b_exp1, const float* __restrict__ b_op1,
                       const float* __restrict__ b_red1,
                       const int* __restrict__ act, float* __restrict__ out) {
    int bid = blockIdx.x, o = threadIdx.x;
    if (bid < 8) {
        int b = bid;
        const int* ab = act + b * 10;
        int g0 = any_bits(act, 0, 2);
        float s0 = 0.f;
        if (ab[0]) {
            float d = 0.f;
            for (int c = 0; c < 64; ++c) d += x0[b * 64 + c] * d_wt[W_OP0_T + c * 64 + o];
            s0 += d + b_op0[o];
        }
        if (ab[1]) {
            float d = 0.f;
            for (int c = 0; c < 128; ++c) d += d_r0[b * 128 + c] * d_wt[W_RED0_T + c * 64 + o];
            s0 += d + b_red0[o];
        }
        out[OUT0 + b * 64 + o] = g0 ? sigf(s0) : 0.f;
    } else {
        int u = bid - 8, b = u >> 5, i = u & 31;
        const int* ab = act + b * 10;
        int g1 = any_bits(act, 2, 5);
        float s1 = 0.f;
        if (ab[2]) {
            float d = 0.f;
            for (int c = 0; c < 64; ++c) d += x0[b * 64 + c] * d_wt[W_EXP1_T + c * 64 + o];
            s1 += d + b_exp1[o];
        }
        if (ab[3]) {
            float d = 0.f;
            for (int c = 0; c < 64; ++c) d += x1[(b * 32 + i) * 64 + c] * d_wt[W_OP1_T + c * 64 + o];
            s1 += d + b_op1[o];
        }
        if (ab[4]) {
            float d = 0.f;
            for (int c = 0; c < 128; ++c) d += d_r1[(b * 32 + i) * 128 + c] * d_wt[W_RED1_T + c * 64 + o];
            s1 += d + b_red1[o];
        }
        out[OUT1 + (b * 32 + i) * 64 + o] = g1 ? sigf(s1) : 0.f;
    }
}

// ---------------- o2: one block per (b,i), weights staged in smem once ----------------
#define O2_SMEM ((32768 + 512 + 1024) * 4)
__global__ void __launch_bounds__(256, 1)
k_o2(const float* __restrict__ x1, const float* __restrict__ x2,
     const float* __restrict__ b_exp2, const float* __restrict__ b_op2,
     const float* __restrict__ b_red2,
     const int* __restrict__ act, float* __restrict__ out) {
    extern __shared__ float s2[];
    float* ws = s2;
    float* ein = s2 + 32768;
    float* psum = s2 + 33280;
    int b = blockIdx.x >> 5, i = blockIdx.x & 31;
    int tx = threadIdx.x;
    const int* ab = act + b * 10;
    int g2 = any_bits(act, 5, 8);

    for (int u = tx; u < 8192; u += 256) {
        int row = u >> 4, sg = u & 15;
        const float* src;
        if (row < 128)      src = d_wt + W_EXP2_T + row * 64;
        else if (row < 256) src = d_wt + W_OP2_T + (row - 128) * 64;
        else                src = d_wt + W_RED2_T + (row - 256) * 64;
        cp16(ws + row * 64 + sg * 4, src + sg * 4);
    }
    cp_commit();

    int og = (tx & 15) * 4, sl = tx >> 4;
    int bit = ab[5 + (sl >= 4) + (sl >= 8)];
    cp_wait0();
    __syncthreads();

    for (int j = 0; j < 32; ++j) {
        __syncthreads();
        for (int idx = tx; idx < 512; idx += 256) {
            float v;
            if (idx < 64)       v = x1[(b * 32 + i) * 64 + idx];
            else if (idx < 128) v = x1[(b * 32 + j) * 64 + idx - 64];
            else if (idx < 192) v = x2[((b * 32 + i) * 32 + j) * 64 + idx - 128];
            else if (idx < 256) v = x2[((b * 32 + j) * 32 + i) * 64 + idx - 192];
            else if (idx < 384) v = d_r2[((b * 32 + i) * 32 + j) * 128 + idx - 256];
            else                v = d_r2[((b * 32 + j) * 32 + i) * 128 + idx - 384];
            ein[idx] = v;
        }
        __syncthreads();

        float4 a = make_float4(0.f, 0.f, 0.f, 0.f);
        if (bit) {
            int cb = sl * 32;
#pragma unroll 8
            for (int c = 0; c < 32; ++c) {
                float xv = ein[cb + c];
                float4 w4 = *(const float4*)(ws + (cb + c) * 64 + og);
                a.x += xv * w4.x; a.y += xv * w4.y;
                a.z += xv * w4.z; a.w += xv * w4.w;
            }
        }
        *(float4*)(psum + sl * 64 + og) = a;
        __syncthreads();
        if (tx < 64) {
            int o = tx;
            float s = 0.f;
#pragma unroll
            for (int t = 0; t < 16; ++t) s += psum[t * 64 + o];
            s += (float)ab[5] * b_exp2[o] + (float)ab[6] * b_op2[o] + (float)ab[7] * b_red2[o];
            out[OUT2 + ((b * 32 + i) * 32 + j) * 64 + o] = g2 ? sigf(s) : 0.f;
        }
    }
}

// ---------------- o3: fp16 single-pass mma.sync GEMM, 64x32 warp tiles ----------------
// A fp16 image; B fp16 image; fp32 accumulate. CTA 128 thr = 4 warps,
// each owning 64 rows x 32 cols of D[128,64]. Double-buffered chunks.
#define A_OFF  0
#define B_OFF  18432
#define BUF_STRIDE 27648
#define O3_SMEM (2 * BUF_STRIDE)

__device__ __forceinline__ int elem_off(int q, int b, int i, int j, int k) {
    switch (q) {
        case 0:  return (((b * 32 + i) * 1024) + j * 32 + k) * 64;
        case 1:  return (((b * 32 + i) * 1024) + k * 32 + j) * 64;
        case 2:  return (((b * 32 + j) * 1024) + i * 32 + k) * 64;
        case 3:  return (((b * 32 + k) * 1024) + i * 32 + j) * 64;
        case 4:  return (((b * 32 + j) * 1024) + k * 32 + i) * 64;
        case 5:  return (((b * 32 + k) * 1024) + j * 32 + i) * 64;
        case 6:  return ((b * 32 + i) * 32 + j) * 64;
        case 7:  return ((b * 32 + i) * 32 + k) * 64;
        case 8:  return ((b * 32 + j) * 32 + i) * 64;
        case 9:  return ((b * 32 + k) * 32 + i) * 64;
        case 10: return ((b * 32 + j) * 32 + k) * 64;
        default: return ((b * 32 + k) * 32 + j) * 64;
    }
}

__device__ __forceinline__ void o3_stage(char* smbuf, int q, int b, int i, int jbase, int tx) {
    const __half* src = (q < 6) ? d_x3h : d_x2h;
    // A: 128 rows x 128B (64 fp16), pitch 144B
#pragma unroll
    for (int it = 0; it < 8; ++it) {
        int u = tx + (it << 7);
        int m = u >> 3, seg = u & 7;
        int off = elem_off(q, b, i, jbase + (m >> 5), m & 31);
        cp16(smbuf + A_OFF + m * 144 + seg * 16, (const char*)(src + off) + seg * 16);
    }
    // B: 64 rows x 128B, pitch 144B
    const char* wb = (const char*)(d_wB + q * 4096);
#pragma unroll
    for (int it = 0; it < 4; ++it) {
        int u = tx + (it << 7);
        int o = u >> 3, seg = u & 7;
        cp16(smbuf + B_OFF + o * 144 + seg * 16, wb + o * 128 + seg * 16);
    }
}

__global__ void __launch_bounds__(128, 4)
k_o3(const float* __restrict__ b_exp3, const float* __restrict__ b_op3,
     const int* __restrict__ act, float* __restrict__ out) {
    extern __shared__ char sm[];
    int bid = blockIdx.x;
    int b = bid >> 8, i = (bid >> 3) & 31, jbase = (bid & 7) * 4;
    int tx = threadIdx.x, warp = tx >> 5, lane = tx & 31;
    int rowg = warp >> 1, colg = warp & 1;

    int g3 = any_bits(act, 8, 10);
    int a8 = act[b * 10 + 8], a9 = act[b * 10 + 9];

    if (!g3 || (!a8 && !a9)) {
        float fill = g3 ? 0.5f : 0.0f;
        float4 f4 = make_float4(fill, fill, fill, fill);
        float4* ob = (float4*)(out + OUT3 + ((b * 32 + i) * 32 + jbase) * 2048);
        for (int f = tx; f < 2048; f += 128) ob[f] = f4;
        return;
    }

    // contiguous chunk range: [qlo, qhi)
    int qlo = a9 ? 0 : 6;
    int qhi = a8 ? 12 : 6;

    unsigned smb = smem_u32(sm);
    unsigned aoff = (unsigned)((rowg * 64 + ((lane >> 3) & 1) * 8 + (lane & 7)) * 144
                               + ((lane >> 4) & 1) * 16);
    unsigned bbase = (unsigned)((((lane >> 4) & 1) * 8 + (lane & 7)) * 144
                                + ((lane >> 3) & 1) * 16);
    unsigned boff0 = (unsigned)(colg * 2 * 2304) + bbase;
    unsigned boff1 = boff0 + 2304;

    float acc[16][4];
#pragma unroll
    for (int t = 0; t < 16; ++t)
#pragma unroll
        for (int r = 0; r < 4; ++r) acc[t][r] = 0.f;

    o3_stage(sm, qlo, b, i, jbase, tx);
    cp_commit();

    for (int s = qlo; s < qhi; ++s) {
        int cur = s & 1;
        if (s + 1 < qhi) {
            o3_stage(sm + ((s + 1) & 1) * BUF_STRIDE, s + 1, b, i, jbase, tx);
            cp_commit();
            cp_wait1();
        } else {
            cp_wait0();
        }
        __syncthreads();

        unsigned base = smb + cur * BUF_STRIDE;
#pragma unroll
        for (int ks = 0; ks < 4; ++ks) {
            unsigned B0[4], B1[4];
            ldm4(B0, base + B_OFF + boff0 + ks * 32);
            ldm4(B1, base + B_OFF + boff1 + ks * 32);
#pragma unroll
            for (int rh = 0; rh < 4; ++rh) {
                unsigned A[4];
                ldm4(A, base + A_OFF + aoff + rh * 2304 + ks * 32);
                mma_f16(acc[rh * 4 + 0], A, B0[0], B0[1]);
                mma_f16(acc[rh * 4 + 1], A, B0[2], B0[3]);
                mma_f16(acc[rh * 4 + 2], A, B1[0], B1[1]);
                mma_f16(acc[rh * 4 + 3], A, B1[2], B1[3]);
            }
        }
        __syncthreads();
    }

    // epilogue: warp tile 64 rows x 32 cols
#pragma unroll
    for (int rh = 0; rh < 4; ++rh) {
        int m0 = rowg * 64 + rh * 16 + (lane >> 2);
        int jj = m0 >> 5;
        int k0 = m0 & 31;
        float* prow0 = out + OUT3 + (((b * 32 + i) * 32 + (jbase + jj)) * 32 + k0) * 64;
        float* prow1 = prow0 + 8 * 64;
#pragma unroll
        for (int p = 0; p < 4; ++p) {
            int o = colg * 32 + p * 8 + 2 * (lane & 3);
            float bb0 = (a9 ? __ldg(b_op3 + o) : 0.f) + (a8 ? __ldg(b_exp3 + o) : 0.f);
            float bb1 = (a9 ? __ldg(b_op3 + o + 1) : 0.f) + (a8 ? __ldg(b_exp3 + o + 1) : 0.f);
            const float* a4 = acc[rh * 4 + p];
            float2 v0 = make_float2(sigf(a4[0] + bb0), sigf(a4[1] + bb1));
            float2 v1 = make_float2(sigf(a4[2] + bb0), sigf(a4[3] + bb1));
            *(float2*)(prow0 + o) = v0;
            *(float2*)(prow1 + o) = v1;
        }
    }
}

// ---------------- launch ----------------
extern "C" void kernel_launch(void* const* d_in, const int* in_sizes, int n_in,
                              void* d_out, int out_size) {
    const float* x0 = (const float*)d_in[0];
    const float* x1 = (const float*)d_in[1];
    const float* x2 = (const float*)d_in[2];
    const float* x3 = (const float*)d_in[3];
    const float* w_op0 = (const float*)d_in[4];
    const float* b_op0 = (const float*)d_in[5];
    const float* w_red0 = (const float*)d_in[6];
    const float* b_red0 = (const float*)d_in[7];
    const float* w_exp1 = (const float*)d_in[8];
    const float* b_exp1 = (const float*)d_in[9];
    const float* w_op1 = (const float*)d_in[10];
    const float* b_op1 = (const float*)d_in[11];
    const float* w_red1 = (const float*)d_in[12];
    const float* b_red1 = (const float*)d_in[13];
    const float* w_exp2 = (const float*)d_in[14];
    const float* b_exp2 = (const float*)d_in[15];
    const float* w_op2 = (const float*)d_in[16];
    const float* b_op2 = (const float*)d_in[17];
    const float* w_red2 = (const float*)d_in[18];
    const float* b_red2 = (const float*)d_in[19];
    const float* w_exp3 = (const float*)d_in[20];
    const float* b_exp3 = (const float*)d_in[21];
    const float* w_op3 = (const float*)d_in[22];
    const float* b_op3 = (const float*)d_in[23];
    const int* act = (const int*)d_in[24];
    float* out = (float*)d_out;

    static cudaStream_t s1;
    static cudaEvent_t evA, evP, evW, evC;
    static int init_done = 0;
    if (!init_done) {
        cudaFuncSetAttribute(k_o3, cudaFuncAttributeMaxDynamicSharedMemorySize, O3_SMEM);
        cudaFuncSetAttribute(k_o2, cudaFuncAttributeMaxDynamicSharedMemorySize, O2_SMEM);
        cudaStreamCreateWithFlags(&s1, cudaStreamNonBlocking);
        cudaEventCreateWithFlags(&evA, cudaEventDisableTiming);
        cudaEventCreateWithFlags(&evP, cudaEventDisableTiming);
        cudaEventCreateWithFlags(&evW, cudaEventDisableTiming);
        cudaEventCreateWithFlags(&evC, cudaEventDisableTiming);
        init_done = 1;
    }

    unsigned long long* x2h;
    cudaGetSymbolAddress((void**)&x2h, d_x2h);

    // fork side stream
    cudaEventRecord(evA, 0);
    cudaStreamWaitEvent(s1, evA, 0);

    // side chain: weight preps + small outputs (run while k_sr owns the chip)
    k_prep<<<(W_TOTAL + 255) / 256, 256, 0, s1>>>(w_op0, w_red0, w_exp1, w_op1, w_red1,
                                                  w_exp2, w_op2, w_red2);
    cudaEventRecord(evP, s1);  // d_wt ready (for k_o2)
    k_prep3<<<192, 256, 0, s1>>>(w_exp3, w_op3);
    k_split<<<512, 256, 0, s1>>>((const float4*)x2, x2h, 131072);
    cudaEventRecord(evW, s1);  // d_wB + d_x2h ready (for k_o3)
    k_r0<<<8, 64, 0, s1>>>(x1);
    k_r1<<<256, 64, 0, s1>>>(x2);
    k_o0o1<<<264, 64, 0, s1>>>(x0, x1, b_op0, b_red0, b_exp1, b_op1, b_red1, act, out);
    cudaEventRecord(evC, s1);

    // main chain: sr -> o2 (co-resident with o3) -> o3
    k_sr<<<8192, 256>>>((const float4*)x3);
    cudaStreamWaitEvent(0, evP, 0);
    k_o2<<<256, 256, O2_SMEM>>>(x1, x2, b_exp2, b_op2, b_red2, act, out);
    cudaStreamWaitEvent(0, evW, 0);
    k_o3<<<2048, 128, O3_SMEM>>>(b_exp3, b_op3, act, out);

    // join
    cudaStreamWaitEvent(0, evC, 0);
}

// round 14
// speedup vs baseline: 9.7490x; 1.4871x over previous
#include <cuda_runtime.h>
#include <cuda_fp16.h>

// LogicMachine: B=8, n=32, C=64, O=64
// Output layout (floats): o0[8,64] | o1[8,32,64] | o2[8,32,32,64] | o3[8,32,32,32,64]
#define OUT0 0
#define OUT1 512
#define OUT2 16896
#define OUT3 541184

// d_wt holds only o0/o1 weights (transposed [in][64])
#define W_OP0_T   0
#define W_RED0_T  4096
#define W_EXP1_T  12288
#define W_OP1_T   16384
#define W_RED1_T  20480
#define W_TOTAL   28672

__device__ __align__(16) float d_wt[W_TOTAL];
__device__ __align__(16) float d_r0[8 * 128];
__device__ __align__(16) float d_r1[8 * 32 * 128];
__device__ __align__(16) float d_r2[8 * 32 * 32 * 128];
// fp16 B image for o3: 12 chunks x [64 o][64 c]
__device__ __align__(16) __half d_wB[12 * 4096];
// fp16 B image for o2: [64 o][512 c]
__device__ __align__(16) __half d_wO2[64 * 512];
// fp16 images of x3 / x2
__device__ __align__(16) __half d_x3h[8 * 32 * 32 * 32 * 64];
__device__ __align__(16) __half d_x2h[8 * 32 * 32 * 64];
// fp16 gated o2 input image: [8192 pos][512]
__device__ __align__(16) __half d_ein[8192 * 512];

// ---------------- helpers ----------------
__device__ __forceinline__ float sigf(float s) { return 1.0f / (1.0f + __expf(-s)); }

__device__ __forceinline__ int any_bits(const int* act, int lo, int hi) {
    int g = 0;
    for (int b = 0; b < 8; ++b)
        for (int t = lo; t < hi; ++t) g |= act[b * 10 + t];
    return g;
}
__device__ __forceinline__ unsigned smem_u32(const void* p) {
    return (unsigned)__cvta_generic_to_shared(p);
}
__device__ __forceinline__ void cp16(void* dst_smem, const void* src) {
    unsigned sdst = smem_u32(dst_smem);
    asm volatile("cp.async.ca.shared.global [%0], [%1], 16;" :: "r"(sdst), "l"(src));
}
__device__ __forceinline__ void cp_commit() { asm volatile("cp.async.commit_group;"); }
__device__ __forceinline__ void cp_wait0() { asm volatile("cp.async.wait_group 0;"); }
__device__ __forceinline__ void cp_wait1() { asm volatile("cp.async.wait_group 1;"); }

__device__ __forceinline__ void ldm4(unsigned* r, unsigned addr) {
    asm volatile("ldmatrix.sync.aligned.m8n8.x4.shared.b16 {%0,%1,%2,%3}, [%4];"
                 : "=r"(r[0]), "=r"(r[1]), "=r"(r[2]), "=r"(r[3]) : "r"(addr));
}
__device__ __forceinline__ void mma_f16(float* c, const unsigned* a, unsigned b0, unsigned b1) {
    asm volatile(
        "mma.sync.aligned.m16n8k16.row.col.f32.f16.f16.f32 "
        "{%0,%1,%2,%3}, {%4,%5,%6,%7}, {%8,%9}, {%0,%1,%2,%3};"
        : "+f"(c[0]), "+f"(c[1]), "+f"(c[2]), "+f"(c[3])
        : "r"(a[0]), "r"(a[1]), "r"(a[2]), "r"(a[3]), "r"(b0), "r"(b1));
}

// pack float4 -> 4 fp16 in a u64
__device__ __forceinline__ unsigned long long h4(float4 v) {
    __half2 a = __floats2half2_rn(v.x, v.y);
    __half2 b = __floats2half2_rn(v.z, v.w);
    unsigned ua = *reinterpret_cast<unsigned*>(&a);
    unsigned ub = *reinterpret_cast<unsigned*>(&b);
    return (unsigned long long)ua | ((unsigned long long)ub << 32);
}

// ---------------- fp32 -> fp16 image (x2) ----------------
__global__ void k_split(const float4* __restrict__ src,
                        unsigned long long* __restrict__ dst, int n4) {
    int t = blockIdx.x * 256 + threadIdx.x;
    if (t >= n4) return;
    dst[t] = h4(__ldg(src + t));
}

// ---------------- fused x3->fp16 + r2 reduction: one block per (b,i,j) ----------------
__global__ void k_sr(const float4* __restrict__ x3) {
    __shared__ float xs[2048];
    __shared__ float red[2][4][64];
    int bid = blockIdx.x;
    int b = bid >> 10, i = (bid >> 5) & 31, j = bid & 31;
    int tx = threadIdx.x;
    unsigned long long* dst = reinterpret_cast<unsigned long long*>(d_x3h);
#pragma unroll
    for (int it = 0; it < 2; ++it) {
        int f4 = tx + it * 256;
        float4 v = __ldg(x3 + bid * 512 + f4);
        dst[bid * 512 + f4] = h4(v);
        *(float4*)(xs + f4 * 4) = v;
    }
    __syncthreads();
    int c = tx & 63, kg = tx >> 6;
    float mx = -3.4e38f, mn = 3.4e38f;
#pragma unroll
    for (int kk = 0; kk < 8; ++kk) {
        int k = kg * 8 + kk;
        if (k == i || k == j) continue;
        float v = xs[k * 64 + c];
        mx = fmaxf(mx, v);
        mn = fminf(mn, v);
    }
    red[0][kg][c] = mx;
    red[1][kg][c] = mn;
    __syncthreads();
    if (tx < 64) {
        float MX, MN;
        if (i == j) { MX = 0.f; MN = 1.f; }
        else {
            MX = fmaxf(fmaxf(red[0][0][tx], red[0][1][tx]), fmaxf(red[0][2][tx], red[0][3][tx]));
            MN = fminf(fminf(red[1][0][tx], red[1][1][tx]), fminf(red[1][2][tx], red[1][3][tx]));
        }
        d_r2[bid * 128 + 2 * tx] = MX;
        d_r2[bid * 128 + 2 * tx + 1] = MN;
    }
}

// ---------------- weight transpose (o0/o1 weights only) ----------------
__global__ void k_prep(const float* __restrict__ w_op0, const float* __restrict__ w_red0,
                       const float* __restrict__ w_exp1, const float* __restrict__ w_op1,
                       const float* __restrict__ w_red1) {
    int tid = blockIdx.x * 256 + threadIdx.x;
    if (tid >= W_TOTAL) return;
    const float* src;
    int off, IN;
    if (tid < 4096)        { src = w_op0;  off = tid;          IN = 64;  }
    else if (tid < 12288)  { src = w_red0; off = tid - 4096;   IN = 128; }
    else if (tid < 16384)  { src = w_exp1; off = tid - 12288;  IN = 64;  }
    else if (tid < 20480)  { src = w_op1;  off = tid - 16384;  IN = 64;  }
    else                   { src = w_red1; off = tid - 20480;  IN = 128; }
    int in = off >> 6, o = off & 63;
    d_wt[tid] = src[o * IN + in];
}

// ---------------- o3 weight image: fp16, plain [q][o][c] ----------------
__global__ void k_prep3(const float* __restrict__ w_exp3, const float* __restrict__ w_op3) {
    int tid = blockIdx.x * 256 + threadIdx.x;
    if (tid >= 12 * 4096) return;
    int q = tid >> 12, idx = tid & 4095;
    int o = idx >> 6, c = idx & 63;
    const float* w = (q < 6) ? w_op3 : w_exp3;
    d_wB[tid] = __float2half_rn(w[o * 384 + (q % 6) * 64 + c]);
}

// ---------------- o2 weight image: fp16 [o][c], c = exp2(128)|op2(128)|red2(256) ----------------
__global__ void k_prepO2(const float* __restrict__ w_exp2, const float* __restrict__ w_op2,
                         const float* __restrict__ w_red2) {
    int tid = blockIdx.x * 256 + threadIdx.x;
    if (tid >= 64 * 512) return;
    int o = tid >> 9, c = tid & 511;
    float v;
    if (c < 128)      v = w_exp2[o * 128 + c];
    else if (c < 256) v = w_op2[o * 128 + (c - 128)];
    else              v = w_red2[o * 256 + (c - 256)];
    d_wO2[tid] = __float2half_rn(v);
}

// ---------------- o2 input image: fp16, act-gated, one block per (b,i,j) ----------------
__global__ void k_ein(const float* __restrict__ x1, const float* __restrict__ x2,
                      const int* __restrict__ act) {
    int bid = blockIdx.x;
    int b = bid >> 10, i = (bid >> 5) & 31, j = bid & 31;
    int tx = threadIdx.x;
    const int* ab = act + b * 10;
    int u = tx * 4;  // 128 threads x 4 floats = 512
    int bit = (u < 128) ? ab[5] : (u < 256) ? ab[6] : ab[7];
    float4 v;
    if (u < 64)       v = *(const float4*)(x1 + (b * 32 + i) * 64 + u);
    else if (u < 128) v = *(const float4*)(x1 + (b * 32 + j) * 64 + u - 64);
    else if (u < 192) v = *(const float4*)(x2 + ((b * 32 + i) * 32 + j) * 64 + u - 128);
    else if (u < 256) v = *(const float4*)(x2 + ((b * 32 + j) * 32 + i) * 64 + u - 192);
    else if (u < 384) v = *(const float4*)(d_r2 + ((b * 32 + i) * 32 + j) * 128 + u - 256);
    else              v = *(const float4*)(d_r2 + ((b * 32 + j) * 32 + i) * 128 + u - 384);
    if (!bit) v = make_float4(0.f, 0.f, 0.f, 0.f);
    reinterpret_cast<unsigned long long*>(d_ein)[(bid * 512 + u) >> 2] = h4(v);
}

// ---------------- small reductions ----------------
__global__ void k_r0(const float* __restrict__ x1) {
    int b = blockIdx.x, c = threadIdx.x;
    float mx = -3.4e38f, mn = 3.4e38f;
    for (int i = 0; i < 32; ++i) {
        float v = x1[(b * 32 + i) * 64 + c];
        mx = fmaxf(mx, v);
        mn = fminf(mn, v);
    }
    d_r0[b * 128 + 2 * c] = mx;
    d_r0[b * 128 + 2 * c + 1] = mn;
}

__global__ void k_r1(const float* __restrict__ x2) {
    int b = blockIdx.x >> 5, i = blockIdx.x & 31, c = threadIdx.x;
    float mx = -3.4e38f, mn = 3.4e38f;
    for (int j = 0; j < 32; ++j) {
        if (j == i) continue;
        float v = x2[((b * 32 + i) * 32 + j) * 64 + c];
        mx = fmaxf(mx, v);
        mn = fminf(mn, v);
    }
    d_r1[(b * 32 + i) * 128 + 2 * c] = mx;
    d_r1[(b * 32 + i) * 128 + 2 * c + 1] = mn;
}

// ---------------- o0 + o1 ----------------
__global__ void k_o0o1(const float* __restrict__ x0, const float* __restrict__ x1,
                       const float* __restrict__ b_op0, const float* __restrict__ b_red0,
                       const float* __restrict__ b_exp1, const float* __restrict__ b_op1,
                       const float* __restrict__ b_red1,
                       const int* __restrict__ act, float* __restrict__ out) {
    int bid = blockIdx.x, o = threadIdx.x;
    if (bid < 8) {
        int b = bid;
        const int* ab = act + b * 10;
        int g0 = any_bits(act, 0, 2);
        float s0 = 0.f;
        if (ab[0]) {
            float d = 0.f;
            for (int c = 0; c < 64; ++c) d += x0[b * 64 + c] * d_wt[W_OP0_T + c * 64 + o];
            s0 += d + b_op0[o];
        }
        if (ab[1]) {
            float d = 0.f;
            for (int c = 0; c < 128; ++c) d += d_r0[b * 128 + c] * d_wt[W_RED0_T + c * 64 + o];
            s0 += d + b_red0[o];
        }
        out[OUT0 + b * 64 + o] = g0 ? sigf(s0) : 0.f;
    } else {
        int u = bid - 8, b = u >> 5, i = u & 31;
        const int* ab = act + b * 10;
        int g1 = any_bits(act, 2, 5);
        float s1 = 0.f;
        if (ab[2]) {
            float d = 0.f;
            for (int c = 0; c < 64; ++c) d += x0[b * 64 + c] * d_wt[W_EXP1_T + c * 64 + o];
            s1 += d + b_exp1[o];
        }
        if (ab[3]) {
            float d = 0.f;
            for (int c = 0; c < 64; ++c) d += x1[(b * 32 + i) * 64 + c] * d_wt[W_OP1_T + c * 64 + o];
            s1 += d + b_op1[o];
        }
        if (ab[4]) {
            float d = 0.f;
            for (int c = 0; c < 128; ++c) d += d_r1[(b * 32 + i) * 128 + c] * d_wt[W_RED1_T + c * 64 + o];
            s1 += d + b_red1[o];
        }
        out[OUT1 + (b * 32 + i) * 64 + o] = g1 ? sigf(s1) : 0.f;
    }
}

// ---------------- shared GEMM smem layout (o3 and o2mma) ----------------
#define A_OFF  0
#define B_OFF  18432
#define BUF_STRIDE 27648
#define O3_SMEM (2 * BUF_STRIDE)

// ---------------- o2: tensor-core GEMM over d_ein: 64 CTAs, M=128, K=512 ----------------
__device__ __forceinline__ void o2_stage(char* smbuf, int chunk, int bid, int tx) {
    const char* ea = (const char*)(d_ein) + (size_t)bid * 131072;  // 128 rows x 1024B
#pragma unroll
    for (int it = 0; it < 8; ++it) {
        int u = tx + (it << 7);
        int m = u >> 3, seg = u & 7;
        cp16(smbuf + A_OFF + m * 144 + seg * 16, ea + m * 1024 + chunk * 128 + seg * 16);
    }
    const char* wb = (const char*)(d_wO2);
#pragma unroll
    for (int it = 0; it < 4; ++it) {
        int u = tx + (it << 7);
        int o = u >> 3, seg = u & 7;
        cp16(smbuf + B_OFF + o * 144 + seg * 16, wb + o * 1024 + chunk * 128 + seg * 16);
    }
}

__global__ void __launch_bounds__(128, 4)
k_o2mma(const float* __restrict__ b_exp2, const float* __restrict__ b_op2,
        const float* __restrict__ b_red2,
        const int* __restrict__ act, float* __restrict__ out) {
    extern __shared__ char sm[];
    int bid = blockIdx.x;          // 64 CTAs: pos tile [bid*128, bid*128+128)
    int b = bid >> 3;
    int tx = threadIdx.x, warp = tx >> 5, lane = tx & 31;
    int rowg = warp >> 1, colg = warp & 1;
    const int* ab = act + b * 10;
    int g2 = any_bits(act, 5, 8);

    if (!g2) {
        float4 z = make_float4(0.f, 0.f, 0.f, 0.f);
        float4* ob = (float4*)(out + OUT2 + bid * 128 * 64);
        for (int f = tx; f < 2048; f += 128) ob[f] = z;
        return;
    }

    unsigned smb = smem_u32(sm);
    unsigned aoff = (unsigned)((rowg * 64 + ((lane >> 3) & 1) * 8 + (lane & 7)) * 144
                               + ((lane >> 4) & 1) * 16);
    unsigned bbase = (unsigned)((((lane >> 4) & 1) * 8 + (lane & 7)) * 144
                                + ((lane >> 3) & 1) * 16);
    unsigned boff0 = (unsigned)(colg * 2 * 2304) + bbase;
    unsigned boff1 = boff0 + 2304;

    float acc[16][4];
#pragma unroll
    for (int t = 0; t < 16; ++t)
#pragma unroll
        for (int r = 0; r < 4; ++r) acc[t][r] = 0.f;

    o2_stage(sm, 0, bid, tx);
    cp_commit();

    for (int s = 0; s < 8; ++s) {
        int cur = s & 1;
        if (s + 1 < 8) {
            o2_stage(sm + ((s + 1) & 1) * BUF_STRIDE, s + 1, bid, tx);
            cp_commit();
            cp_wait1();
        } else {
            cp_wait0();
        }
        __syncthreads();

        unsigned base = smb + cur * BUF_STRIDE;
#pragma unroll
        for (int ks = 0; ks < 4; ++ks) {
            unsigned B0[4], B1[4];
            ldm4(B0, base + B_OFF + boff0 + ks * 32);
            ldm4(B1, base + B_OFF + boff1 + ks * 32);
#pragma unroll
            for (int rh = 0; rh < 4; ++rh) {
                unsigned A[4];
                ldm4(A, base + A_OFF + aoff + rh * 2304 + ks * 32);
                mma_f16(acc[rh * 4 + 0], A, B0[0], B0[1]);
                mma_f16(acc[rh * 4 + 1], A, B0[2], B0[3]);
                mma_f16(acc[rh * 4 + 2], A, B1[0], B1[1]);
                mma_f16(acc[rh * 4 + 3], A, B1[2], B1[3]);
            }
        }
        __syncthreads();
    }

    float f5 = (float)ab[5], f6 = (float)ab[6], f7 = (float)ab[7];
#pragma unroll
    for (int rh = 0; rh < 4; ++rh) {
        int m0 = rowg * 64 + rh * 16 + (lane >> 2);
        float* prow0 = out + OUT2 + (bid * 128 + m0) * 64;
        float* prow1 = prow0 + 8 * 64;
#pragma unroll
        for (int p = 0; p < 4; ++p) {
            int o = colg * 32 + p * 8 + 2 * (lane & 3);
            float bb0 = f5 * __ldg(b_exp2 + o) + f6 * __ldg(b_op2 + o) + f7 * __ldg(b_red2 + o);
            float bb1 = f5 * __ldg(b_exp2 + o + 1) + f6 * __ldg(b_op2 + o + 1) + f7 * __ldg(b_red2 + o + 1);
            const float* a4 = acc[rh * 4 + p];
            float2 v0 = make_float2(sigf(a4[0] + bb0), sigf(a4[1] + bb1));
            float2 v1 = make_float2(sigf(a4[2] + bb0), sigf(a4[3] + bb1));
            *(float2*)(prow0 + o) = v0;
            *(float2*)(prow1 + o) = v1;
        }
    }
}

// ---------------- o3: fp16 single-pass mma.sync GEMM, 64x32 warp tiles ----------------
__device__ __forceinline__ int elem_off(int q, int b, int i, int j, int k) {
    switch (q) {
        case 0:  return (((b * 32 + i) * 1024) + j * 32 + k) * 64;
        case 1:  return (((b * 32 + i) * 1024) + k * 32 + j) * 64;
        case 2:  return (((b * 32 + j) * 1024) + i * 32 + k) * 64;
        case 3:  return (((b * 32 + k) * 1024) + i * 32 + j) * 64;
        case 4:  return (((b * 32 + j) * 1024) + k * 32 + i) * 64;
        case 5:  return (((b * 32 + k) * 1024) + j * 32 + i) * 64;
        case 6:  return ((b * 32 + i) * 32 + j) * 64;
        case 7:  return ((b * 32 + i) * 32 + k) * 64;
        case 8:  return ((b * 32 + j) * 32 + i) * 64;
        case 9:  return ((b * 32 + k) * 32 + i) * 64;
        case 10: return ((b * 32 + j) * 32 + k) * 64;
        default: return ((b * 32 + k) * 32 + j) * 64;
    }
}

__device__ __forceinline__ void o3_stage(char* smbuf, int q, int b, int i, int jbase, int tx) {
    const __half* src = (q < 6) ? d_x3h : d_x2h;
#pragma unroll
    for (int it = 0; it < 8; ++it) {
        int u = tx + (it << 7);
        int m = u >> 3, seg = u & 7;
        int off = elem_off(q, b, i, jbase + (m >> 5), m & 31);
        cp16(smbuf + A_OFF + m * 144 + seg * 16, (const char*)(src + off) + seg * 16);
    }
    const char* wb = (const char*)(d_wB + q * 4096);
#pragma unroll
    for (int it = 0; it < 4; ++it) {
        int u = tx + (it << 7);
        int o = u >> 3, seg = u & 7;
        cp16(smbuf + B_OFF + o * 144 + seg * 16, wb + o * 128 + seg * 16);
    }
}

__global__ void __launch_bounds__(128, 4)
k_o3(const float* __restrict__ b_exp3, const float* __restrict__ b_op3,
     const int* __restrict__ act, float* __restrict__ out) {
    extern __shared__ char sm[];
    int bid = blockIdx.x;
    int b = bid >> 8, i = (bid >> 3) & 31, jbase = (bid & 7) * 4;
    int tx = threadIdx.x, warp = tx >> 5, lane = tx & 31;
    int rowg = warp >> 1, colg = warp & 1;

    int g3 = any_bits(act, 8, 10);
    int a8 = act[b * 10 + 8], a9 = act[b * 10 + 9];

    if (!g3 || (!a8 && !a9)) {
        float fill = g3 ? 0.5f : 0.0f;
        float4 f4 = make_float4(fill, fill, fill, fill);
        float4* ob = (float4*)(out + OUT3 + ((b * 32 + i) * 32 + jbase) * 2048);
        for (int f = tx; f < 2048; f += 128) ob[f] = f4;
        return;
    }

    int qlo = a9 ? 0 : 6;
    int qhi = a8 ? 12 : 6;

    unsigned smb = smem_u32(sm);
    unsigned aoff = (unsigned)((rowg * 64 + ((lane >> 3) & 1) * 8 + (lane & 7)) * 144
                               + ((lane >> 4) & 1) * 16);
    unsigned bbase = (unsigned)((((lane >> 4) & 1) * 8 + (lane & 7)) * 144
                                + ((lane >> 3) & 1) * 16);
    unsigned boff0 = (unsigned)(colg * 2 * 2304) + bbase;
    unsigned boff1 = boff0 + 2304;

    float acc[16][4];
#pragma unroll
    for (int t = 0; t < 16; ++t)
#pragma unroll
        for (int r = 0; r < 4; ++r) acc[t][r] = 0.f;

    o3_stage(sm, qlo, b, i, jbase, tx);
    cp_commit();

    for (int s = qlo; s < qhi; ++s) {
        int cur = s & 1;
        if (s + 1 < qhi) {
            o3_stage(sm + ((s + 1) & 1) * BUF_STRIDE, s + 1, b, i, jbase, tx);
            cp_commit();
            cp_wait1();
        } else {
            cp_wait0();
        }
        __syncthreads();

        unsigned base = smb + cur * BUF_STRIDE;
#pragma unroll
        for (int ks = 0; ks < 4; ++ks) {
            unsigned B0[4], B1[4];
            ldm4(B0, base + B_OFF + boff0 + ks * 32);
            ldm4(B1, base + B_OFF + boff1 + ks * 32);
#pragma unroll
            for (int rh = 0; rh < 4; ++rh) {
                unsigned A[4];
                ldm4(A, base + A_OFF + aoff + rh * 2304 + ks * 32);
                mma_f16(acc[rh * 4 + 0], A, B0[0], B0[1]);
                mma_f16(acc[rh * 4 + 1], A, B0[2], B0[3]);
                mma_f16(acc[rh * 4 + 2], A, B1[0], B1[1]);
                mma_f16(acc[rh * 4 + 3], A, B1[2], B1[3]);
            }
        }
        __syncthreads();
    }

#pragma unroll
    for (int rh = 0; rh < 4; ++rh) {
        int m0 = rowg * 64 + rh * 16 + (lane >> 2);
        int jj = m0 >> 5;
        int k0 = m0 & 31;
        float* prow0 = out + OUT3 + (((b * 32 + i) * 32 + (jbase + jj)) * 32 + k0) * 64;
        float* prow1 = prow0 + 8 * 64;
#pragma unroll
        for (int p = 0; p < 4; ++p) {
            int o = colg * 32 + p * 8 + 2 * (lane & 3);
            float bb0 = (a9 ? __ldg(b_op3 + o) : 0.f) + (a8 ? __ldg(b_exp3 + o) : 0.f);
            float bb1 = (a9 ? __ldg(b_op3 + o + 1) : 0.f) + (a8 ? __ldg(b_exp3 + o + 1) : 0.f);
            const float* a4 = acc[rh * 4 + p];
            float2 v0 = make_float2(sigf(a4[0] + bb0), sigf(a4[1] + bb1));
            float2 v1 = make_float2(sigf(a4[2] + bb0), sigf(a4[3] + bb1));
            *(float2*)(prow0 + o) = v0;
            *(float2*)(prow1 + o) = v1;
        }
    }
}

// ---------------- launch ----------------
extern "C" void kernel_launch(void* const* d_in, const int* in_sizes, int n_in,
                              void* d_out, int out_size) {
    const float* x0 = (const float*)d_in[0];
    const float* x1 = (const float*)d_in[1];
    const float* x2 = (const float*)d_in[2];
    const float* x3 = (const float*)d_in[3];
    const float* w_op0 = (const float*)d_in[4];
    const float* b_op0 = (const float*)d_in[5];
    const float* w_red0 = (const float*)d_in[6];
    const float* b_red0 = (const float*)d_in[7];
    const float* w_exp1 = (const float*)d_in[8];
    const float* b_exp1 = (const float*)d_in[9];
    const float* w_op1 = (const float*)d_in[10];
    const float* b_op1 = (const float*)d_in[11];
    const float* w_red1 = (const float*)d_in[12];
    const float* b_red1 = (const float*)d_in[13];
    const float* w_exp2 = (const float*)d_in[14];
    const float* b_exp2 = (const float*)d_in[15];
    const float* w_op2 = (const float*)d_in[16];
    const float* b_op2 = (const float*)d_in[17];
    const float* w_red2 = (const float*)d_in[18];
    const float* b_red2 = (const float*)d_in[19];
    const float* w_exp3 = (const float*)d_in[20];
    const float* b_exp3 = (const float*)d_in[21];
    const float* w_op3 = (const float*)d_in[22];
    const float* b_op3 = (const float*)d_in[23];
    const int* act = (const int*)d_in[24];
    float* out = (float*)d_out;

    static cudaStream_t s1;
    static cudaEvent_t evA, evW, evB, evC;
    static int init_done = 0;
    if (!init_done) {
        cudaFuncSetAttribute(k_o3, cudaFuncAttributeMaxDynamicSharedMemorySize, O3_SMEM);
        cudaFuncSetAttribute(k_o2mma, cudaFuncAttributeMaxDynamicSharedMemorySize, O3_SMEM);
        cudaStreamCreateWithFlags(&s1, cudaStreamNonBlocking);
        cudaEventCreateWithFlags(&evA, cudaEventDisableTiming);
        cudaEventCreateWithFlags(&evW, cudaEventDisableTiming);
        cudaEventCreateWithFlags(&evB, cudaEventDisableTiming);
        cudaEventCreateWithFlags(&evC, cudaEventDisableTiming);
        init_done = 1;
    }

    unsigned long long* x2h;
    cudaGetSymbolAddress((void**)&x2h, d_x2h);

    // fork side stream (record before wait — capture requires issue order)
    cudaEventRecord(evA, 0);
    cudaStreamWaitEvent(s1, evA, 0);

    // main chain part 1: sr, then record evB (r2 + x3h ready)
    k_sr<<<8192, 256>>>((const float4*)x3);
    cudaEventRecord(evB, 0);

    // side chain: preps + small outputs; then wait evB -> ein -> o2mma
    k_prep3<<<192, 256, 0, s1>>>(w_exp3, w_op3);
    k_split<<<512, 256, 0, s1>>>((const float4*)x2, x2h, 131072);
    cudaEventRecord(evW, s1);  // d_wB + d_x2h ready (for k_o3)
    k_prep<<<(W_TOTAL + 255) / 256, 256, 0, s1>>>(w_op0, w_red0, w_exp1, w_op1, w_red1);
    k_prepO2<<<128, 256, 0, s1>>>(w_exp2, w_op2, w_red2);
    k_r0<<<8, 64, 0, s1>>>(x1);
    k_r1<<<256, 64, 0, s1>>>(x2);
    k_o0o1<<<264, 64, 0, s1>>>(x0, x1, b_op0, b_red0, b_exp1, b_op1, b_red1, act, out);
    cudaStreamWaitEvent(s1, evB, 0);  // r2 ready (recorded above)
    k_ein<<<8192, 128, 0, s1>>>(x1, x2, act);
    k_o2mma<<<64, 128, O3_SMEM, s1>>>(b_exp2, b_op2, b_red2, act, out);
    cudaEventRecord(evC, s1);

    // main chain part 2: o3 (needs d_wB + d_x2h from side stream)
    cudaStreamWaitEvent(0, evW, 0);
    k_o3<<<2048, 128, O3_SMEM>>>(b_exp3, b_op3, act, out);

    // join
    cudaStreamWaitEvent(0, evC, 0);
}

// round 15
// speedup vs baseline: 10.0854x; 1.0345x over previous
#include <cuda_runtime.h>
#include <cuda_fp16.h>

// LogicMachine: B=8, n=32, C=64, O=64
// Output layout (floats): o0[8,64] | o1[8,32,64] | o2[8,32,32,64] | o3[8,32,32,32,64]
#define OUT0 0
#define OUT1 512
#define OUT2 16896
#define OUT3 541184

// d_wt holds only o0/o1 weights (transposed [in][64])
#define W_OP0_T   0
#define W_RED0_T  4096
#define W_EXP1_T  12288
#define W_OP1_T   16384
#define W_RED1_T  20480
#define W_TOTAL   28672

__device__ __align__(16) float d_wt[W_TOTAL];
__device__ __align__(16) float d_r0[8 * 128];
__device__ __align__(16) float d_r1[8 * 32 * 128];
__device__ __align__(16) float d_r2[8 * 32 * 32 * 128];
// fp16 B image for o3: 12 chunks x [64 o][64 c]
__device__ __align__(16) __half d_wB[12 * 4096];
// fp16 B image for o2: [64 o][512 c]
__device__ __align__(16) __half d_wO2[64 * 512];
// fp16 images of x3 / x2
__device__ __align__(16) __half d_x3h[8 * 32 * 32 * 32 * 64];
__device__ __align__(16) __half d_x2h[8 * 32 * 32 * 64];
// fp16 gated o2 input image: [8192 pos][512]
__device__ __align__(16) __half d_ein[8192 * 512];

// ---------------- helpers ----------------
__device__ __forceinline__ float sigf(float s) { return 1.0f / (1.0f + __expf(-s)); }

__device__ __forceinline__ int any_bits(const int* act, int lo, int hi) {
    int g = 0;
    for (int b = 0; b < 8; ++b)
        for (int t = lo; t < hi; ++t) g |= act[b * 10 + t];
    return g;
}
__device__ __forceinline__ unsigned smem_u32(const void* p) {
    return (unsigned)__cvta_generic_to_shared(p);
}
__device__ __forceinline__ void cp16(void* dst_smem, const void* src) {
    unsigned sdst = smem_u32(dst_smem);
    asm volatile("cp.async.ca.shared.global [%0], [%1], 16;" :: "r"(sdst), "l"(src));
}
__device__ __forceinline__ void cp_commit() { asm volatile("cp.async.commit_group;"); }
__device__ __forceinline__ void cp_wait0() { asm volatile("cp.async.wait_group 0;"); }
__device__ __forceinline__ void cp_wait1() { asm volatile("cp.async.wait_group 1;"); }

__device__ __forceinline__ void ldm4(unsigned* r, unsigned addr) {
    asm volatile("ldmatrix.sync.aligned.m8n8.x4.shared.b16 {%0,%1,%2,%3}, [%4];"
                 : "=r"(r[0]), "=r"(r[1]), "=r"(r[2]), "=r"(r[3]) : "r"(addr));
}
__device__ __forceinline__ void mma_f16(float* c, const unsigned* a, unsigned b0, unsigned b1) {
    asm volatile(
        "mma.sync.aligned.m16n8k16.row.col.f32.f16.f16.f32 "
        "{%0,%1,%2,%3}, {%4,%5,%6,%7}, {%8,%9}, {%0,%1,%2,%3};"
        : "+f"(c[0]), "+f"(c[1]), "+f"(c[2]), "+f"(c[3])
        : "r"(a[0]), "r"(a[1]), "r"(a[2]), "r"(a[3]), "r"(b0), "r"(b1));
}

// pack float4 -> 4 fp16 in a u64
__device__ __forceinline__ unsigned long long h4(float4 v) {
    __half2 a = __floats2half2_rn(v.x, v.y);
    __half2 b = __floats2half2_rn(v.z, v.w);
    unsigned ua = *reinterpret_cast<unsigned*>(&a);
    unsigned ub = *reinterpret_cast<unsigned*>(&b);
    return (unsigned long long)ua | ((unsigned long long)ub << 32);
}

// ---------------- fp32 -> fp16 image (x2) ----------------
__global__ void k_split(const float4* __restrict__ src,
                        unsigned long long* __restrict__ dst, int n4) {
    int t = blockIdx.x * 256 + threadIdx.x;
    if (t >= n4) return;
    dst[t] = h4(__ldg(src + t));
}

// ---------------- fused x3->fp16 + r2 reduction: one block per (b,i,j), offset-able ----------------
__global__ void k_sr(const float4* __restrict__ x3, int base) {
    __shared__ float xs[2048];
    __shared__ float red[2][4][64];
    int bid = blockIdx.x + base;
    int b = bid >> 10, i = (bid >> 5) & 31, j = bid & 31;
    int tx = threadIdx.x;
    unsigned long long* dst = reinterpret_cast<unsigned long long*>(d_x3h);
#pragma unroll
    for (int it = 0; it < 2; ++it) {
        int f4 = tx + it * 256;
        float4 v = __ldg(x3 + bid * 512 + f4);
        dst[bid * 512 + f4] = h4(v);
        *(float4*)(xs + f4 * 4) = v;
    }
    __syncthreads();
    int c = tx & 63, kg = tx >> 6;
    float mx = -3.4e38f, mn = 3.4e38f;
#pragma unroll
    for (int kk = 0; kk < 8; ++kk) {
        int k = kg * 8 + kk;
        if (k == i || k == j) continue;
        float v = xs[k * 64 + c];
        mx = fmaxf(mx, v);
        mn = fminf(mn, v);
    }
    red[0][kg][c] = mx;
    red[1][kg][c] = mn;
    __syncthreads();
    if (tx < 64) {
        float MX, MN;
        if (i == j) { MX = 0.f; MN = 1.f; }
        else {
            MX = fmaxf(fmaxf(red[0][0][tx], red[0][1][tx]), fmaxf(red[0][2][tx], red[0][3][tx]));
            MN = fminf(fminf(red[1][0][tx], red[1][1][tx]), fminf(red[1][2][tx], red[1][3][tx]));
        }
        d_r2[bid * 128 + 2 * tx] = MX;
        d_r2[bid * 128 + 2 * tx + 1] = MN;
    }
}

// ---------------- weight transpose (o0/o1 weights only) ----------------
__global__ void k_prep(const float* __restrict__ w_op0, const float* __restrict__ w_red0,
                       const float* __restrict__ w_exp1, const float* __restrict__ w_op1,
                       const float* __restrict__ w_red1) {
    int tid = blockIdx.x * 256 + threadIdx.x;
    if (tid >= W_TOTAL) return;
    const float* src;
    int off, IN;
    if (tid < 4096)        { src = w_op0;  off = tid;          IN = 64;  }
    else if (tid < 12288)  { src = w_red0; off = tid - 4096;   IN = 128; }
    else if (tid < 16384)  { src = w_exp1; off = tid - 12288;  IN = 64;  }
    else if (tid < 20480)  { src = w_op1;  off = tid - 16384;  IN = 64;  }
    else                   { src = w_red1; off = tid - 20480;  IN = 128; }
    int in = off >> 6, o = off & 63;
    d_wt[tid] = src[o * IN + in];
}

// ---------------- o3 weight image: fp16, plain [q][o][c] ----------------
__global__ void k_prep3(const float* __restrict__ w_exp3, const float* __restrict__ w_op3) {
    int tid = blockIdx.x * 256 + threadIdx.x;
    if (tid >= 12 * 4096) return;
    int q = tid >> 12, idx = tid & 4095;
    int o = idx >> 6, c = idx & 63;
    const float* w = (q < 6) ? w_op3 : w_exp3;
    d_wB[tid] = __float2half_rn(w[o * 384 + (q % 6) * 64 + c]);
}

// ---------------- o2 weight image: fp16 [o][c], c = exp2(128)|op2(128)|red2(256) ----------------
__global__ void k_prepO2(const float* __restrict__ w_exp2, const float* __restrict__ w_op2,
                         const float* __restrict__ w_red2) {
    int tid = blockIdx.x * 256 + threadIdx.x;
    if (tid >= 64 * 512) return;
    int o = tid >> 9, c = tid & 511;
    float v;
    if (c < 128)      v = w_exp2[o * 128 + c];
    else if (c < 256) v = w_op2[o * 128 + (c - 128)];
    else              v = w_red2[o * 256 + (c - 256)];
    d_wO2[tid] = __float2half_rn(v);
}

// ---------------- o2 input image: fp16, act-gated, one block per (b,i,j) ----------------
__global__ void k_ein(const float* __restrict__ x1, const float* __restrict__ x2,
                      const int* __restrict__ act) {
    int bid = blockIdx.x;
    int b = bid >> 10, i = (bid >> 5) & 31, j = bid & 31;
    int tx = threadIdx.x;
    const int* ab = act + b * 10;
    int u = tx * 4;  // 128 threads x 4 floats = 512
    int bit = (u < 128) ? ab[5] : (u < 256) ? ab[6] : ab[7];
    float4 v;
    if (u < 64)       v = *(const float4*)(x1 + (b * 32 + i) * 64 + u);
    else if (u < 128) v = *(const float4*)(x1 + (b * 32 + j) * 64 + u - 64);
    else if (u < 192) v = *(const float4*)(x2 + ((b * 32 + i) * 32 + j) * 64 + u - 128);
    else if (u < 256) v = *(const float4*)(x2 + ((b * 32 + j) * 32 + i) * 64 + u - 192);
    else if (u < 384) v = *(const float4*)(d_r2 + ((b * 32 + i) * 32 + j) * 128 + u - 256);
    else              v = *(const float4*)(d_r2 + ((b * 32 + j) * 32 + i) * 128 + u - 384);
    if (!bit) v = make_float4(0.f, 0.f, 0.f, 0.f);
    reinterpret_cast<unsigned long long*>(d_ein)[(bid * 512 + u) >> 2] = h4(v);
}

// ---------------- small reductions ----------------
__global__ void k_r0(const float* __restrict__ x1) {
    int b = blockIdx.x, c = threadIdx.x;
    float mx = -3.4e38f, mn = 3.4e38f;
    for (int i = 0; i < 32; ++i) {
        float v = x1[(b * 32 + i) * 64 + c];
        mx = fmaxf(mx, v);
        mn = fminf(mn, v);
    }
    d_r0[b * 128 + 2 * c] = mx;
    d_r0[b * 128 + 2 * c + 1] = mn;
}

__global__ void k_r1(const float* __restrict__ x2) {
    int b = blockIdx.x >> 5, i = blockIdx.x & 31, c = threadIdx.x;
    float mx = -3.4e38f, mn = 3.4e38f;
    for (int j = 0; j < 32; ++j) {
        if (j == i) continue;
        float v = x2[((b * 32 + i) * 32 + j) * 64 + c];
        mx = fmaxf(mx, v);
        mn = fminf(mn, v);
    }
    d_r1[(b * 32 + i) * 128 + 2 * c] = mx;
    d_r1[(b * 32 + i) * 128 + 2 * c + 1] = mn;
}

// ---------------- o0 + o1 ----------------
__global__ void k_o0o1(const float* __restrict__ x0, const float* __restrict__ x1,
                       const float* __restrict__ b_op0, const float* __restrict__ b_red0,
                       const float* __restrict__ b_exp1, const float* __restrict__ b_op1,
                       const float* __restrict__ b_red1,
                       const int* __restrict__ act, float* __restrict__ out) {
    int bid = blockIdx.x, o = threadIdx.x;
    if (bid < 8) {
        int b = bid;
        const int* ab = act + b * 10;
        int g0 = any_bits(act, 0, 2);
        float s0 = 0.f;
        if (ab[0]) {
            float d = 0.f;
            for (int c = 0; c < 64; ++c) d += x0[b * 64 + c] * d_wt[W_OP0_T + c * 64 + o];
            s0 += d + b_op0[o];
        }
        if (ab[1]) {
            float d = 0.f;
            for (int c = 0; c < 128; ++c) d += d_r0[b * 128 + c] * d_wt[W_RED0_T + c * 64 + o];
            s0 += d + b_red0[o];
        }
        out[OUT0 + b * 64 + o] = g0 ? sigf(s0) : 0.f;
    } else {
        int u = bid - 8, b = u >> 5, i = u & 31;
        const int* ab = act + b * 10;
        int g1 = any_bits(act, 2, 5);
        float s1 = 0.f;
        if (ab[2]) {
            float d = 0.f;
            for (int c = 0; c < 64; ++c) d += x0[b * 64 + c] * d_wt[W_EXP1_T + c * 64 + o];
            s1 += d + b_exp1[o];
        }
        if (ab[3]) {
            float d = 0.f;
            for (int c = 0; c < 64; ++c) d += x1[(b * 32 + i) * 64 + c] * d_wt[W_OP1_T + c * 64 + o];
            s1 += d + b_op1[o];
        }
        if (ab[4]) {
            float d = 0.f;
            for (int c = 0; c < 128; ++c) d += d_r1[(b * 32 + i) * 128 + c] * d_wt[W_RED1_T + c * 64 + o];
            s1 += d + b_red1[o];
        }
        out[OUT1 + (b * 32 + i) * 64 + o] = g1 ? sigf(s1) : 0.f;
    }
}

// ---------------- shared GEMM smem layout (o3 and o2mma) ----------------
#define A_OFF  0
#define B_OFF  18432
#define BUF_STRIDE 27648
#define O3_SMEM (2 * BUF_STRIDE)

// ---------------- o2: tensor-core GEMM over d_ein: 64 CTAs, M=128, K=512 ----------------
__device__ __forceinline__ void o2_stage(char* smbuf, int chunk, int bid, int tx) {
    const char* ea = (const char*)(d_ein) + (size_t)bid * 131072;  // 128 rows x 1024B
#pragma unroll
    for (int it = 0; it < 8; ++it) {
        int u = tx + (it << 7);
        int m = u >> 3, seg = u & 7;
        cp16(smbuf + A_OFF + m * 144 + seg * 16, ea + m * 1024 + chunk * 128 + seg * 16);
    }
    const char* wb = (const char*)(d_wO2);
#pragma unroll
    for (int it = 0; it < 4; ++it) {
        int u = tx + (it << 7);
        int o = u >> 3, seg = u & 7;
        cp16(smbuf + B_OFF + o * 144 + seg * 16, wb + o * 1024 + chunk * 128 + seg * 16);
    }
}

__global__ void __launch_bounds__(128, 4)
k_o2mma(const float* __restrict__ b_exp2, const float* __restrict__ b_op2,
        const float* __restrict__ b_red2,
        const int* __restrict__ act, float* __restrict__ out) {
    extern __shared__ char sm[];
    int bid = blockIdx.x;          // 64 CTAs: pos tile [bid*128, bid*128+128)
    int b = bid >> 3;
    int tx = threadIdx.x, warp = tx >> 5, lane = tx & 31;
    int rowg = warp >> 1, colg = warp & 1;
    const int* ab = act + b * 10;
    int g2 = any_bits(act, 5, 8);

    if (!g2) {
        float4 z = make_float4(0.f, 0.f, 0.f, 0.f);
        float4* ob = (float4*)(out + OUT2 + bid * 128 * 64);
        for (int f = tx; f < 2048; f += 128) ob[f] = z;
        return;
    }

    unsigned smb = smem_u32(sm);
    unsigned aoff = (unsigned)((rowg * 64 + ((lane >> 3) & 1) * 8 + (lane & 7)) * 144
                               + ((lane >> 4) & 1) * 16);
    unsigned bbase = (unsigned)((((lane >> 4) & 1) * 8 + (lane & 7)) * 144
                                + ((lane >> 3) & 1) * 16);
    unsigned boff0 = (unsigned)(colg * 2 * 2304) + bbase;
    unsigned boff1 = boff0 + 2304;

    float acc[16][4];
#pragma unroll
    for (int t = 0; t < 16; ++t)
#pragma unroll
        for (int r = 0; r < 4; ++r) acc[t][r] = 0.f;

    o2_stage(sm, 0, bid, tx);
    cp_commit();

    for (int s = 0; s < 8; ++s) {
        int cur = s & 1;
        if (s + 1 < 8) {
            o2_stage(sm + ((s + 1) & 1) * BUF_STRIDE, s + 1, bid, tx);
            cp_commit();
            cp_wait1();
        } else {
            cp_wait0();
        }
        __syncthreads();

        unsigned base = smb + cur * BUF_STRIDE;
#pragma unroll
        for (int ks = 0; ks < 4; ++ks) {
            unsigned B0[4], B1[4];
            ldm4(B0, base + B_OFF + boff0 + ks * 32);
            ldm4(B1, base + B_OFF + boff1 + ks * 32);
#pragma unroll
            for (int rh = 0; rh < 4; ++rh) {
                unsigned A[4];
                ldm4(A, base + A_OFF + aoff + rh * 2304 + ks * 32);
                mma_f16(acc[rh * 4 + 0], A, B0[0], B0[1]);
                mma_f16(acc[rh * 4 + 1], A, B0[2], B0[3]);
                mma_f16(acc[rh * 4 + 2], A, B1[0], B1[1]);
                mma_f16(acc[rh * 4 + 3], A, B1[2], B1[3]);
            }
        }
        __syncthreads();
    }

    float f5 = (float)ab[5], f6 = (float)ab[6], f7 = (float)ab[7];
#pragma unroll
    for (int rh = 0; rh < 4; ++rh) {
        int m0 = rowg * 64 + rh * 16 + (lane >> 2);
        float* prow0 = out + OUT2 + (bid * 128 + m0) * 64;
        float* prow1 = prow0 + 8 * 64;
#pragma unroll
        for (int p = 0; p < 4; ++p) {
            int o = colg * 32 + p * 8 + 2 * (lane & 3);
            float bb0 = f5 * __ldg(b_exp2 + o) + f6 * __ldg(b_op2 + o) + f7 * __ldg(b_red2 + o);
            float bb1 = f5 * __ldg(b_exp2 + o + 1) + f6 * __ldg(b_op2 + o + 1) + f7 * __ldg(b_red2 + o + 1);
            const float* a4 = acc[rh * 4 + p];
            float2 v0 = make_float2(sigf(a4[0] + bb0), sigf(a4[1] + bb1));
            float2 v1 = make_float2(sigf(a4[2] + bb0), sigf(a4[3] + bb1));
            *(float2*)(prow0 + o) = v0;
            *(float2*)(prow1 + o) = v1;
        }
    }
}

// ---------------- o3: fp16 single-pass mma.sync GEMM, 64x32 warp tiles, offset-able ----------------
__device__ __forceinline__ int elem_off(int q, int b, int i, int j, int k) {
    switch (q) {
        case 0:  return (((b * 32 + i) * 1024) + j * 32 + k) * 64;
        case 1:  return (((b * 32 + i) * 1024) + k * 32 + j) * 64;
        case 2:  return (((b * 32 + j) * 1024) + i * 32 + k) * 64;
        case 3:  return (((b * 32 + k) * 1024) + i * 32 + j) * 64;
        case 4:  return (((b * 32 + j) * 1024) + k * 32 + i) * 64;
        case 5:  return (((b * 32 + k) * 1024) + j * 32 + i) * 64;
        case 6:  return ((b * 32 + i) * 32 + j) * 64;
        case 7:  return ((b * 32 + i) * 32 + k) * 64;
        case 8:  return ((b * 32 + j) * 32 + i) * 64;
        case 9:  return ((b * 32 + k) * 32 + i) * 64;
        case 10: return ((b * 32 + j) * 32 + k) * 64;
        default: return ((b * 32 + k) * 32 + j) * 64;
    }
}

__device__ __forceinline__ void o3_stage(char* smbuf, int q, int b, int i, int jbase, int tx) {
    const __half* src = (q < 6) ? d_x3h : d_x2h;
#pragma unroll
    for (int it = 0; it < 8; ++it) {
        int u = tx + (it << 7);
        int m = u >> 3, seg = u & 7;
        int off = elem_off(q, b, i, jbase + (m >> 5), m & 31);
        cp16(smbuf + A_OFF + m * 144 + seg * 16, (const char*)(src + off) + seg * 16);
    }
    const char* wb = (const char*)(d_wB + q * 4096);
#pragma unroll
    for (int it = 0; it < 4; ++it) {
        int u = tx + (it << 7);
        int o = u >> 3, seg = u & 7;
        cp16(smbuf + B_OFF + o * 144 + seg * 16, wb + o * 128 + seg * 16);
    }
}

__global__ void __launch_bounds__(128, 4)
k_o3(const float* __restrict__ b_exp3, const float* __restrict__ b_op3,
     const int* __restrict__ act, float* __restrict__ out, int base) {
    extern __shared__ char sm[];
    int bid = blockIdx.x + base;
    int b = bid >> 8, i = (bid >> 3) & 31, jbase = (bid & 7) * 4;
    int tx = threadIdx.x, warp = tx >> 5, lane = tx & 31;
    int rowg = warp >> 1, colg = warp & 1;

    int g3 = any_bits(act, 8, 10);
    int a8 = act[b * 10 + 8], a9 = act[b * 10 + 9];

    if (!g3 || (!a8 && !a9)) {
        float fill = g3 ? 0.5f : 0.0f;
        float4 f4 = make_float4(fill, fill, fill, fill);
        float4* ob = (float4*)(out + OUT3 + ((b * 32 + i) * 32 + jbase) * 2048);
        for (int f = tx; f < 2048; f += 128) ob[f] = f4;
        return;
    }

    int qlo = a9 ? 0 : 6;
    int qhi = a8 ? 12 : 6;

    unsigned smb = smem_u32(sm);
    unsigned aoff = (unsigned)((rowg * 64 + ((lane >> 3) & 1) * 8 + (lane & 7)) * 144
                               + ((lane >> 4) & 1) * 16);
    unsigned bbase = (unsigned)((((lane >> 4) & 1) * 8 + (lane & 7)) * 144
                                + ((lane >> 3) & 1) * 16);
    unsigned boff0 = (unsigned)(colg * 2 * 2304) + bbase;
    unsigned boff1 = boff0 + 2304;

    float acc[16][4];
#pragma unroll
    for (int t = 0; t < 16; ++t)
#pragma unroll
        for (int r = 0; r < 4; ++r) acc[t][r] = 0.f;

    o3_stage(sm, qlo, b, i, jbase, tx);
    cp_commit();

    for (int s = qlo; s < qhi; ++s) {
        int cur = s & 1;
        if (s + 1 < qhi) {
            o3_stage(sm + ((s + 1) & 1) * BUF_STRIDE, s + 1, b, i, jbase, tx);
            cp_commit();
            cp_wait1();
        } else {
            cp_wait0();
        }
        __syncthreads();

        unsigned base2 = smb + cur * BUF_STRIDE;
#pragma unroll
        for (int ks = 0; ks < 4; ++ks) {
            unsigned B0[4], B1[4];
            ldm4(B0, base2 + B_OFF + boff0 + ks * 32);
            ldm4(B1, base2 + B_OFF + boff1 + ks * 32);
#pragma unroll
            for (int rh = 0; rh < 4; ++rh) {
                unsigned A[4];
                ldm4(A, base2 + A_OFF + aoff + rh * 2304 + ks * 32);
                mma_f16(acc[rh * 4 + 0], A, B0[0], B0[1]);
                mma_f16(acc[rh * 4 + 1], A, B0[2], B0[3]);
                mma_f16(acc[rh * 4 + 2], A, B1[0], B1[1]);
                mma_f16(acc[rh * 4 + 3], A, B1[2], B1[3]);
            }
        }
        __syncthreads();
    }

#pragma unroll
    for (int rh = 0; rh < 4; ++rh) {
        int m0 = rowg * 64 + rh * 16 + (lane >> 2);
        int jj = m0 >> 5;
        int k0 = m0 & 31;
        float* prow0 = out + OUT3 + (((b * 32 + i) * 32 + (jbase + jj)) * 32 + k0) * 64;
        float* prow1 = prow0 + 8 * 64;
#pragma unroll
        for (int p = 0; p < 4; ++p) {
            int o = colg * 32 + p * 8 + 2 * (lane & 3);
            float bb0 = (a9 ? __ldg(b_op3 + o) : 0.f) + (a8 ? __ldg(b_exp3 + o) : 0.f);
            float bb1 = (a9 ? __ldg(b_op3 + o + 1) : 0.f) + (a8 ? __ldg(b_exp3 + o + 1) : 0.f);
            const float* a4 = acc[rh * 4 + p];
            float2 v0 = make_float2(sigf(a4[0] + bb0), sigf(a4[1] + bb1));
            float2 v1 = make_float2(sigf(a4[2] + bb0), sigf(a4[3] + bb1));
            *(float2*)(prow0 + o) = v0;
            *(float2*)(prow1 + o) = v1;
        }
    }
}

// ---------------- launch ----------------
extern "C" void kernel_launch(void* const* d_in, const int* in_sizes, int n_in,
                              void* d_out, int out_size) {
    const float* x0 = (const float*)d_in[0];
    const float* x1 = (const float*)d_in[1];
    const float* x2 = (const float*)d_in[2];
    const float* x3 = (const float*)d_in[3];
    const float* w_op0 = (const float*)d_in[4];
    const float* b_op0 = (const float*)d_in[5];
    const float* w_red0 = (const float*)d_in[6];
    const float* b_red0 = (const float*)d_in[7];
    const float* w_exp1 = (const float*)d_in[8];
    const float* b_exp1 = (const float*)d_in[9];
    const float* w_op1 = (const float*)d_in[10];
    const float* b_op1 = (const float*)d_in[11];
    const float* w_red1 = (const float*)d_in[12];
    const float* b_red1 = (const float*)d_in[13];
    const float* w_exp2 = (const float*)d_in[14];
    const float* b_exp2 = (const float*)d_in[15];
    const float* w_op2 = (const float*)d_in[16];
    const float* b_op2 = (const float*)d_in[17];
    const float* w_red2 = (const float*)d_in[18];
    const float* b_red2 = (const float*)d_in[19];
    const float* w_exp3 = (const float*)d_in[20];
    const float* b_exp3 = (const float*)d_in[21];
    const float* w_op3 = (const float*)d_in[22];
    const float* b_op3 = (const float*)d_in[23];
    const int* act = (const int*)d_in[24];
    float* out = (float*)d_out;

    static cudaStream_t s1, s2;
    static cudaEvent_t evA, e0, e1, evW, eD, evC;
    static int init_done = 0;
    if (!init_done) {
        cudaFuncSetAttribute(k_o3, cudaFuncAttributeMaxDynamicSharedMemorySize, O3_SMEM);
        cudaFuncSetAttribute(k_o2mma, cudaFuncAttributeMaxDynamicSharedMemorySize, O3_SMEM);
        cudaStreamCreateWithFlags(&s1, cudaStreamNonBlocking);
        cudaStreamCreateWithFlags(&s2, cudaStreamNonBlocking);
        cudaEventCreateWithFlags(&evA, cudaEventDisableTiming);
        cudaEventCreateWithFlags(&e0, cudaEventDisableTiming);
        cudaEventCreateWithFlags(&e1, cudaEventDisableTiming);
        cudaEventCreateWithFlags(&evW, cudaEventDisableTiming);
        cudaEventCreateWithFlags(&eD, cudaEventDisableTiming);
        cudaEventCreateWithFlags(&evC, cudaEventDisableTiming);
        init_done = 1;
    }

    unsigned long long* x2h;
    cudaGetSymbolAddress((void**)&x2h, d_x2h);

    // fork side streams (records precede waits in issue order)
    cudaEventRecord(evA, 0);
    cudaStreamWaitEvent(s1, evA, 0);
    cudaStreamWaitEvent(s2, evA, 0);

    // s0: sr half0 (batches 0-3)
    k_sr<<<4096, 256>>>((const float4*)x3, 0);
    cudaEventRecord(e0, 0);

    // s1: o3/o2 prerequisites
    k_prep3<<<192, 256, 0, s1>>>(w_exp3, w_op3);
    k_split<<<512, 256, 0, s1>>>((const float4*)x2, x2h, 131072);
    cudaEventRecord(evW, s1);  // d_wB + d_x2h ready

    // s2: o3 half0 (needs sr half0 + evW)
    cudaStreamWaitEvent(s2, e0, 0);
    cudaStreamWaitEvent(s2, evW, 0);
    k_o3<<<1024, 128, O3_SMEM, s2>>>(b_exp3, b_op3, act, out, 0);
    cudaEventRecord(eD, s2);

    // s0: sr half1 (batches 4-7), then o3 half1
    k_sr<<<4096, 256>>>((const float4*)x3, 4096);
    cudaEventRecord(e1, 0);  // full r2 + x3h ready
    cudaStreamWaitEvent(0, evW, 0);
    k_o3<<<1024, 128, O3_SMEM>>>(b_exp3, b_op3, act, out, 1024);

    // s1: small outputs, then (after full r2) ein -> o2mma
    k_prep<<<(W_TOTAL + 255) / 256, 256, 0, s1>>>(w_op0, w_red0, w_exp1, w_op1, w_red1);
    k_prepO2<<<128, 256, 0, s1>>>(w_exp2, w_op2, w_red2);
    k_r0<<<8, 64, 0, s1>>>(x1);
    k_r1<<<256, 64, 0, s1>>>(x2);
    k_o0o1<<<264, 64, 0, s1>>>(x0, x1, b_op0, b_red0, b_exp1, b_op1, b_red1, act, out);
    cudaStreamWaitEvent(s1, e1, 0);
    k_ein<<<8192, 128, 0, s1>>>(x1, x2, act);
    k_o2mma<<<64, 128, O3_SMEM, s1>>>(b_exp2, b_op2, b_red2, act, out);
    cudaEventRecord(evC, s1);

    // join on s0
    cudaStreamWaitEvent(0, eD, 0);
    cudaStreamWaitEvent(0, evC, 0);
}

// round 16
// speedup vs baseline: 10.3996x; 1.0312x over previous
#include <cuda_runtime.h>
#include <cuda_fp16.h>

// LogicMachine: B=8, n=32, C=64, O=64
// Output layout (floats): o0[8,64] | o1[8,32,64] | o2[8,32,32,64] | o3[8,32,32,32,64]
#define OUT0 0
#define OUT1 512
#define OUT2 16896
#define OUT3 541184

// d_wt holds only o0/o1 weights (transposed [in][64])
#define W_OP0_T   0
#define W_RED0_T  4096
#define W_EXP1_T  12288
#define W_OP1_T   16384
#define W_RED1_T  20480
#define W_TOTAL   28672

__device__ __align__(16) float d_wt[W_TOTAL];
__device__ __align__(16) float d_r0[8 * 128];
__device__ __align__(16) float d_r1[8 * 32 * 128];
__device__ __align__(16) float d_r2[8 * 32 * 32 * 128];
// fp16 B image for o3: 12 chunks x [64 o][64 c]
__device__ __align__(16) __half d_wB[12 * 4096];
// fp16 B image for o2: [64 o][512 c]
__device__ __align__(16) __half d_wO2[64 * 512];
// fp16 images of x3 / x2
__device__ __align__(16) __half d_x3h[8 * 32 * 32 * 32 * 64];
__device__ __align__(16) __half d_x2h[8 * 32 * 32 * 64];
// fp16 gated o2 input image: [8192 pos][512]
__device__ __align__(16) __half d_ein[8192 * 512];

// ---------------- helpers ----------------
__device__ __forceinline__ float sigf(float s) { return 1.0f / (1.0f + __expf(-s)); }

__device__ __forceinline__ int any_bits(const int* act, int lo, int hi) {
    int g = 0;
    for (int b = 0; b < 8; ++b)
        for (int t = lo; t < hi; ++t) g |= act[b * 10 + t];
    return g;
}
__device__ __forceinline__ unsigned smem_u32(const void* p) {
    return (unsigned)__cvta_generic_to_shared(p);
}
__device__ __forceinline__ void cp16(void* dst_smem, const void* src) {
    unsigned sdst = smem_u32(dst_smem);
    asm volatile("cp.async.ca.shared.global [%0], [%1], 16;" :: "r"(sdst), "l"(src));
}
__device__ __forceinline__ void cp_commit() { asm volatile("cp.async.commit_group;"); }
__device__ __forceinline__ void cp_wait0() { asm volatile("cp.async.wait_group 0;"); }
__device__ __forceinline__ void cp_wait1() { asm volatile("cp.async.wait_group 1;"); }

__device__ __forceinline__ void ldm4(unsigned* r, unsigned addr) {
    asm volatile("ldmatrix.sync.aligned.m8n8.x4.shared.b16 {%0,%1,%2,%3}, [%4];"
                 : "=r"(r[0]), "=r"(r[1]), "=r"(r[2]), "=r"(r[3]) : "r"(addr));
}
__device__ __forceinline__ void mma_f16(float* c, const unsigned* a, unsigned b0, unsigned b1) {
    asm volatile(
        "mma.sync.aligned.m16n8k16.row.col.f32.f16.f16.f32 "
        "{%0,%1,%2,%3}, {%4,%5,%6,%7}, {%8,%9}, {%0,%1,%2,%3};"
        : "+f"(c[0]), "+f"(c[1]), "+f"(c[2]), "+f"(c[3])
        : "r"(a[0]), "r"(a[1]), "r"(a[2]), "r"(a[3]), "r"(b0), "r"(b1));
}

// pack float4 -> 4 fp16 in a u64
__device__ __forceinline__ unsigned long long h4(float4 v) {
    __half2 a = __floats2half2_rn(v.x, v.y);
    __half2 b = __floats2half2_rn(v.z, v.w);
    unsigned ua = *reinterpret_cast<unsigned*>(&a);
    unsigned ub = *reinterpret_cast<unsigned*>(&b);
    return (unsigned long long)ua | ((unsigned long long)ub << 32);
}

// ---------------- fp32 -> fp16 image (x2) ----------------
__global__ void k_split(const float4* __restrict__ src,
                        unsigned long long* __restrict__ dst, int n4) {
    int t = blockIdx.x * 256 + threadIdx.x;
    if (t >= n4) return;
    dst[t] = h4(__ldg(src + t));
}

// ---------------- fused x3->fp16 + r2 reduction: one block per (b,i,j), offset-able ----------------
__global__ void k_sr(const float4* __restrict__ x3, int base) {
    __shared__ float xs[2048];
    __shared__ float red[2][4][64];
    int bid = blockIdx.x + base;
    int b = bid >> 10, i = (bid >> 5) & 31, j = bid & 31;
    int tx = threadIdx.x;
    unsigned long long* dst = reinterpret_cast<unsigned long long*>(d_x3h);
#pragma unroll
    for (int it = 0; it < 2; ++it) {
        int f4 = tx + it * 256;
        float4 v = __ldg(x3 + bid * 512 + f4);
        dst[bid * 512 + f4] = h4(v);
        *(float4*)(xs + f4 * 4) = v;
    }
    __syncthreads();
    int c = tx & 63, kg = tx >> 6;
    float mx = -3.4e38f, mn = 3.4e38f;
#pragma unroll
    for (int kk = 0; kk < 8; ++kk) {
        int k = kg * 8 + kk;
        if (k == i || k == j) continue;
        float v = xs[k * 64 + c];
        mx = fmaxf(mx, v);
        mn = fminf(mn, v);
    }
    red[0][kg][c] = mx;
    red[1][kg][c] = mn;
    __syncthreads();
    if (tx < 64) {
        float MX, MN;
        if (i == j) { MX = 0.f; MN = 1.f; }
        else {
            MX = fmaxf(fmaxf(red[0][0][tx], red[0][1][tx]), fmaxf(red[0][2][tx], red[0][3][tx]));
            MN = fminf(fminf(red[1][0][tx], red[1][1][tx]), fminf(red[1][2][tx], red[1][3][tx]));
        }
        d_r2[bid * 128 + 2 * tx] = MX;
        d_r2[bid * 128 + 2 * tx + 1] = MN;
    }
}

// ---------------- weight transpose (o0/o1 weights only) ----------------
__global__ void k_prep(const float* __restrict__ w_op0, const float* __restrict__ w_red0,
                       const float* __restrict__ w_exp1, const float* __restrict__ w_op1,
                       const float* __restrict__ w_red1) {
    int tid = blockIdx.x * 256 + threadIdx.x;
    if (tid >= W_TOTAL) return;
    const float* src;
    int off, IN;
    if (tid < 4096)        { src = w_op0;  off = tid;          IN = 64;  }
    else if (tid < 12288)  { src = w_red0; off = tid - 4096;   IN = 128; }
    else if (tid < 16384)  { src = w_exp1; off = tid - 12288;  IN = 64;  }
    else if (tid < 20480)  { src = w_op1;  off = tid - 16384;  IN = 64;  }
    else                   { src = w_red1; off = tid - 20480;  IN = 128; }
    int in = off >> 6, o = off & 63;
    d_wt[tid] = src[o * IN + in];
}

// ---------------- o3 weight image: fp16, plain [q][o][c] ----------------
__global__ void k_prep3(const float* __restrict__ w_exp3, const float* __restrict__ w_op3) {
    int tid = blockIdx.x * 256 + threadIdx.x;
    if (tid >= 12 * 4096) return;
    int q = tid >> 12, idx = tid & 4095;
    int o = idx >> 6, c = idx & 63;
    const float* w = (q < 6) ? w_op3 : w_exp3;
    d_wB[tid] = __float2half_rn(w[o * 384 + (q % 6) * 64 + c]);
}

// ---------------- o2 weight image: fp16 [o][c], c = exp2(128)|op2(128)|red2(256) ----------------
__global__ void k_prepO2(const float* __restrict__ w_exp2, const float* __restrict__ w_op2,
                         const float* __restrict__ w_red2) {
    int tid = blockIdx.x * 256 + threadIdx.x;
    if (tid >= 64 * 512) return;
    int o = tid >> 9, c = tid & 511;
    float v;
    if (c < 128)      v = w_exp2[o * 128 + c];
    else if (c < 256) v = w_op2[o * 128 + (c - 128)];
    else              v = w_red2[o * 256 + (c - 256)];
    d_wO2[tid] = __float2half_rn(v);
}

// ---------------- o2 input image: fp16, act-gated, one block per (b,i,j) ----------------
__global__ void k_ein(const float* __restrict__ x1, const float* __restrict__ x2,
                      const int* __restrict__ act) {
    int bid = blockIdx.x;
    int b = bid >> 10, i = (bid >> 5) & 31, j = bid & 31;
    int tx = threadIdx.x;
    const int* ab = act + b * 10;
    int u = tx * 4;  // 128 threads x 4 floats = 512
    int bit = (u < 128) ? ab[5] : (u < 256) ? ab[6] : ab[7];
    float4 v;
    if (u < 64)       v = *(const float4*)(x1 + (b * 32 + i) * 64 + u);
    else if (u < 128) v = *(const float4*)(x1 + (b * 32 + j) * 64 + u - 64);
    else if (u < 192) v = *(const float4*)(x2 + ((b * 32 + i) * 32 + j) * 64 + u - 128);
    else if (u < 256) v = *(const float4*)(x2 + ((b * 32 + j) * 32 + i) * 64 + u - 192);
    else if (u < 384) v = *(const float4*)(d_r2 + ((b * 32 + i) * 32 + j) * 128 + u - 256);
    else              v = *(const float4*)(d_r2 + ((b * 32 + j) * 32 + i) * 128 + u - 384);
    if (!bit) v = make_float4(0.f, 0.f, 0.f, 0.f);
    reinterpret_cast<unsigned long long*>(d_ein)[(bid * 512 + u) >> 2] = h4(v);
}

// ---------------- small reductions ----------------
__global__ void k_r0(const float* __restrict__ x1) {
    int b = blockIdx.x, c = threadIdx.x;
    float mx = -3.4e38f, mn = 3.4e38f;
    for (int i = 0; i < 32; ++i) {
        float v = x1[(b * 32 + i) * 64 + c];
        mx = fmaxf(mx, v);
        mn = fminf(mn, v);
    }
    d_r0[b * 128 + 2 * c] = mx;
    d_r0[b * 128 + 2 * c + 1] = mn;
}

__global__ void k_r1(const float* __restrict__ x2) {
    int b = blockIdx.x >> 5, i = blockIdx.x & 31, c = threadIdx.x;
    float mx = -3.4e38f, mn = 3.4e38f;
    for (int j = 0; j < 32; ++j) {
        if (j == i) continue;
        float v = x2[((b * 32 + i) * 32 + j) * 64 + c];
        mx = fmaxf(mx, v);
        mn = fminf(mn, v);
    }
    d_r1[(b * 32 + i) * 128 + 2 * c] = mx;
    d_r1[(b * 32 + i) * 128 + 2 * c + 1] = mn;
}

// ---------------- o0 + o1 ----------------
__global__ void k_o0o1(const float* __restrict__ x0, const float* __restrict__ x1,
                       const float* __restrict__ b_op0, const float* __restrict__ b_red0,
                       const float* __restrict__ b_exp1, const float* __restrict__ b_op1,
                       const float* __restrict__ b_red1,
                       const int* __restrict__ act, float* __restrict__ out) {
    int bid = blockIdx.x, o = threadIdx.x;
    if (bid < 8) {
        int b = bid;
        const int* ab = act + b * 10;
        int g0 = any_bits(act, 0, 2);
        float s0 = 0.f;
        if (ab[0]) {
            float d = 0.f;
            for (int c = 0; c < 64; ++c) d += x0[b * 64 + c] * d_wt[W_OP0_T + c * 64 + o];
            s0 += d + b_op0[o];
        }
        if (ab[1]) {
            float d = 0.f;
            for (int c = 0; c < 128; ++c) d += d_r0[b * 128 + c] * d_wt[W_RED0_T + c * 64 + o];
            s0 += d + b_red0[o];
        }
        out[OUT0 + b * 64 + o] = g0 ? sigf(s0) : 0.f;
    } else {
        int u = bid - 8, b = u >> 5, i = u & 31;
        const int* ab = act + b * 10;
        int g1 = any_bits(act, 2, 5);
        float s1 = 0.f;
        if (ab[2]) {
            float d = 0.f;
            for (int c = 0; c < 64; ++c) d += x0[b * 64 + c] * d_wt[W_EXP1_T + c * 64 + o];
            s1 += d + b_exp1[o];
        }
        if (ab[3]) {
            float d = 0.f;
            for (int c = 0; c < 64; ++c) d += x1[(b * 32 + i) * 64 + c] * d_wt[W_OP1_T + c * 64 + o];
            s1 += d + b_op1[o];
        }
        if (ab[4]) {
            float d = 0.f;
            for (int c = 0; c < 128; ++c) d += d_r1[(b * 32 + i) * 128 + c] * d_wt[W_RED1_T + c * 64 + o];
            s1 += d + b_red1[o];
        }
        out[OUT1 + (b * 32 + i) * 64 + o] = g1 ? sigf(s1) : 0.f;
    }
}

// ---------------- shared GEMM smem layout (o3 and o2mma) ----------------
#define A_OFF  0
#define B_OFF  18432
#define BUF_STRIDE 27648
#define O3_SMEM (2 * BUF_STRIDE)

// ---------------- o2: tensor-core GEMM over d_ein: 64 CTAs, M=128, K=512 ----------------
__device__ __forceinline__ void o2_stage(char* smbuf, int chunk, int bid, int tx) {
    const char* ea = (const char*)(d_ein) + (size_t)bid * 131072;  // 128 rows x 1024B
#pragma unroll
    for (int it = 0; it < 8; ++it) {
        int u = tx + (it << 7);
        int m = u >> 3, seg = u & 7;
        cp16(smbuf + A_OFF + m * 144 + seg * 16, ea + m * 1024 + chunk * 128 + seg * 16);
    }
    const char* wb = (const char*)(d_wO2);
#pragma unroll
    for (int it = 0; it < 4; ++it) {
        int u = tx + (it << 7);
        int o = u >> 3, seg = u & 7;
        cp16(smbuf + B_OFF + o * 144 + seg * 16, wb + o * 1024 + chunk * 128 + seg * 16);
    }
}

__global__ void __launch_bounds__(128, 4)
k_o2mma(const float* __restrict__ b_exp2, const float* __restrict__ b_op2,
        const float* __restrict__ b_red2,
        const int* __restrict__ act, float* __restrict__ out) {
    extern __shared__ char sm[];
    int bid = blockIdx.x;          // 64 CTAs: pos tile [bid*128, bid*128+128)
    int b = bid >> 3;
    int tx = threadIdx.x, warp = tx >> 5, lane = tx & 31;
    int rowg = warp >> 1, colg = warp & 1;
    const int* ab = act + b * 10;
    int g2 = any_bits(act, 5, 8);

    if (!g2) {
        float4 z = make_float4(0.f, 0.f, 0.f, 0.f);
        float4* ob = (float4*)(out + OUT2 + bid * 128 * 64);
        for (int f = tx; f < 2048; f += 128) ob[f] = z;
        return;
    }

    unsigned smb = smem_u32(sm);
    unsigned aoff = (unsigned)((rowg * 64 + ((lane >> 3) & 1) * 8 + (lane & 7)) * 144
                               + ((lane >> 4) & 1) * 16);
    unsigned bbase = (unsigned)((((lane >> 4) & 1) * 8 + (lane & 7)) * 144
                                + ((lane >> 3) & 1) * 16);
    unsigned boff0 = (unsigned)(colg * 2 * 2304) + bbase;
    unsigned boff1 = boff0 + 2304;

    float acc[16][4];
#pragma unroll
    for (int t = 0; t < 16; ++t)
#pragma unroll
        for (int r = 0; r < 4; ++r) acc[t][r] = 0.f;

    o2_stage(sm, 0, bid, tx);
    cp_commit();

#pragma unroll
    for (int s = 0; s < 8; ++s) {
        int cur = s & 1;
        if (s + 1 < 8) {
            o2_stage(sm + ((s + 1) & 1) * BUF_STRIDE, s + 1, bid, tx);
            cp_commit();
            cp_wait1();
        } else {
            cp_wait0();
        }
        __syncthreads();

        unsigned base = smb + cur * BUF_STRIDE;
#pragma unroll
        for (int ks = 0; ks < 4; ++ks) {
            unsigned B0[4], B1[4];
            ldm4(B0, base + B_OFF + boff0 + ks * 32);
            ldm4(B1, base + B_OFF + boff1 + ks * 32);
#pragma unroll
            for (int rh = 0; rh < 4; ++rh) {
                unsigned A[4];
                ldm4(A, base + A_OFF + aoff + rh * 2304 + ks * 32);
                mma_f16(acc[rh * 4 + 0], A, B0[0], B0[1]);
                mma_f16(acc[rh * 4 + 1], A, B0[2], B0[3]);
                mma_f16(acc[rh * 4 + 2], A, B1[0], B1[1]);
                mma_f16(acc[rh * 4 + 3], A, B1[2], B1[3]);
            }
        }
        __syncthreads();
    }

    float f5 = (float)ab[5], f6 = (float)ab[6], f7 = (float)ab[7];
#pragma unroll
    for (int rh = 0; rh < 4; ++rh) {
        int m0 = rowg * 64 + rh * 16 + (lane >> 2);
        float* prow0 = out + OUT2 + (bid * 128 + m0) * 64;
        float* prow1 = prow0 + 8 * 64;
#pragma unroll
        for (int p = 0; p < 4; ++p) {
            int o = colg * 32 + p * 8 + 2 * (lane & 3);
            float bb0 = f5 * __ldg(b_exp2 + o) + f6 * __ldg(b_op2 + o) + f7 * __ldg(b_red2 + o);
            float bb1 = f5 * __ldg(b_exp2 + o + 1) + f6 * __ldg(b_op2 + o + 1) + f7 * __ldg(b_red2 + o + 1);
            const float* a4 = acc[rh * 4 + p];
            float2 v0 = make_float2(sigf(a4[0] + bb0), sigf(a4[1] + bb1));
            float2 v1 = make_float2(sigf(a4[2] + bb0), sigf(a4[3] + bb1));
            *(float2*)(prow0 + o) = v0;
            *(float2*)(prow1 + o) = v1;
        }
    }
}

// ---------------- o3: fp16 single-pass mma.sync GEMM, 64x32 warp tiles ----------------
// q is ALWAYS a compile-time constant at the call sites below (unrolled loops),
// so the switch constant-folds into straight-line address math.
__device__ __forceinline__ int elem_off(int q, int b, int i, int j, int k) {
    switch (q) {
        case 0:  return (((b * 32 + i) * 1024) + j * 32 + k) * 64;
        case 1:  return (((b * 32 + i) * 1024) + k * 32 + j) * 64;
        case 2:  return (((b * 32 + j) * 1024) + i * 32 + k) * 64;
        case 3:  return (((b * 32 + k) * 1024) + i * 32 + j) * 64;
        case 4:  return (((b * 32 + j) * 1024) + k * 32 + i) * 64;
        case 5:  return (((b * 32 + k) * 1024) + j * 32 + i) * 64;
        case 6:  return ((b * 32 + i) * 32 + j) * 64;
        case 7:  return ((b * 32 + i) * 32 + k) * 64;
        case 8:  return ((b * 32 + j) * 32 + i) * 64;
        case 9:  return ((b * 32 + k) * 32 + i) * 64;
        case 10: return ((b * 32 + j) * 32 + k) * 64;
        default: return ((b * 32 + k) * 32 + j) * 64;
    }
}

__device__ __forceinline__ void o3_stage(char* smbuf, int q, int b, int i, int jbase, int tx) {
    const __half* src = (q < 6) ? d_x3h : d_x2h;
#pragma unroll
    for (int it = 0; it < 8; ++it) {
        int u = tx + (it << 7);
        int m = u >> 3, seg = u & 7;
        int off = elem_off(q, b, i, jbase + (m >> 5), m & 31);
        cp16(smbuf + A_OFF + m * 144 + seg * 16, (const char*)(src + off) + seg * 16);
    }
    const char* wb = (const char*)(d_wB + q * 4096);
#pragma unroll
    for (int it = 0; it < 4; ++it) {
        int u = tx + (it << 7);
        int o = u >> 3, seg = u & 7;
        cp16(smbuf + B_OFF + o * 144 + seg * 16, wb + o * 128 + seg * 16);
    }
}

template <int QLO, int QHI>
__device__ __forceinline__ void o3_body(char* sm, unsigned smb, int b, int i, int jbase, int tx,
                                        unsigned aoff, unsigned boff0, unsigned boff1,
                                        float (&acc)[16][4]) {
    o3_stage(sm, QLO, b, i, jbase, tx);
    cp_commit();
#pragma unroll
    for (int s = QLO; s < QHI; ++s) {
        int cur = s & 1;
        if (s + 1 < QHI) {
            o3_stage(sm + ((s + 1) & 1) * BUF_STRIDE, s + 1, b, i, jbase, tx);
            cp_commit();
            cp_wait1();
        } else {
            cp_wait0();
        }
        __syncthreads();

        unsigned base2 = smb + cur * BUF_STRIDE;
#pragma unroll
        for (int ks = 0; ks < 4; ++ks) {
            unsigned B0[4], B1[4];
            ldm4(B0, base2 + B_OFF + boff0 + ks * 32);
            ldm4(B1, base2 + B_OFF + boff1 + ks * 32);
#pragma unroll
            for (int rh = 0; rh < 4; ++rh) {
                unsigned A[4];
                ldm4(A, base2 + A_OFF + aoff + rh * 2304 + ks * 32);
                mma_f16(acc[rh * 4 + 0], A, B0[0], B0[1]);
                mma_f16(acc[rh * 4 + 1], A, B0[2], B0[3]);
                mma_f16(acc[rh * 4 + 2], A, B1[0], B1[1]);
                mma_f16(acc[rh * 4 + 3], A, B1[2], B1[3]);
            }
        }
        __syncthreads();
    }
}

__global__ void __launch_bounds__(128, 4)
k_o3(const float* __restrict__ b_exp3, const float* __restrict__ b_op3,
     const int* __restrict__ act, float* __restrict__ out, int base) {
    extern __shared__ char sm[];
    int bid = blockIdx.x + base;
    int b = bid >> 8, i = (bid >> 3) & 31, jbase = (bid & 7) * 4;
    int tx = threadIdx.x, warp = tx >> 5, lane = tx & 31;
    int rowg = warp >> 1, colg = warp & 1;

    int g3 = any_bits(act, 8, 10);
    int a8 = act[b * 10 + 8], a9 = act[b * 10 + 9];

    if (!g3 || (!a8 && !a9)) {
        float fill = g3 ? 0.5f : 0.0f;
        float4 f4 = make_float4(fill, fill, fill, fill);
        float4* ob = (float4*)(out + OUT3 + ((b * 32 + i) * 32 + jbase) * 2048);
        for (int f = tx; f < 2048; f += 128) ob[f] = f4;
        return;
    }

    unsigned smb = smem_u32(sm);
    unsigned aoff = (unsigned)((rowg * 64 + ((lane >> 3) & 1) * 8 + (lane & 7)) * 144
                               + ((lane >> 4) & 1) * 16);
    unsigned bbase = (unsigned)((((lane >> 4) & 1) * 8 + (lane & 7)) * 144
                                + ((lane >> 3) & 1) * 16);
    unsigned boff0 = (unsigned)(colg * 2 * 2304) + bbase;
    unsigned boff1 = boff0 + 2304;

    float acc[16][4];
#pragma unroll
    for (int t = 0; t < 16; ++t)
#pragma unroll
        for (int r = 0; r < 4; ++r) acc[t][r] = 0.f;

    if (a9) {
        if (a8) o3_body<0, 12>(sm, smb, b, i, jbase, tx, aoff, boff0, boff1, acc);
        else    o3_body<0, 6>(sm, smb, b, i, jbase, tx, aoff, boff0, boff1, acc);
    } else {
        o3_body<6, 12>(sm, smb, b, i, jbase, tx, aoff, boff0, boff1, acc);
    }

#pragma unroll
    for (int rh = 0; rh < 4; ++rh) {
        int m0 = rowg * 64 + rh * 16 + (lane >> 2);
        int jj = m0 >> 5;
        int k0 = m0 & 31;
        float* prow0 = out + OUT3 + (((b * 32 + i) * 32 + (jbase + jj)) * 32 + k0) * 64;
        float* prow1 = prow0 + 8 * 64;
#pragma unroll
        for (int p = 0; p < 4; ++p) {
            int o = colg * 32 + p * 8 + 2 * (lane & 3);
            float bb0 = (a9 ? __ldg(b_op3 + o) : 0.f) + (a8 ? __ldg(b_exp3 + o) : 0.f);
            float bb1 = (a9 ? __ldg(b_op3 + o + 1) : 0.f) + (a8 ? __ldg(b_exp3 + o + 1) : 0.f);
            const float* a4 = acc[rh * 4 + p];
            float2 v0 = make_float2(sigf(a4[0] + bb0), sigf(a4[1] + bb1));
            float2 v1 = make_float2(sigf(a4[2] + bb0), sigf(a4[3] + bb1));
            *(float2*)(prow0 + o) = v0;
            *(float2*)(prow1 + o) = v1;
        }
    }
}

// ---------------- launch ----------------
extern "C" void kernel_launch(void* const* d_in, const int* in_sizes, int n_in,
                              void* d_out, int out_size) {
    const float* x0 = (const float*)d_in[0];
    const float* x1 = (const float*)d_in[1];
    const float* x2 = (const float*)d_in[2];
    const float* x3 = (const float*)d_in[3];
    const float* w_op0 = (const float*)d_in[4];
    const float* b_op0 = (const float*)d_in[5];
    const float* w_red0 = (const float*)d_in[6];
    const float* b_red0 = (const float*)d_in[7];
    const float* w_exp1 = (const float*)d_in[8];
    const float* b_exp1 = (const float*)d_in[9];
    const float* w_op1 = (const float*)d_in[10];
    const float* b_op1 = (const float*)d_in[11];
    const float* w_red1 = (const float*)d_in[12];
    const float* b_red1 = (const float*)d_in[13];
    const float* w_exp2 = (const float*)d_in[14];
    const float* b_exp2 = (const float*)d_in[15];
    const float* w_op2 = (const float*)d_in[16];
    const float* b_op2 = (const float*)d_in[17];
    const float* w_red2 = (const float*)d_in[18];
    const float* b_red2 = (const float*)d_in[19];
    const float* w_exp3 = (const float*)d_in[20];
    const float* b_exp3 = (const float*)d_in[21];
    const float* w_op3 = (const float*)d_in[22];
    const float* b_op3 = (const float*)d_in[23];
    const int* act = (const int*)d_in[24];
    float* out = (float*)d_out;

    static cudaStream_t s1, s2;
    static cudaEvent_t evA, e0, e1, evW, eD, evC;
    static int init_done = 0;
    if (!init_done) {
        cudaFuncSetAttribute(k_o3, cudaFuncAttributeMaxDynamicSharedMemorySize, O3_SMEM);
        cudaFuncSetAttribute(k_o2mma, cudaFuncAttributeMaxDynamicSharedMemorySize, O3_SMEM);
        cudaStreamCreateWithFlags(&s1, cudaStreamNonBlocking);
        cudaStreamCreateWithFlags(&s2, cudaStreamNonBlocking);
        cudaEventCreateWithFlags(&evA, cudaEventDisableTiming);
        cudaEventCreateWithFlags(&e0, cudaEventDisableTiming);
        cudaEventCreateWithFlags(&e1, cudaEventDisableTiming);
        cudaEventCreateWithFlags(&evW, cudaEventDisableTiming);
        cudaEventCreateWithFlags(&eD, cudaEventDisableTiming);
        cudaEventCreateWithFlags(&evC, cudaEventDisableTiming);
        init_done = 1;
    }

    unsigned long long* x2h;
    cudaGetSymbolAddress((void**)&x2h, d_x2h);

    // fork side streams (records precede waits in issue order)
    cudaEventRecord(evA, 0);
    cudaStreamWaitEvent(s1, evA, 0);
    cudaStreamWaitEvent(s2, evA, 0);

    // s0: sr half0 (batches 0-3)
    k_sr<<<4096, 256>>>((const float4*)x3, 0);
    cudaEventRecord(e0, 0);

    // s1: o3/o2 prerequisites
    k_prep3<<<192, 256, 0, s1>>>(w_exp3, w_op3);
    k_split<<<512, 256, 0, s1>>>((const float4*)x2, x2h, 131072);
    cudaEventRecord(evW, s1);  // d_wB + d_x2h ready

    // s2: o3 half0 (needs sr half0 + evW)
    cudaStreamWaitEvent(s2, e0, 0);
    cudaStreamWaitEvent(s2, evW, 0);
    k_o3<<<1024, 128, O3_SMEM, s2>>>(b_exp3, b_op3, act, out, 0);
    cudaEventRecord(eD, s2);

    // s0: sr half1 (batches 4-7), then o3 half1
    k_sr<<<4096, 256>>>((const float4*)x3, 4096);
    cudaEventRecord(e1, 0);  // full r2 + x3h ready
    cudaStreamWaitEvent(0, evW, 0);
    k_o3<<<1024, 128, O3_SMEM>>>(b_exp3, b_op3, act, out, 1024);

    // s1: small outputs, then (after full r2) ein -> o2mma
    k_prep<<<(W_TOTAL + 255) / 256, 256, 0, s1>>>(w_op0, w_red0, w_exp1, w_op1, w_red1);
    k_prepO2<<<128, 256, 0, s1>>>(w_exp2, w_op2, w_red2);
    k_r0<<<8, 64, 0, s1>>>(x1);
    k_r1<<<256, 64, 0, s1>>>(x2);
    k_o0o1<<<264, 64, 0, s1>>>(x0, x1, b_op0, b_red0, b_exp1, b_op1, b_red1, act, out);
    cudaStreamWaitEvent(s1, e1, 0);
    k_ein<<<8192, 128, 0, s1>>>(x1, x2, act);
    k_o2mma<<<64, 128, O3_SMEM, s1>>>(b_exp2, b_op2, b_red2, act, out);
    cudaEventRecord(evC, s1);

    // join on s0
    cudaStreamWaitEvent(0, eD, 0);
    cudaStreamWaitEvent(0, evC, 0);
}